// round 10
// baseline (speedup 1.0000x reference)
#include <cuda_runtime.h>
#include <cuda_fp16.h>
#include <math.h>
#include <stdint.h>

// ---------------- problem constants ----------------
#define BATCH 32
#define CH    256
#define HWS   3136
#define TOK   100352
#define SHIFT3 3
#define HEADS 8
#define HDIM  32
#define HIDDEN 1024
#define QKVN  768

// ---------------- scratch ----------------
__device__ __half g_ywin [(size_t)TOK*CH];
__device__ __half g_qkv  [(size_t)TOK*QKVN];
__device__ __half g_ow   [(size_t)TOK*CH];
__device__ float  g_x1   [(size_t)TOK*CH];
__device__ __half g_h2   [(size_t)TOK*CH];
__device__ __half g_hmid [(size_t)TOK*HIDDEN];
// fp16, TRANSPOSED weight copies: [N][K]
__device__ __half g_wqkv [QKVN*CH];
__device__ __half g_wproj[CH*CH];
__device__ __half g_w1   [HIDDEN*CH];
__device__ __half g_w2   [CH*HIDDEN];

__device__ __forceinline__ void cpasync16(uint32_t dst, const void* src) {
    asm volatile("cp.async.cg.shared.global [%0], [%1], 16;" :: "r"(dst), "l"(src));
}

__device__ __forceinline__ void ldsm4(uint32_t& r0, uint32_t& r1, uint32_t& r2, uint32_t& r3,
                                      uint32_t addr) {
    asm volatile("ldmatrix.sync.aligned.m8n8.x4.shared.b16 {%0,%1,%2,%3}, [%4];"
                 : "=r"(r0), "=r"(r1), "=r"(r2), "=r"(r3) : "r"(addr));
}

__device__ __forceinline__ void ldsm4t(uint32_t& r0, uint32_t& r1, uint32_t& r2, uint32_t& r3,
                                       uint32_t addr) {
    asm volatile("ldmatrix.sync.aligned.m8n8.x4.trans.shared.b16 {%0,%1,%2,%3}, [%4];"
                 : "=r"(r0), "=r"(r1), "=r"(r2), "=r"(r3) : "r"(addr));
}

#define MMA16816(d0,d1,d2,d3,a0,a1,a2,a3,b0,b1) \
    asm volatile( \
        "mma.sync.aligned.m16n8k16.row.col.f32.f16.f16.f32 " \
        "{%0,%1,%2,%3}, {%4,%5,%6,%7}, {%8,%9}, {%0,%1,%2,%3};" \
        : "+f"(d0), "+f"(d1), "+f"(d2), "+f"(d3) \
        : "r"(a0), "r"(a1), "r"(a2), "r"(a3), "r"(b0), "r"(b1))

// ---------------- prep: ALL weights transpose + fp16 round, one launch ----------------
__global__ __launch_bounds__(256) void transpose_round_all(
    const float* __restrict__ w0, __half* __restrict__ o0,
    const float* __restrict__ w1_, __half* __restrict__ o1,
    const float* __restrict__ w2_, __half* __restrict__ o2,
    const float* __restrict__ w3_, __half* __restrict__ o3)
{
    __shared__ float t[32][33];
    int blk = blockIdx.x;
    const float* w; __half* wt; int K, N, nb;
    if (blk < 192)      { w = w0;  wt = o0; K = CH;     N = QKVN;   nb = QKVN/32; }
    else if (blk < 256) { blk -= 192; w = w1_; wt = o1; K = CH;     N = CH;     nb = CH/32; }
    else if (blk < 512) { blk -= 256; w = w2_; wt = o2; K = CH;     N = HIDDEN; nb = HIDDEN/32; }
    else                { blk -= 512; w = w3_; wt = o3; K = HIDDEN; N = CH;     nb = CH/32; }
    const int k0 = (blk / nb) * 32, n0 = (blk % nb) * 32;
    const int x = threadIdx.x & 31, y = threadIdx.x >> 5;
    for (int yy = y; yy < 32; yy += 8)
        t[yy][x] = w[(size_t)(k0 + yy)*N + n0 + x];
    __syncthreads();
    for (int yy = y; yy < 32; yy += 8)
        wt[(size_t)(n0 + yy)*K + k0 + x] = __float2half_rn(t[x][yy]);
}

// ---------------- kernel 1: LN1 + shift + window partition ----------------
__global__ __launch_bounds__(256) void ln1_kernel(
    const float* __restrict__ x, const float* __restrict__ g, const float* __restrict__ bta,
    __half* __restrict__ ywin)
{
    __shared__ float ts[256*33];
    __shared__ float cmu[32], crs[32];
    const int blk = blockIdx.x;
    const int b   = blk / 98;
    const int hw0 = (blk % 98) * 32;
    const int tid = threadIdx.x;
    const float* xb = x + (size_t)b*CH*HWS;

    for (int idx = tid; idx < 256*32; idx += 256) {
        int ch = idx >> 5, j = idx & 31;
        ts[ch*33 + j] = xb[(size_t)ch*HWS + hw0 + j];
    }
    __syncthreads();

    {
        int col = tid >> 3, kk = tid & 7;
        float s = 0.f, s2 = 0.f;
        for (int ch = kk; ch < 256; ch += 8) {
            float v = ts[ch*33 + col];
            s += v; s2 += v*v;
        }
        #pragma unroll
        for (int o = 4; o; o >>= 1) {
            s  += __shfl_down_sync(0xffffffffu, s,  o, 8);
            s2 += __shfl_down_sync(0xffffffffu, s2, o, 8);
        }
        if (kk == 0) {
            float mu = s * (1.f/256.f);
            cmu[col] = mu;
            crs[col] = rsqrtf(s2*(1.f/256.f) - mu*mu + 1e-5f);
        }
    }
    __syncthreads();

    const float gg = g[tid], bb = bta[tid];
    for (int j = 0; j < 32; j++) {
        int hw = hw0 + j;
        int h = hw / 56, w = hw % 56;
        int hs = h + (56 - SHIFT3); if (hs >= 56) hs -= 56;
        int wsh = w + (56 - SHIFT3); if (wsh >= 56) wsh -= 56;
        int wi = hs / 7, r = hs % 7;
        int wj = wsh / 7, c = wsh % 7;
        int win = ((b << 3) + wi) * 8 + wj;
        int n = r*7 + c;
        ywin[((size_t)win*49 + n)*CH + tid] =
            __float2half_rn((ts[tid*33 + j] - cmu[j]) * crs[j] * gg + bb);
    }
}

// ---------------- fp16 mma GEMM: CTA 128x256, warp 64x64, BK=64, 2-stage ----------------
#define BK 64
#define STAGES 2
#define A_STAGE_B (128*128)
#define B_STAGE_B (256*128)
#define STAGE_B   (A_STAGE_B + B_STAGE_B)
#define SMEM_DYN  (STAGES*STAGE_B)   // 96 KB -> 2 CTAs/SM

enum { EPI_BIAS = 0, EPI_PROJLN = 1, EPI_GELU = 2, EPI_RES = 3 };

template<int EPI>
__global__ __launch_bounds__(256, 2) void mma_gemm(
    const __half* __restrict__ A, const __half* __restrict__ BT,
    const float* __restrict__ bias, void* __restrict__ Cp,
    const float* __restrict__ aux,
    const float* __restrict__ gamma, const float* __restrict__ beta2,
    __half* __restrict__ h2out,
    int M, int N, int K)
{
    extern __shared__ char sm[];
    const uint32_t smb = (uint32_t)__cvta_generic_to_shared(sm);

    const int tid  = threadIdx.x;
    const int lane = tid & 31, warp = tid >> 5;
    const int g    = lane >> 2, c4 = lane & 3;
    const int wm0  = (warp >> 2) * 64;
    const int wn0  = (warp & 3) * 64;
    const int m0   = blockIdx.y * 128, n0 = blockIdx.x * 256;

    const int fr  = ((lane >> 3) & 1) * 8 + (lane & 7);
    const int fk  = lane >> 4;

    int arow[4], asw[4], brow[4], bsw[4];
    #pragma unroll
    for (int i = 0; i < 4; i++) {
        int ra = wm0 + i*16 + fr;
        arow[i] = ra*128; asw[i] = ra & 7;
        int rb = wn0 + i*16 + fr;
        brow[i] = rb*128; bsw[i] = rb & 7;
    }

    const int cr = tid >> 3, cc = tid & 7;

    float acc[4][8][4];
    #pragma unroll
    for (int i = 0; i < 4; i++)
        #pragma unroll
        for (int j = 0; j < 8; j++)
            #pragma unroll
            for (int k = 0; k < 4; k++) acc[i][j][k] = 0.f;

    auto fill = [&](int t) {
        const int s = t % STAGES;
        const uint32_t ab = smb + (uint32_t)(s*STAGE_B);
        const uint32_t bb = ab + A_STAGE_B;
        const int k0 = t * BK;
        #pragma unroll
        for (int i = 0; i < 4; i++) {
            int rr = cr + 32*i;
            cpasync16(ab + (uint32_t)(rr*128) + (uint32_t)((cc ^ (rr & 7)) << 4),
                      &A[(size_t)(m0 + rr)*K + k0 + cc*8]);
        }
        #pragma unroll
        for (int i = 0; i < 8; i++) {
            int rr = cr + 32*i;
            cpasync16(bb + (uint32_t)(rr*128) + (uint32_t)((cc ^ (rr & 7)) << 4),
                      &BT[(size_t)(n0 + rr)*K + k0 + cc*8]);
        }
    };

    const int nt = K / BK;
    fill(0);
    asm volatile("cp.async.commit_group;");

    for (int t = 0; t < nt; t++) {
        asm volatile("cp.async.wait_group 0;" ::: "memory");
        __syncthreads();
        if (t + 1 < nt) fill(t + 1);
        asm volatile("cp.async.commit_group;");

        const uint32_t ab = smb + (uint32_t)((t % STAGES)*STAGE_B);
        const uint32_t bb = ab + A_STAGE_B;

        #pragma unroll
        for (int kk = 0; kk < 4; kk++) {
            const int kc = kk*2 + fk;
            uint32_t af[4][4], bf[4][4];
            #pragma unroll
            for (int mi = 0; mi < 4; mi++)
                ldsm4(af[mi][0], af[mi][1], af[mi][2], af[mi][3],
                      ab + (uint32_t)arow[mi] + (uint32_t)((kc ^ asw[mi]) << 4));
            #pragma unroll
            for (int np = 0; np < 4; np++)
                ldsm4(bf[np][0], bf[np][1], bf[np][2], bf[np][3],
                      bb + (uint32_t)brow[np] + (uint32_t)((kc ^ bsw[np]) << 4));

            #pragma unroll
            for (int mi = 0; mi < 4; mi++)
                #pragma unroll
                for (int ni = 0; ni < 8; ni++) {
                    const int p = ni >> 1, sb = ni & 1;
                    MMA16816(acc[mi][ni][0], acc[mi][ni][1], acc[mi][ni][2], acc[mi][ni][3],
                             af[mi][0], af[mi][1], af[mi][2], af[mi][3],
                             bf[p][sb], bf[p][2 + sb]);
                }
        }
    }

    // -------- epilogue --------
    if (EPI == EPI_PROJLN) {
        asm volatile("cp.async.wait_group 0;" ::: "memory");
        __syncthreads();
        float* red  = (float*)sm;
        float* red2 = red + 512;
        float* smu  = red2 + 512;
        float* srs  = smu + 128;

        float* C = (float*)Cp;
        float psum[4][2], psum2[4][2];
        #pragma unroll
        for (int mi = 0; mi < 4; mi++) { psum[mi][0]=psum[mi][1]=psum2[mi][0]=psum2[mi][1]=0.f; }

        #pragma unroll
        for (int mi = 0; mi < 4; mi++) {
            #pragma unroll
            for (int h = 0; h < 2; h++) {
                const int m = m0 + wm0 + mi*16 + g + 8*h;
                int win = m / 49, n = m % 49;
                int bq = win >> 6;
                int wr = (win >> 3) & 7;
                int wc = win & 7;
                int rr = n / 7, ccv = n % 7;
                int hh = wr*7 + rr + SHIFT3; if (hh >= 56) hh -= 56;
                int wwv = wc*7 + ccv + SHIFT3; if (wwv >= 56) wwv -= 56;
                int sp = hh*56 + wwv;
                size_t drow = (size_t)bq*HWS + sp;
                #pragma unroll
                for (int ni = 0; ni < 8; ni++) {
                    const int col = wn0 + ni*8 + 2*c4;
                    float v0 = acc[mi][ni][2*h+0] + bias[col] + aux[((size_t)(bq*CH + col    ))*HWS + sp];
                    float v1 = acc[mi][ni][2*h+1] + bias[col+1] + aux[((size_t)(bq*CH + col + 1))*HWS + sp];
                    acc[mi][ni][2*h+0] = v0; acc[mi][ni][2*h+1] = v1;
                    float2 out; out.x = v0; out.y = v1;
                    *reinterpret_cast<float2*>(&C[drow*CH + col]) = out;
                    psum [mi][h] += v0 + v1;
                    psum2[mi][h] += v0*v0 + v1*v1;
                }
            }
        }
        #pragma unroll
        for (int mi = 0; mi < 4; mi++)
            #pragma unroll
            for (int h = 0; h < 2; h++) {
                float s = psum[mi][h], s2 = psum2[mi][h];
                s  += __shfl_xor_sync(0xffffffffu, s, 1);  s  += __shfl_xor_sync(0xffffffffu, s, 2);
                s2 += __shfl_xor_sync(0xffffffffu, s2, 1); s2 += __shfl_xor_sync(0xffffffffu, s2, 2);
                if (c4 == 0) {
                    int rloc = wm0 + mi*16 + g + 8*h;
                    red [rloc*4 + (warp & 3)] = s;
                    red2[rloc*4 + (warp & 3)] = s2;
                }
            }
        __syncthreads();
        if (tid < 128) {
            float s  = red [tid*4] + red [tid*4+1] + red [tid*4+2] + red [tid*4+3];
            float s2 = red2[tid*4] + red2[tid*4+1] + red2[tid*4+2] + red2[tid*4+3];
            float mu = s * (1.f/256.f);
            smu[tid] = mu;
            srs[tid] = rsqrtf(s2*(1.f/256.f) - mu*mu + 1e-5f);
        }
        __syncthreads();
        #pragma unroll
        for (int mi = 0; mi < 4; mi++) {
            #pragma unroll
            for (int h = 0; h < 2; h++) {
                const int rloc = wm0 + mi*16 + g + 8*h;
                const int m = m0 + rloc;
                float mu = smu[rloc], rs = srs[rloc];
                int win = m / 49, n = m % 49;
                int bq = win >> 6;
                int wr = (win >> 3) & 7;
                int wc = win & 7;
                int rr = n / 7, ccv = n % 7;
                int hh = wr*7 + rr + SHIFT3; if (hh >= 56) hh -= 56;
                int wwv = wc*7 + ccv + SHIFT3; if (wwv >= 56) wwv -= 56;
                size_t drow = (size_t)bq*HWS + hh*56 + wwv;
                #pragma unroll
                for (int ni = 0; ni < 8; ni++) {
                    const int col = wn0 + ni*8 + 2*c4;
                    float h0 = (acc[mi][ni][2*h+0] - mu)*rs*gamma[col  ] + beta2[col  ];
                    float h1 = (acc[mi][ni][2*h+1] - mu)*rs*gamma[col+1] + beta2[col+1];
                    *reinterpret_cast<__half2*>(&h2out[drow*CH + col]) = __floats2half2_rn(h0, h1);
                }
            }
        }
        return;
    }

    #pragma unroll
    for (int mi = 0; mi < 4; mi++) {
        #pragma unroll
        for (int h = 0; h < 2; h++) {
            const int m = m0 + wm0 + mi*16 + g + 8*h;
            int bq = 0, sp = 0;
            if (EPI == EPI_RES) { bq = m / HWS; sp = m % HWS; }
            #pragma unroll
            for (int ni = 0; ni < 8; ni++) {
                const int col = n0 + wn0 + ni*8 + 2*c4;
                float v0 = acc[mi][ni][2*h + 0] + bias[col];
                float v1 = acc[mi][ni][2*h + 1] + bias[col + 1];
                if (EPI == EPI_BIAS) {
                    __half2* C = (__half2*)Cp;
                    C[((size_t)m*N + col) >> 1] = __floats2half2_rn(v0, v1);
                } else if (EPI == EPI_GELU) {
                    __half2* C = (__half2*)Cp;
                    float g0 = 0.5f*v0*(1.f + erff(v0*0.70710678118654752f));
                    float g1 = 0.5f*v1*(1.f + erff(v1*0.70710678118654752f));
                    C[((size_t)m*N + col) >> 1] = __floats2half2_rn(g0, g1);
                } else { // EPI_RES
                    float* C = (float*)Cp;
                    float2 a = *reinterpret_cast<const float2*>(&aux[(size_t)m*N + col]);
                    C[((size_t)(bq*CH + col    ))*HWS + sp] = v0 + a.x;
                    C[((size_t)(bq*CH + col + 1))*HWS + sp] = v1 + a.y;
                }
            }
        }
    }
}

// ---------------- kernel 3: TC attention, CTA = (window, 4 heads), 256 thr ----------------
// Q/K/V row-major per head: 64 rows x 40 halfs (80B stride), tokens 0..48 valid.
#define T_STRIDE 40
#define REG_HALFS (64*T_STRIDE)         // 2560 halfs per tile
#define ATT_SMEM  (12*REG_HALFS*2)      // 61440 B -> 3 CTAs/SM

__global__ __launch_bounds__(256) void attn_kernel(
    const __half* __restrict__ qkv, __half* __restrict__ o)
{
    extern __shared__ __half ash[];
    const int win  = blockIdx.x >> 1;
    const int hgrp = blockIdx.x & 1;      // heads hgrp*4 .. hgrp*4+3
    const int tid  = threadIdx.x;
    const int warp = tid >> 5, lane = tid & 31;
    const int hloc = warp >> 1, half = warp & 1;
    const int head = hgrp*4 + hloc;
    const int g    = lane >> 2, c4 = lane & 3;
    const int fr   = ((lane >> 3) & 1) * 8 + (lane & 7);
    const int fk   = lane >> 4;

    __half* Qb = ash;
    __half* Kb = ash + 4*REG_HALFS;
    __half* Vb = ash + 8*REG_HALFS;

    // zero V token-pad rows 49..63 (4 heads x 15 rows x 5 chunks)
    for (int i = tid; i < 300; i += 256) {
        int h = i / 75, rem = i % 75;
        int row = 49 + rem / 5, q = rem % 5;
        *(uint4*)(Vb + h*REG_HALFS + row*T_STRIDE + q*8) = make_uint4(0,0,0,0);
    }
    __syncthreads();

    // load q,k,v for 4 heads: 49 tokens x 48 chunks
    const __half* src = qkv + (size_t)win*49*QKVN;
    for (int idx = tid; idx < 49*48; idx += 256) {
        int n = idx / 48, ck = idx % 48;
        int sec = ck >> 4;
        int cc  = ck & 15;
        int hl  = cc >> 2, dq = (cc & 3)*8;
        int col = sec*256 + (hgrp*4 + hl)*32 + dq;
        uint4 v = *(const uint4*)(src + (size_t)n*QKVN + col);
        __half* base = (sec == 0) ? Qb : (sec == 1) ? Kb : Vb;
        *(uint4*)(base + hl*REG_HALFS + n*T_STRIDE + dq) = v;
    }
    __syncthreads();

    const uint32_t Qsm = (uint32_t)__cvta_generic_to_shared(Qb + hloc*REG_HALFS)
                       + (half*32 + fr)*T_STRIDE*2;
    const uint32_t Ksm = (uint32_t)__cvta_generic_to_shared(Kb + hloc*REG_HALFS)
                       + fr*T_STRIDE*2;
    const uint32_t Vsm = (uint32_t)__cvta_generic_to_shared(Vb + hloc*REG_HALFS)
                       + fr*T_STRIDE*2;

    // ---- S = Q K^T (32 q-rows per warp) ----
    float acc[2][7][4];
    #pragma unroll
    for (int i = 0; i < 2; i++)
        #pragma unroll
        for (int j = 0; j < 7; j++)
            #pragma unroll
            for (int k = 0; k < 4; k++) acc[i][j][k] = 0.f;

    #pragma unroll
    for (int kk = 0; kk < 2; kk++) {
        const int kc = kk*2 + fk;
        uint32_t af[2][4], bf[4][4];
        #pragma unroll
        for (int mi = 0; mi < 2; mi++)
            ldsm4(af[mi][0], af[mi][1], af[mi][2], af[mi][3],
                  Qsm + mi*16*T_STRIDE*2 + kc*16);
        #pragma unroll
        for (int p = 0; p < 4; p++)
            ldsm4(bf[p][0], bf[p][1], bf[p][2], bf[p][3],
                  Ksm + p*16*T_STRIDE*2 + kc*16);
        #pragma unroll
        for (int mi = 0; mi < 2; mi++)
            #pragma unroll
            for (int ni = 0; ni < 7; ni++) {
                const int p = ni >> 1, sb = ni & 1;
                MMA16816(acc[mi][ni][0], acc[mi][ni][1], acc[mi][ni][2], acc[mi][ni][3],
                         af[mi][0], af[mi][1], af[mi][2], af[mi][3],
                         bf[p][sb], bf[p][2 + sb]);
            }
    }

    // ---- softmax (register) ----
    const float scale = 0.17677669529663687f;
    float mx[2][2], sum[2][2];
    #pragma unroll
    for (int mi = 0; mi < 2; mi++) { mx[mi][0] = mx[mi][1] = -1e30f; sum[mi][0] = sum[mi][1] = 0.f; }

    #pragma unroll
    for (int mi = 0; mi < 2; mi++)
        #pragma unroll
        for (int ni = 0; ni < 7; ni++)
            #pragma unroll
            for (int b = 0; b < 2; b++) {
                int j = ni*8 + 2*c4 + b;
                float v0 = acc[mi][ni][b]   * scale;
                float v1 = acc[mi][ni][2+b] * scale;
                if (j >= 49) { v0 = -1e30f; v1 = -1e30f; }
                acc[mi][ni][b] = v0; acc[mi][ni][2+b] = v1;
                mx[mi][0] = fmaxf(mx[mi][0], v0);
                mx[mi][1] = fmaxf(mx[mi][1], v1);
            }
    #pragma unroll
    for (int mi = 0; mi < 2; mi++)
        #pragma unroll
        for (int r = 0; r < 2; r++) {
            float m_ = mx[mi][r];
            m_ = fmaxf(m_, __shfl_xor_sync(0xffffffffu, m_, 1));
            m_ = fmaxf(m_, __shfl_xor_sync(0xffffffffu, m_, 2));
            mx[mi][r] = m_;
        }
    #pragma unroll
    for (int mi = 0; mi < 2; mi++)
        #pragma unroll
        for (int ni = 0; ni < 7; ni++)
            #pragma unroll
            for (int b = 0; b < 2; b++) {
                float e0 = __expf(acc[mi][ni][b]   - mx[mi][0]);
                float e1 = __expf(acc[mi][ni][2+b] - mx[mi][1]);
                acc[mi][ni][b] = e0; acc[mi][ni][2+b] = e1;
                sum[mi][0] += e0; sum[mi][1] += e1;
            }
    #pragma unroll
    for (int mi = 0; mi < 2; mi++)
        #pragma unroll
        for (int r = 0; r < 2; r++) {
            float s_ = sum[mi][r];
            s_ += __shfl_xor_sync(0xffffffffu, s_, 1);
            s_ += __shfl_xor_sync(0xffffffffu, s_, 2);
            sum[mi][r] = 1.f / s_;
        }

    uint32_t ph[2][7][2];
    #pragma unroll
    for (int mi = 0; mi < 2; mi++)
        #pragma unroll
        for (int ni = 0; ni < 7; ni++) {
            __half2 p0 = __floats2half2_rn(acc[mi][ni][0]*sum[mi][0], acc[mi][ni][1]*sum[mi][0]);
            __half2 p1 = __floats2half2_rn(acc[mi][ni][2]*sum[mi][1], acc[mi][ni][3]*sum[mi][1]);
            ph[mi][ni][0] = *reinterpret_cast<uint32_t*>(&p0);
            ph[mi][ni][1] = *reinterpret_cast<uint32_t*>(&p1);
        }

    // ---- O = P V  (V row-major, ldmatrix.trans B operand) ----
    float oacc[2][4][4];
    #pragma unroll
    for (int i = 0; i < 2; i++)
        #pragma unroll
        for (int j = 0; j < 4; j++)
            #pragma unroll
            for (int k = 0; k < 4; k++) oacc[i][j][k] = 0.f;

    #pragma unroll
    for (int kf = 0; kf < 4; kf++) {
        uint32_t bf[2][4];
        #pragma unroll
        for (int cp = 0; cp < 2; cp++)
            ldsm4t(bf[cp][0], bf[cp][1], bf[cp][2], bf[cp][3],
                   Vsm + kf*16*T_STRIDE*2 + (2*cp + fk)*16);
        #pragma unroll
        for (int mi = 0; mi < 2; mi++) {
            const int n0f = 2*kf, n1f = 2*kf + 1;
            uint32_t a0 = ph[mi][n0f][0], a1 = ph[mi][n0f][1];
            uint32_t a2 = (n1f < 7) ? ph[mi][n1f][0] : 0u;
            uint32_t a3 = (n1f < 7) ? ph[mi][n1f][1] : 0u;
            #pragma unroll
            for (int ni2 = 0; ni2 < 4; ni2++) {
                const int cp = ni2 >> 1, q = ni2 & 1;
                MMA16816(oacc[mi][ni2][0], oacc[mi][ni2][1], oacc[mi][ni2][2], oacc[mi][ni2][3],
                         a0, a1, a2, a3, bf[cp][2*q], bf[cp][2*q + 1]);
            }
        }
    }

    // ---- store O ----
    #pragma unroll
    for (int mi = 0; mi < 2; mi++) {
        const int i0 = half*32 + mi*16 + g, i1 = i0 + 8;
        #pragma unroll
        for (int ni2 = 0; ni2 < 4; ni2++) {
            const int col = head*HDIM + ni2*8 + 2*c4;
            if (i0 < 49) {
                __half2 v = __floats2half2_rn(oacc[mi][ni2][0], oacc[mi][ni2][1]);
                *reinterpret_cast<__half2*>(&o[((size_t)win*49 + i0)*CH + col]) = v;
            }
            if (i1 < 49) {
                __half2 v = __floats2half2_rn(oacc[mi][ni2][2], oacc[mi][ni2][3]);
                *reinterpret_cast<__half2*>(&o[((size_t)win*49 + i1)*CH + col]) = v;
            }
        }
    }
}

// ---------------- launch ----------------
extern "C" void kernel_launch(void* const* d_in, const int* in_sizes, int n_in,
                              void* d_out, int out_size)
{
    const float* x      = (const float*)d_in[0];
    const float* n1_g   = (const float*)d_in[1];
    const float* n1_b   = (const float*)d_in[2];
    const float* qkv_w  = (const float*)d_in[3];
    const float* qkv_b  = (const float*)d_in[4];
    const float* proj_w = (const float*)d_in[5];
    const float* proj_b = (const float*)d_in[6];
    const float* n2_g   = (const float*)d_in[7];
    const float* n2_b   = (const float*)d_in[8];
    const float* mlp_w1 = (const float*)d_in[9];
    const float* mlp_b1 = (const float*)d_in[10];
    const float* mlp_w2 = (const float*)d_in[11];
    const float* mlp_b2 = (const float*)d_in[12];

    __half *ywin, *qkvb, *ow, *h2, *hmid;
    float  *x1;
    __half *wqkv, *wproj, *w1, *w2;
    cudaGetSymbolAddress((void**)&ywin,  g_ywin);
    cudaGetSymbolAddress((void**)&qkvb,  g_qkv);
    cudaGetSymbolAddress((void**)&ow,    g_ow);
    cudaGetSymbolAddress((void**)&x1,    g_x1);
    cudaGetSymbolAddress((void**)&h2,    g_h2);
    cudaGetSymbolAddress((void**)&hmid,  g_hmid);
    cudaGetSymbolAddress((void**)&wqkv,  g_wqkv);
    cudaGetSymbolAddress((void**)&wproj, g_wproj);
    cudaGetSymbolAddress((void**)&w1,    g_w1);
    cudaGetSymbolAddress((void**)&w2,    g_w2);

    static bool attr_done = false;
    if (!attr_done) {
        cudaFuncSetAttribute(mma_gemm<EPI_BIAS>,   cudaFuncAttributeMaxDynamicSharedMemorySize, SMEM_DYN);
        cudaFuncSetAttribute(mma_gemm<EPI_PROJLN>, cudaFuncAttributeMaxDynamicSharedMemorySize, SMEM_DYN);
        cudaFuncSetAttribute(mma_gemm<EPI_GELU>,   cudaFuncAttributeMaxDynamicSharedMemorySize, SMEM_DYN);
        cudaFuncSetAttribute(mma_gemm<EPI_RES>,    cudaFuncAttributeMaxDynamicSharedMemorySize, SMEM_DYN);
        cudaFuncSetAttribute(attn_kernel,          cudaFuncAttributeMaxDynamicSharedMemorySize, ATT_SMEM);
        attr_done = true;
    }

    // 0) all weights: transpose + fp16 round -> [N][K]
    transpose_round_all<<<768, 256>>>(qkv_w, wqkv, proj_w, wproj, mlp_w1, w1, mlp_w2, w2);

    // 1) LN1 + shift + window partition
    ln1_kernel<<<BATCH*98, 256>>>(x, n1_g, n1_b, ywin);

    // 2) qkv = ywin @ qkv_w + qkv_b
    mma_gemm<EPI_BIAS><<<dim3(QKVN/256, TOK/128), 256, SMEM_DYN>>>(
        ywin, wqkv, qkv_b, qkvb, nullptr, nullptr, nullptr, nullptr, TOK, QKVN, CH);

    // 3) tensor-core windowed attention (2 CTAs per window, 4 heads each)
    attn_kernel<<<4096, 256, ATT_SMEM>>>(qkvb, ow);

    // 4) x1 = shortcut(x) + proj(ow); h2 = LN2(x1)   (fused)
    mma_gemm<EPI_PROJLN><<<dim3(CH/256, TOK/128), 256, SMEM_DYN>>>(
        ow, wproj, proj_b, x1, x, n2_g, n2_b, h2, TOK, CH, CH);

    // 5) hmid = gelu(h2 @ mlp_w1 + mlp_b1)
    mma_gemm<EPI_GELU><<<dim3(HIDDEN/256, TOK/128), 256, SMEM_DYN>>>(
        h2, w1, mlp_b1, hmid, nullptr, nullptr, nullptr, nullptr, TOK, HIDDEN, CH);

    // 6) out(NCHW) = x1 + hmid @ mlp_w2 + mlp_b2   (fused transpose)
    mma_gemm<EPI_RES><<<dim3(CH/256, TOK/128), 256, SMEM_DYN>>>(
        hmid, w2, mlp_b2, (float*)d_out, x1, nullptr, nullptr, nullptr, TOK, CH, HIDDEN);
}

// round 11
// speedup vs baseline: 1.6759x; 1.6759x over previous
#include <cuda_runtime.h>
#include <cuda_fp16.h>
#include <math.h>
#include <stdint.h>

// ---------------- problem constants ----------------
#define BATCH 32
#define CH    256
#define HWS   3136
#define TOK   100352
#define SHIFT3 3
#define HEADS 8
#define HDIM  32
#define HIDDEN 1024
#define QKVN  768

// ---------------- scratch ----------------
__device__ __half g_ywin [(size_t)TOK*CH];
__device__ __half g_qkv  [(size_t)TOK*QKVN];
__device__ __half g_ow   [(size_t)TOK*CH];
__device__ float  g_x1   [(size_t)TOK*CH];
__device__ __half g_h2   [(size_t)TOK*CH];
__device__ __half g_hmid [(size_t)TOK*HIDDEN];
// fp16, TRANSPOSED weight copies: [N][K]
__device__ __half g_wqkv [QKVN*CH];
__device__ __half g_wproj[CH*CH];
__device__ __half g_w1   [HIDDEN*CH];
__device__ __half g_w2   [CH*HIDDEN];

__device__ __forceinline__ void cpasync16(uint32_t dst, const void* src) {
    asm volatile("cp.async.cg.shared.global [%0], [%1], 16;" :: "r"(dst), "l"(src));
}

__device__ __forceinline__ void ldsm4(uint32_t& r0, uint32_t& r1, uint32_t& r2, uint32_t& r3,
                                      uint32_t addr) {
    asm volatile("ldmatrix.sync.aligned.m8n8.x4.shared.b16 {%0,%1,%2,%3}, [%4];"
                 : "=r"(r0), "=r"(r1), "=r"(r2), "=r"(r3) : "r"(addr));
}

__device__ __forceinline__ void ldsm4t(uint32_t& r0, uint32_t& r1, uint32_t& r2, uint32_t& r3,
                                       uint32_t addr) {
    asm volatile("ldmatrix.sync.aligned.m8n8.x4.trans.shared.b16 {%0,%1,%2,%3}, [%4];"
                 : "=r"(r0), "=r"(r1), "=r"(r2), "=r"(r3) : "r"(addr));
}

#define MMA16816(d0,d1,d2,d3,a0,a1,a2,a3,b0,b1) \
    asm volatile( \
        "mma.sync.aligned.m16n8k16.row.col.f32.f16.f16.f32 " \
        "{%0,%1,%2,%3}, {%4,%5,%6,%7}, {%8,%9}, {%0,%1,%2,%3};" \
        : "+f"(d0), "+f"(d1), "+f"(d2), "+f"(d3) \
        : "r"(a0), "r"(a1), "r"(a2), "r"(a3), "r"(b0), "r"(b1))

// ---------------- prep: ALL weights transpose + fp16 round, one launch ----------------
__global__ __launch_bounds__(256) void transpose_round_all(
    const float* __restrict__ w0, __half* __restrict__ o0,
    const float* __restrict__ w1_, __half* __restrict__ o1,
    const float* __restrict__ w2_, __half* __restrict__ o2,
    const float* __restrict__ w3_, __half* __restrict__ o3)
{
    __shared__ float t[32][33];
    int blk = blockIdx.x;
    const float* w; __half* wt; int K, N, nb;
    if (blk < 192)      { w = w0;  wt = o0; K = CH;     N = QKVN;   nb = QKVN/32; }
    else if (blk < 256) { blk -= 192; w = w1_; wt = o1; K = CH;     N = CH;     nb = CH/32; }
    else if (blk < 512) { blk -= 256; w = w2_; wt = o2; K = CH;     N = HIDDEN; nb = HIDDEN/32; }
    else                { blk -= 512; w = w3_; wt = o3; K = HIDDEN; N = CH;     nb = CH/32; }
    const int k0 = (blk / nb) * 32, n0 = (blk % nb) * 32;
    const int x = threadIdx.x & 31, y = threadIdx.x >> 5;
    for (int yy = y; yy < 32; yy += 8)
        t[yy][x] = w[(size_t)(k0 + yy)*N + n0 + x];
    __syncthreads();
    for (int yy = y; yy < 32; yy += 8)
        wt[(size_t)(n0 + yy)*K + k0 + x] = __float2half_rn(t[x][yy]);
}

// ---------------- kernel 1: LN1 + shift + window partition ----------------
__global__ __launch_bounds__(256) void ln1_kernel(
    const float* __restrict__ x, const float* __restrict__ g, const float* __restrict__ bta,
    __half* __restrict__ ywin)
{
    __shared__ float ts[256*33];
    __shared__ float cmu[32], crs[32];
    const int blk = blockIdx.x;
    const int b   = blk / 98;
    const int hw0 = (blk % 98) * 32;
    const int tid = threadIdx.x;
    const float* xb = x + (size_t)b*CH*HWS;

    for (int idx = tid; idx < 256*32; idx += 256) {
        int ch = idx >> 5, j = idx & 31;
        ts[ch*33 + j] = xb[(size_t)ch*HWS + hw0 + j];
    }
    __syncthreads();

    {
        int col = tid >> 3, kk = tid & 7;
        float s = 0.f, s2 = 0.f;
        for (int ch = kk; ch < 256; ch += 8) {
            float v = ts[ch*33 + col];
            s += v; s2 += v*v;
        }
        #pragma unroll
        for (int o = 4; o; o >>= 1) {
            s  += __shfl_down_sync(0xffffffffu, s,  o, 8);
            s2 += __shfl_down_sync(0xffffffffu, s2, o, 8);
        }
        if (kk == 0) {
            float mu = s * (1.f/256.f);
            cmu[col] = mu;
            crs[col] = rsqrtf(s2*(1.f/256.f) - mu*mu + 1e-5f);
        }
    }
    __syncthreads();

    const float gg = g[tid], bb = bta[tid];
    for (int j = 0; j < 32; j++) {
        int hw = hw0 + j;
        int h = hw / 56, w = hw % 56;
        int hs = h + (56 - SHIFT3); if (hs >= 56) hs -= 56;
        int wsh = w + (56 - SHIFT3); if (wsh >= 56) wsh -= 56;
        int wi = hs / 7, r = hs % 7;
        int wj = wsh / 7, c = wsh % 7;
        int win = ((b << 3) + wi) * 8 + wj;
        int n = r*7 + c;
        ywin[((size_t)win*49 + n)*CH + tid] =
            __float2half_rn((ts[tid*33 + j] - cmu[j]) * crs[j] * gg + bb);
    }
}

// ---------------- fp16 mma GEMM: CTA 128x256, warp 64x64, BK=64, 3-stage ----------------
#define BK 64
#define STAGES 3
#define A_STAGE_B (128*128)
#define B_STAGE_B (256*128)
#define STAGE_B   (A_STAGE_B + B_STAGE_B)
#define SMEM_DYN  (STAGES*STAGE_B)

enum { EPI_BIAS = 0, EPI_PROJLN = 1, EPI_GELU = 2, EPI_RES = 3 };

template<int EPI>
__global__ __launch_bounds__(256) void mma_gemm(
    const __half* __restrict__ A, const __half* __restrict__ BT,
    const float* __restrict__ bias, void* __restrict__ Cp,
    const float* __restrict__ aux,
    const float* __restrict__ gamma, const float* __restrict__ beta2,
    __half* __restrict__ h2out,
    int M, int N, int K)
{
    extern __shared__ char sm[];
    const uint32_t smb = (uint32_t)__cvta_generic_to_shared(sm);

    const int tid  = threadIdx.x;
    const int lane = tid & 31, warp = tid >> 5;
    const int g    = lane >> 2, c4 = lane & 3;
    const int wm0  = (warp >> 2) * 64;
    const int wn0  = (warp & 3) * 64;
    const int m0   = blockIdx.y * 128, n0 = blockIdx.x * 256;

    const int fr  = ((lane >> 3) & 1) * 8 + (lane & 7);
    const int fk  = lane >> 4;

    int arow[4], asw[4], brow[4], bsw[4];
    #pragma unroll
    for (int i = 0; i < 4; i++) {
        int ra = wm0 + i*16 + fr;
        arow[i] = ra*128; asw[i] = ra & 7;
        int rb = wn0 + i*16 + fr;
        brow[i] = rb*128; bsw[i] = rb & 7;
    }

    const int cr = tid >> 3, cc = tid & 7;

    float acc[4][8][4];
    #pragma unroll
    for (int i = 0; i < 4; i++)
        #pragma unroll
        for (int j = 0; j < 8; j++)
            #pragma unroll
            for (int k = 0; k < 4; k++) acc[i][j][k] = 0.f;

    auto fill = [&](int t) {
        const int s = t % STAGES;
        const uint32_t ab = smb + (uint32_t)(s*STAGE_B);
        const uint32_t bb = ab + A_STAGE_B;
        const int k0 = t * BK;
        #pragma unroll
        for (int i = 0; i < 4; i++) {
            int rr = cr + 32*i;
            cpasync16(ab + (uint32_t)(rr*128) + (uint32_t)((cc ^ (rr & 7)) << 4),
                      &A[(size_t)(m0 + rr)*K + k0 + cc*8]);
        }
        #pragma unroll
        for (int i = 0; i < 8; i++) {
            int rr = cr + 32*i;
            cpasync16(bb + (uint32_t)(rr*128) + (uint32_t)((cc ^ (rr & 7)) << 4),
                      &BT[(size_t)(n0 + rr)*K + k0 + cc*8]);
        }
    };

    const int nt = K / BK;
    #pragma unroll
    for (int s = 0; s < STAGES-1; s++) {
        fill(s);
        asm volatile("cp.async.commit_group;");
    }

    for (int t = 0; t < nt; t++) {
        asm volatile("cp.async.wait_group %0;" :: "n"(STAGES-2));
        __syncthreads();
        if (t + STAGES - 1 < nt) fill(t + STAGES - 1);
        asm volatile("cp.async.commit_group;");

        const uint32_t ab = smb + (uint32_t)((t % STAGES)*STAGE_B);
        const uint32_t bb = ab + A_STAGE_B;

        #pragma unroll
        for (int kk = 0; kk < 4; kk++) {
            const int kc = kk*2 + fk;
            uint32_t af[4][4], bf[4][4];
            #pragma unroll
            for (int mi = 0; mi < 4; mi++)
                ldsm4(af[mi][0], af[mi][1], af[mi][2], af[mi][3],
                      ab + (uint32_t)arow[mi] + (uint32_t)((kc ^ asw[mi]) << 4));
            #pragma unroll
            for (int np = 0; np < 4; np++)
                ldsm4(bf[np][0], bf[np][1], bf[np][2], bf[np][3],
                      bb + (uint32_t)brow[np] + (uint32_t)((kc ^ bsw[np]) << 4));

            #pragma unroll
            for (int mi = 0; mi < 4; mi++)
                #pragma unroll
                for (int ni = 0; ni < 8; ni++) {
                    const int p = ni >> 1, sb = ni & 1;
                    MMA16816(acc[mi][ni][0], acc[mi][ni][1], acc[mi][ni][2], acc[mi][ni][3],
                             af[mi][0], af[mi][1], af[mi][2], af[mi][3],
                             bf[p][sb], bf[p][2 + sb]);
                }
        }
    }

    // -------- epilogue --------
    if (EPI == EPI_PROJLN) {
        asm volatile("cp.async.wait_group 0;" ::: "memory");
        __syncthreads();
        float* red  = (float*)sm;
        float* red2 = red + 512;
        float* smu  = red2 + 512;
        float* srs  = smu + 128;

        float* C = (float*)Cp;
        float psum[4][2], psum2[4][2];
        #pragma unroll
        for (int mi = 0; mi < 4; mi++) { psum[mi][0]=psum[mi][1]=psum2[mi][0]=psum2[mi][1]=0.f; }

        #pragma unroll
        for (int mi = 0; mi < 4; mi++) {
            #pragma unroll
            for (int h = 0; h < 2; h++) {
                const int m = m0 + wm0 + mi*16 + g + 8*h;
                int win = m / 49, n = m % 49;
                int bq = win >> 6;
                int wr = (win >> 3) & 7;
                int wc = win & 7;
                int rr = n / 7, ccv = n % 7;
                int hh = wr*7 + rr + SHIFT3; if (hh >= 56) hh -= 56;
                int wwv = wc*7 + ccv + SHIFT3; if (wwv >= 56) wwv -= 56;
                int sp = hh*56 + wwv;
                size_t drow = (size_t)bq*HWS + sp;
                #pragma unroll
                for (int ni = 0; ni < 8; ni++) {
                    const int col = wn0 + ni*8 + 2*c4;
                    float v0 = acc[mi][ni][2*h+0] + bias[col] + aux[((size_t)(bq*CH + col    ))*HWS + sp];
                    float v1 = acc[mi][ni][2*h+1] + bias[col+1] + aux[((size_t)(bq*CH + col + 1))*HWS + sp];
                    acc[mi][ni][2*h+0] = v0; acc[mi][ni][2*h+1] = v1;
                    float2 out; out.x = v0; out.y = v1;
                    *reinterpret_cast<float2*>(&C[drow*CH + col]) = out;
                    psum [mi][h] += v0 + v1;
                    psum2[mi][h] += v0*v0 + v1*v1;
                }
            }
        }
        #pragma unroll
        for (int mi = 0; mi < 4; mi++)
            #pragma unroll
            for (int h = 0; h < 2; h++) {
                float s = psum[mi][h], s2 = psum2[mi][h];
                s  += __shfl_xor_sync(0xffffffffu, s, 1);  s  += __shfl_xor_sync(0xffffffffu, s, 2);
                s2 += __shfl_xor_sync(0xffffffffu, s2, 1); s2 += __shfl_xor_sync(0xffffffffu, s2, 2);
                if (c4 == 0) {
                    int rloc = wm0 + mi*16 + g + 8*h;
                    red [rloc*4 + (warp & 3)] = s;
                    red2[rloc*4 + (warp & 3)] = s2;
                }
            }
        __syncthreads();
        if (tid < 128) {
            float s  = red [tid*4] + red [tid*4+1] + red [tid*4+2] + red [tid*4+3];
            float s2 = red2[tid*4] + red2[tid*4+1] + red2[tid*4+2] + red2[tid*4+3];
            float mu = s * (1.f/256.f);
            smu[tid] = mu;
            srs[tid] = rsqrtf(s2*(1.f/256.f) - mu*mu + 1e-5f);
        }
        __syncthreads();
        #pragma unroll
        for (int mi = 0; mi < 4; mi++) {
            #pragma unroll
            for (int h = 0; h < 2; h++) {
                const int rloc = wm0 + mi*16 + g + 8*h;
                const int m = m0 + rloc;
                float mu = smu[rloc], rs = srs[rloc];
                int win = m / 49, n = m % 49;
                int bq = win >> 6;
                int wr = (win >> 3) & 7;
                int wc = win & 7;
                int rr = n / 7, ccv = n % 7;
                int hh = wr*7 + rr + SHIFT3; if (hh >= 56) hh -= 56;
                int wwv = wc*7 + ccv + SHIFT3; if (wwv >= 56) wwv -= 56;
                size_t drow = (size_t)bq*HWS + hh*56 + wwv;
                #pragma unroll
                for (int ni = 0; ni < 8; ni++) {
                    const int col = wn0 + ni*8 + 2*c4;
                    float h0 = (acc[mi][ni][2*h+0] - mu)*rs*gamma[col  ] + beta2[col  ];
                    float h1 = (acc[mi][ni][2*h+1] - mu)*rs*gamma[col+1] + beta2[col+1];
                    *reinterpret_cast<__half2*>(&h2out[drow*CH + col]) = __floats2half2_rn(h0, h1);
                }
            }
        }
        return;
    }

    #pragma unroll
    for (int mi = 0; mi < 4; mi++) {
        #pragma unroll
        for (int h = 0; h < 2; h++) {
            const int m = m0 + wm0 + mi*16 + g + 8*h;
            int bq = 0, sp = 0;
            if (EPI == EPI_RES) { bq = m / HWS; sp = m % HWS; }
            #pragma unroll
            for (int ni = 0; ni < 8; ni++) {
                const int col = n0 + wn0 + ni*8 + 2*c4;
                float v0 = acc[mi][ni][2*h + 0] + bias[col];
                float v1 = acc[mi][ni][2*h + 1] + bias[col + 1];
                if (EPI == EPI_BIAS) {
                    __half2* C = (__half2*)Cp;
                    C[((size_t)m*N + col) >> 1] = __floats2half2_rn(v0, v1);
                } else if (EPI == EPI_GELU) {
                    __half2* C = (__half2*)Cp;
                    float g0 = 0.5f*v0*(1.f + erff(v0*0.70710678118654752f));
                    float g1 = 0.5f*v1*(1.f + erff(v1*0.70710678118654752f));
                    C[((size_t)m*N + col) >> 1] = __floats2half2_rn(g0, g1);
                } else { // EPI_RES
                    float* C = (float*)Cp;
                    float2 a = *reinterpret_cast<const float2*>(&aux[(size_t)m*N + col]);
                    C[((size_t)(bq*CH + col    ))*HWS + sp] = v0 + a.x;
                    C[((size_t)(bq*CH + col + 1))*HWS + sp] = v1 + a.y;
                }
            }
        }
    }
}

// ---------------- kernel 3: TC attention, CTA = (window, 4 heads), 256 thr ----------------
#define T_STRIDE 40
#define REG_HALFS (64*T_STRIDE)
#define ATT_SMEM  (12*REG_HALFS*2)      // 61440 B -> 3 CTAs/SM

__global__ __launch_bounds__(256) void attn_kernel(
    const __half* __restrict__ qkv, __half* __restrict__ o)
{
    extern __shared__ __half ash[];
    const int win  = blockIdx.x >> 1;
    const int hgrp = blockIdx.x & 1;
    const int tid  = threadIdx.x;
    const int warp = tid >> 5, lane = tid & 31;
    const int hloc = warp >> 1, half = warp & 1;
    const int head = hgrp*4 + hloc;
    const int g    = lane >> 2, c4 = lane & 3;
    const int fr   = ((lane >> 3) & 1) * 8 + (lane & 7);
    const int fk   = lane >> 4;

    __half* Qb = ash;
    __half* Kb = ash + 4*REG_HALFS;
    __half* Vb = ash + 8*REG_HALFS;

    for (int i = tid; i < 300; i += 256) {
        int h = i / 75, rem = i % 75;
        int row = 49 + rem / 5, q = rem % 5;
        *(uint4*)(Vb + h*REG_HALFS + row*T_STRIDE + q*8) = make_uint4(0,0,0,0);
    }
    __syncthreads();

    const __half* src = qkv + (size_t)win*49*QKVN;
    for (int idx = tid; idx < 49*48; idx += 256) {
        int n = idx / 48, ck = idx % 48;
        int sec = ck >> 4;
        int cc  = ck & 15;
        int hl  = cc >> 2, dq = (cc & 3)*8;
        int col = sec*256 + (hgrp*4 + hl)*32 + dq;
        uint4 v = *(const uint4*)(src + (size_t)n*QKVN + col);
        __half* base = (sec == 0) ? Qb : (sec == 1) ? Kb : Vb;
        *(uint4*)(base + hl*REG_HALFS + n*T_STRIDE + dq) = v;
    }
    __syncthreads();

    const uint32_t Qsm = (uint32_t)__cvta_generic_to_shared(Qb + hloc*REG_HALFS)
                       + (half*32 + fr)*T_STRIDE*2;
    const uint32_t Ksm = (uint32_t)__cvta_generic_to_shared(Kb + hloc*REG_HALFS)
                       + fr*T_STRIDE*2;
    const uint32_t Vsm = (uint32_t)__cvta_generic_to_shared(Vb + hloc*REG_HALFS)
                       + fr*T_STRIDE*2;

    float acc[2][7][4];
    #pragma unroll
    for (int i = 0; i < 2; i++)
        #pragma unroll
        for (int j = 0; j < 7; j++)
            #pragma unroll
            for (int k = 0; k < 4; k++) acc[i][j][k] = 0.f;

    #pragma unroll
    for (int kk = 0; kk < 2; kk++) {
        const int kc = kk*2 + fk;
        uint32_t af[2][4], bf[4][4];
        #pragma unroll
        for (int mi = 0; mi < 2; mi++)
            ldsm4(af[mi][0], af[mi][1], af[mi][2], af[mi][3],
                  Qsm + mi*16*T_STRIDE*2 + kc*16);
        #pragma unroll
        for (int p = 0; p < 4; p++)
            ldsm4(bf[p][0], bf[p][1], bf[p][2], bf[p][3],
                  Ksm + p*16*T_STRIDE*2 + kc*16);
        #pragma unroll
        for (int mi = 0; mi < 2; mi++)
            #pragma unroll
            for (int ni = 0; ni < 7; ni++) {
                const int p = ni >> 1, sb = ni & 1;
                MMA16816(acc[mi][ni][0], acc[mi][ni][1], acc[mi][ni][2], acc[mi][ni][3],
                         af[mi][0], af[mi][1], af[mi][2], af[mi][3],
                         bf[p][sb], bf[p][2 + sb]);
            }
    }

    const float scale = 0.17677669529663687f;
    float mx[2][2], sum[2][2];
    #pragma unroll
    for (int mi = 0; mi < 2; mi++) { mx[mi][0] = mx[mi][1] = -1e30f; sum[mi][0] = sum[mi][1] = 0.f; }

    #pragma unroll
    for (int mi = 0; mi < 2; mi++)
        #pragma unroll
        for (int ni = 0; ni < 7; ni++)
            #pragma unroll
            for (int b = 0; b < 2; b++) {
                int j = ni*8 + 2*c4 + b;
                float v0 = acc[mi][ni][b]   * scale;
                float v1 = acc[mi][ni][2+b] * scale;
                if (j >= 49) { v0 = -1e30f; v1 = -1e30f; }
                acc[mi][ni][b] = v0; acc[mi][ni][2+b] = v1;
                mx[mi][0] = fmaxf(mx[mi][0], v0);
                mx[mi][1] = fmaxf(mx[mi][1], v1);
            }
    #pragma unroll
    for (int mi = 0; mi < 2; mi++)
        #pragma unroll
        for (int r = 0; r < 2; r++) {
            float m_ = mx[mi][r];
            m_ = fmaxf(m_, __shfl_xor_sync(0xffffffffu, m_, 1));
            m_ = fmaxf(m_, __shfl_xor_sync(0xffffffffu, m_, 2));
            mx[mi][r] = m_;
        }
    #pragma unroll
    for (int mi = 0; mi < 2; mi++)
        #pragma unroll
        for (int ni = 0; ni < 7; ni++)
            #pragma unroll
            for (int b = 0; b < 2; b++) {
                float e0 = __expf(acc[mi][ni][b]   - mx[mi][0]);
                float e1 = __expf(acc[mi][ni][2+b] - mx[mi][1]);
                acc[mi][ni][b] = e0; acc[mi][ni][2+b] = e1;
                sum[mi][0] += e0; sum[mi][1] += e1;
            }
    #pragma unroll
    for (int mi = 0; mi < 2; mi++)
        #pragma unroll
        for (int r = 0; r < 2; r++) {
            float s_ = sum[mi][r];
            s_ += __shfl_xor_sync(0xffffffffu, s_, 1);
            s_ += __shfl_xor_sync(0xffffffffu, s_, 2);
            sum[mi][r] = 1.f / s_;
        }

    uint32_t ph[2][7][2];
    #pragma unroll
    for (int mi = 0; mi < 2; mi++)
        #pragma unroll
        for (int ni = 0; ni < 7; ni++) {
            __half2 p0 = __floats2half2_rn(acc[mi][ni][0]*sum[mi][0], acc[mi][ni][1]*sum[mi][0]);
            __half2 p1 = __floats2half2_rn(acc[mi][ni][2]*sum[mi][1], acc[mi][ni][3]*sum[mi][1]);
            ph[mi][ni][0] = *reinterpret_cast<uint32_t*>(&p0);
            ph[mi][ni][1] = *reinterpret_cast<uint32_t*>(&p1);
        }

    float oacc[2][4][4];
    #pragma unroll
    for (int i = 0; i < 2; i++)
        #pragma unroll
        for (int j = 0; j < 4; j++)
            #pragma unroll
            for (int k = 0; k < 4; k++) oacc[i][j][k] = 0.f;

    #pragma unroll
    for (int kf = 0; kf < 4; kf++) {
        uint32_t bf[2][4];
        #pragma unroll
        for (int cp = 0; cp < 2; cp++)
            ldsm4t(bf[cp][0], bf[cp][1], bf[cp][2], bf[cp][3],
                   Vsm + kf*16*T_STRIDE*2 + (2*cp + fk)*16);
        #pragma unroll
        for (int mi = 0; mi < 2; mi++) {
            const int n0f = 2*kf, n1f = 2*kf + 1;
            uint32_t a0 = ph[mi][n0f][0], a1 = ph[mi][n0f][1];
            uint32_t a2 = (n1f < 7) ? ph[mi][n1f][0] : 0u;
            uint32_t a3 = (n1f < 7) ? ph[mi][n1f][1] : 0u;
            #pragma unroll
            for (int ni2 = 0; ni2 < 4; ni2++) {
                const int cp = ni2 >> 1, q = ni2 & 1;
                MMA16816(oacc[mi][ni2][0], oacc[mi][ni2][1], oacc[mi][ni2][2], oacc[mi][ni2][3],
                         a0, a1, a2, a3, bf[cp][2*q], bf[cp][2*q + 1]);
            }
        }
    }

    #pragma unroll
    for (int mi = 0; mi < 2; mi++) {
        const int i0 = half*32 + mi*16 + g, i1 = i0 + 8;
        #pragma unroll
        for (int ni2 = 0; ni2 < 4; ni2++) {
            const int col = head*HDIM + ni2*8 + 2*c4;
            if (i0 < 49) {
                __half2 v = __floats2half2_rn(oacc[mi][ni2][0], oacc[mi][ni2][1]);
                *reinterpret_cast<__half2*>(&o[((size_t)win*49 + i0)*CH + col]) = v;
            }
            if (i1 < 49) {
                __half2 v = __floats2half2_rn(oacc[mi][ni2][2], oacc[mi][ni2][3]);
                *reinterpret_cast<__half2*>(&o[((size_t)win*49 + i1)*CH + col]) = v;
            }
        }
    }
}

// ---------------- launch ----------------
extern "C" void kernel_launch(void* const* d_in, const int* in_sizes, int n_in,
                              void* d_out, int out_size)
{
    const float* x      = (const float*)d_in[0];
    const float* n1_g   = (const float*)d_in[1];
    const float* n1_b   = (const float*)d_in[2];
    const float* qkv_w  = (const float*)d_in[3];
    const float* qkv_b  = (const float*)d_in[4];
    const float* proj_w = (const float*)d_in[5];
    const float* proj_b = (const float*)d_in[6];
    const float* n2_g   = (const float*)d_in[7];
    const float* n2_b   = (const float*)d_in[8];
    const float* mlp_w1 = (const float*)d_in[9];
    const float* mlp_b1 = (const float*)d_in[10];
    const float* mlp_w2 = (const float*)d_in[11];
    const float* mlp_b2 = (const float*)d_in[12];

    __half *ywin, *qkvb, *ow, *h2, *hmid;
    float  *x1;
    __half *wqkv, *wproj, *w1, *w2;
    cudaGetSymbolAddress((void**)&ywin,  g_ywin);
    cudaGetSymbolAddress((void**)&qkvb,  g_qkv);
    cudaGetSymbolAddress((void**)&ow,    g_ow);
    cudaGetSymbolAddress((void**)&x1,    g_x1);
    cudaGetSymbolAddress((void**)&h2,    g_h2);
    cudaGetSymbolAddress((void**)&hmid,  g_hmid);
    cudaGetSymbolAddress((void**)&wqkv,  g_wqkv);
    cudaGetSymbolAddress((void**)&wproj, g_wproj);
    cudaGetSymbolAddress((void**)&w1,    g_w1);
    cudaGetSymbolAddress((void**)&w2,    g_w2);

    static bool attr_done = false;
    if (!attr_done) {
        cudaFuncSetAttribute(mma_gemm<EPI_BIAS>,   cudaFuncAttributeMaxDynamicSharedMemorySize, SMEM_DYN);
        cudaFuncSetAttribute(mma_gemm<EPI_PROJLN>, cudaFuncAttributeMaxDynamicSharedMemorySize, SMEM_DYN);
        cudaFuncSetAttribute(mma_gemm<EPI_GELU>,   cudaFuncAttributeMaxDynamicSharedMemorySize, SMEM_DYN);
        cudaFuncSetAttribute(mma_gemm<EPI_RES>,    cudaFuncAttributeMaxDynamicSharedMemorySize, SMEM_DYN);
        cudaFuncSetAttribute(attn_kernel,          cudaFuncAttributeMaxDynamicSharedMemorySize, ATT_SMEM);
        attr_done = true;
    }

    // 0) all weights: transpose + fp16 round -> [N][K]
    transpose_round_all<<<768, 256>>>(qkv_w, wqkv, proj_w, wproj, mlp_w1, w1, mlp_w2, w2);

    // 1) LN1 + shift + window partition
    ln1_kernel<<<BATCH*98, 256>>>(x, n1_g, n1_b, ywin);

    // 2) qkv = ywin @ qkv_w + qkv_b
    mma_gemm<EPI_BIAS><<<dim3(QKVN/256, TOK/128), 256, SMEM_DYN>>>(
        ywin, wqkv, qkv_b, qkvb, nullptr, nullptr, nullptr, nullptr, TOK, QKVN, CH);

    // 3) tensor-core windowed attention (2 CTAs per window, 4 heads each)
    attn_kernel<<<4096, 256, ATT_SMEM>>>(qkvb, ow);

    // 4) x1 = shortcut(x) + proj(ow); h2 = LN2(x1)   (fused)
    mma_gemm<EPI_PROJLN><<<dim3(CH/256, TOK/128), 256, SMEM_DYN>>>(
        ow, wproj, proj_b, x1, x, n2_g, n2_b, h2, TOK, CH, CH);

    // 5) hmid = gelu(h2 @ mlp_w1 + mlp_b1)
    mma_gemm<EPI_GELU><<<dim3(HIDDEN/256, TOK/128), 256, SMEM_DYN>>>(
        h2, w1, mlp_b1, hmid, nullptr, nullptr, nullptr, nullptr, TOK, HIDDEN, CH);

    // 6) out(NCHW) = x1 + hmid @ mlp_w2 + mlp_b2   (fused transpose)
    mma_gemm<EPI_RES><<<dim3(CH/256, TOK/128), 256, SMEM_DYN>>>(
        hmid, w2, mlp_b2, (float*)d_out, x1, nullptr, nullptr, nullptr, TOK, CH, HIDDEN);
}

// round 12
// speedup vs baseline: 1.7006x; 1.0147x over previous
#include <cuda_runtime.h>
#include <cuda_fp16.h>
#include <math.h>
#include <stdint.h>

// ---------------- problem constants ----------------
#define BATCH 32
#define CH    256
#define HWS   3136
#define TOK   100352
#define SHIFT3 3
#define HEADS 8
#define HDIM  32
#define HIDDEN 1024
#define QKVN  768

// ---------------- scratch ----------------
__device__ __half g_ywin [(size_t)TOK*CH];
__device__ __half g_qkv  [(size_t)TOK*QKVN];
__device__ __half g_ow   [(size_t)TOK*CH];
__device__ __half g_x1   [(size_t)TOK*CH];     // fp16 residual
__device__ __half g_h2   [(size_t)TOK*CH];
__device__ __half g_hmid [(size_t)TOK*HIDDEN];
// fp16, TRANSPOSED weight copies: [N][K]
__device__ __half g_wqkv [QKVN*CH];
__device__ __half g_wproj[CH*CH];
__device__ __half g_w1   [HIDDEN*CH];
__device__ __half g_w2   [CH*HIDDEN];

__device__ __forceinline__ void cpasync16(uint32_t dst, const void* src) {
    asm volatile("cp.async.cg.shared.global [%0], [%1], 16;" :: "r"(dst), "l"(src));
}

__device__ __forceinline__ void ldsm4(uint32_t& r0, uint32_t& r1, uint32_t& r2, uint32_t& r3,
                                      uint32_t addr) {
    asm volatile("ldmatrix.sync.aligned.m8n8.x4.shared.b16 {%0,%1,%2,%3}, [%4];"
                 : "=r"(r0), "=r"(r1), "=r"(r2), "=r"(r3) : "r"(addr));
}

__device__ __forceinline__ void ldsm4t(uint32_t& r0, uint32_t& r1, uint32_t& r2, uint32_t& r3,
                                       uint32_t addr) {
    asm volatile("ldmatrix.sync.aligned.m8n8.x4.trans.shared.b16 {%0,%1,%2,%3}, [%4];"
                 : "=r"(r0), "=r"(r1), "=r"(r2), "=r"(r3) : "r"(addr));
}

#define MMA16816(d0,d1,d2,d3,a0,a1,a2,a3,b0,b1) \
    asm volatile( \
        "mma.sync.aligned.m16n8k16.row.col.f32.f16.f16.f32 " \
        "{%0,%1,%2,%3}, {%4,%5,%6,%7}, {%8,%9}, {%0,%1,%2,%3};" \
        : "+f"(d0), "+f"(d1), "+f"(d2), "+f"(d3) \
        : "r"(a0), "r"(a1), "r"(a2), "r"(a3), "r"(b0), "r"(b1))

// ---------------- prep: ALL weights transpose + fp16 round, one launch ----------------
__global__ __launch_bounds__(256) void transpose_round_all(
    const float* __restrict__ w0, __half* __restrict__ o0,
    const float* __restrict__ w1_, __half* __restrict__ o1,
    const float* __restrict__ w2_, __half* __restrict__ o2,
    const float* __restrict__ w3_, __half* __restrict__ o3)
{
    __shared__ float t[32][33];
    int blk = blockIdx.x;
    const float* w; __half* wt; int K, N, nb;
    if (blk < 192)      { w = w0;  wt = o0; K = CH;     N = QKVN;   nb = QKVN/32; }
    else if (blk < 256) { blk -= 192; w = w1_; wt = o1; K = CH;     N = CH;     nb = CH/32; }
    else if (blk < 512) { blk -= 256; w = w2_; wt = o2; K = CH;     N = HIDDEN; nb = HIDDEN/32; }
    else                { blk -= 512; w = w3_; wt = o3; K = HIDDEN; N = CH;     nb = CH/32; }
    const int k0 = (blk / nb) * 32, n0 = (blk % nb) * 32;
    const int x = threadIdx.x & 31, y = threadIdx.x >> 5;
    for (int yy = y; yy < 32; yy += 8)
        t[yy][x] = w[(size_t)(k0 + yy)*N + n0 + x];
    __syncthreads();
    for (int yy = y; yy < 32; yy += 8)
        wt[(size_t)(n0 + yy)*K + k0 + x] = __float2half_rn(t[x][yy]);
}

// ---------------- kernel 1: LN1 + shift + window partition ----------------
__global__ __launch_bounds__(256) void ln1_kernel(
    const float* __restrict__ x, const float* __restrict__ g, const float* __restrict__ bta,
    __half* __restrict__ ywin)
{
    __shared__ float ts[256*33];
    __shared__ float cmu[32], crs[32];
    const int blk = blockIdx.x;
    const int b   = blk / 98;
    const int hw0 = (blk % 98) * 32;
    const int tid = threadIdx.x;
    const float* xb = x + (size_t)b*CH*HWS;

    for (int idx = tid; idx < 256*32; idx += 256) {
        int ch = idx >> 5, j = idx & 31;
        ts[ch*33 + j] = xb[(size_t)ch*HWS + hw0 + j];
    }
    __syncthreads();

    {
        int col = tid >> 3, kk = tid & 7;
        float s = 0.f, s2 = 0.f;
        for (int ch = kk; ch < 256; ch += 8) {
            float v = ts[ch*33 + col];
            s += v; s2 += v*v;
        }
        #pragma unroll
        for (int o = 4; o; o >>= 1) {
            s  += __shfl_down_sync(0xffffffffu, s,  o, 8);
            s2 += __shfl_down_sync(0xffffffffu, s2, o, 8);
        }
        if (kk == 0) {
            float mu = s * (1.f/256.f);
            cmu[col] = mu;
            crs[col] = rsqrtf(s2*(1.f/256.f) - mu*mu + 1e-5f);
        }
    }
    __syncthreads();

    const float gg = g[tid], bb = bta[tid];
    for (int j = 0; j < 32; j++) {
        int hw = hw0 + j;
        int h = hw / 56, w = hw % 56;
        int hs = h + (56 - SHIFT3); if (hs >= 56) hs -= 56;
        int wsh = w + (56 - SHIFT3); if (wsh >= 56) wsh -= 56;
        int wi = hs / 7, r = hs % 7;
        int wj = wsh / 7, c = wsh % 7;
        int win = ((b << 3) + wi) * 8 + wj;
        int n = r*7 + c;
        ywin[((size_t)win*49 + n)*CH + tid] =
            __float2half_rn((ts[tid*33 + j] - cmu[j]) * crs[j] * gg + bb);
    }
}

// ---------------- fp16 mma GEMM: CTA 128x256, warp 64x64, BK=64, 3-stage ----------------
#define BK 64
#define STAGES 3
#define A_STAGE_B (128*128)
#define B_STAGE_B (256*128)
#define STAGE_B   (A_STAGE_B + B_STAGE_B)
#define SMEM_DYN  (STAGES*STAGE_B)

enum { EPI_BIAS = 0, EPI_PROJLN = 1, EPI_GELU = 2, EPI_RES = 3 };

template<int EPI>
__global__ __launch_bounds__(256) void mma_gemm(
    const __half* __restrict__ A, const __half* __restrict__ BT,
    const float* __restrict__ bias, void* __restrict__ Cp,
    const void* __restrict__ auxp,
    const float* __restrict__ gamma, const float* __restrict__ beta2,
    __half* __restrict__ h2out,
    int M, int N, int K)
{
    extern __shared__ char sm[];
    const uint32_t smb = (uint32_t)__cvta_generic_to_shared(sm);

    const int tid  = threadIdx.x;
    const int lane = tid & 31, warp = tid >> 5;
    const int g    = lane >> 2, c4 = lane & 3;
    const int wm0  = (warp >> 2) * 64;
    const int wn0  = (warp & 3) * 64;
    const int m0   = blockIdx.y * 128, n0 = blockIdx.x * 256;

    const int fr  = ((lane >> 3) & 1) * 8 + (lane & 7);
    const int fk  = lane >> 4;

    int arow[4], asw[4], brow[4], bsw[4];
    #pragma unroll
    for (int i = 0; i < 4; i++) {
        int ra = wm0 + i*16 + fr;
        arow[i] = ra*128; asw[i] = ra & 7;
        int rb = wn0 + i*16 + fr;
        brow[i] = rb*128; bsw[i] = rb & 7;
    }

    const int cr = tid >> 3, cc = tid & 7;

    float acc[4][8][4];
    #pragma unroll
    for (int i = 0; i < 4; i++)
        #pragma unroll
        for (int j = 0; j < 8; j++)
            #pragma unroll
            for (int k = 0; k < 4; k++) acc[i][j][k] = 0.f;

    auto fill = [&](int t) {
        const int s = t % STAGES;
        const uint32_t ab = smb + (uint32_t)(s*STAGE_B);
        const uint32_t bb = ab + A_STAGE_B;
        const int k0 = t * BK;
        #pragma unroll
        for (int i = 0; i < 4; i++) {
            int rr = cr + 32*i;
            cpasync16(ab + (uint32_t)(rr*128) + (uint32_t)((cc ^ (rr & 7)) << 4),
                      &A[(size_t)(m0 + rr)*K + k0 + cc*8]);
        }
        #pragma unroll
        for (int i = 0; i < 8; i++) {
            int rr = cr + 32*i;
            cpasync16(bb + (uint32_t)(rr*128) + (uint32_t)((cc ^ (rr & 7)) << 4),
                      &BT[(size_t)(n0 + rr)*K + k0 + cc*8]);
        }
    };

    const int nt = K / BK;
    #pragma unroll
    for (int s = 0; s < STAGES-1; s++) {
        fill(s);
        asm volatile("cp.async.commit_group;");
    }

    for (int t = 0; t < nt; t++) {
        asm volatile("cp.async.wait_group %0;" :: "n"(STAGES-2));
        __syncthreads();
        if (t + STAGES - 1 < nt) fill(t + STAGES - 1);
        asm volatile("cp.async.commit_group;");

        const uint32_t ab = smb + (uint32_t)((t % STAGES)*STAGE_B);
        const uint32_t bb = ab + A_STAGE_B;

        #pragma unroll
        for (int kk = 0; kk < 4; kk++) {
            const int kc = kk*2 + fk;
            uint32_t af[4][4], bf[4][4];
            #pragma unroll
            for (int mi = 0; mi < 4; mi++)
                ldsm4(af[mi][0], af[mi][1], af[mi][2], af[mi][3],
                      ab + (uint32_t)arow[mi] + (uint32_t)((kc ^ asw[mi]) << 4));
            #pragma unroll
            for (int np = 0; np < 4; np++)
                ldsm4(bf[np][0], bf[np][1], bf[np][2], bf[np][3],
                      bb + (uint32_t)brow[np] + (uint32_t)((kc ^ bsw[np]) << 4));

            #pragma unroll
            for (int mi = 0; mi < 4; mi++)
                #pragma unroll
                for (int ni = 0; ni < 8; ni++) {
                    const int p = ni >> 1, sb = ni & 1;
                    MMA16816(acc[mi][ni][0], acc[mi][ni][1], acc[mi][ni][2], acc[mi][ni][3],
                             af[mi][0], af[mi][1], af[mi][2], af[mi][3],
                             bf[p][sb], bf[p][2 + sb]);
                }
        }
    }

    // -------- epilogue --------
    if (EPI == EPI_PROJLN) {
        asm volatile("cp.async.wait_group 0;" ::: "memory");
        __syncthreads();
        const float* aux = (const float*)auxp;   // shortcut x, NCHW fp32
        float* red  = (float*)sm;
        float* red2 = red + 512;
        float* smu  = red2 + 512;
        float* srs  = smu + 128;

        __half* C = (__half*)Cp;                 // x1, fp16
        float psum[4][2], psum2[4][2];
        #pragma unroll
        for (int mi = 0; mi < 4; mi++) { psum[mi][0]=psum[mi][1]=psum2[mi][0]=psum2[mi][1]=0.f; }

        #pragma unroll
        for (int mi = 0; mi < 4; mi++) {
            #pragma unroll
            for (int h = 0; h < 2; h++) {
                const int m = m0 + wm0 + mi*16 + g + 8*h;
                int win = m / 49, n = m % 49;
                int bq = win >> 6;
                int wr = (win >> 3) & 7;
                int wc = win & 7;
                int rr = n / 7, ccv = n % 7;
                int hh = wr*7 + rr + SHIFT3; if (hh >= 56) hh -= 56;
                int wwv = wc*7 + ccv + SHIFT3; if (wwv >= 56) wwv -= 56;
                int sp = hh*56 + wwv;
                size_t drow = (size_t)bq*HWS + sp;
                #pragma unroll
                for (int ni = 0; ni < 8; ni++) {
                    const int col = wn0 + ni*8 + 2*c4;
                    float v0 = acc[mi][ni][2*h+0] + bias[col] + aux[((size_t)(bq*CH + col    ))*HWS + sp];
                    float v1 = acc[mi][ni][2*h+1] + bias[col+1] + aux[((size_t)(bq*CH + col + 1))*HWS + sp];
                    acc[mi][ni][2*h+0] = v0; acc[mi][ni][2*h+1] = v1;
                    *reinterpret_cast<__half2*>(&C[drow*CH + col]) = __floats2half2_rn(v0, v1);
                    psum [mi][h] += v0 + v1;
                    psum2[mi][h] += v0*v0 + v1*v1;
                }
            }
        }
        #pragma unroll
        for (int mi = 0; mi < 4; mi++)
            #pragma unroll
            for (int h = 0; h < 2; h++) {
                float s = psum[mi][h], s2 = psum2[mi][h];
                s  += __shfl_xor_sync(0xffffffffu, s, 1);  s  += __shfl_xor_sync(0xffffffffu, s, 2);
                s2 += __shfl_xor_sync(0xffffffffu, s2, 1); s2 += __shfl_xor_sync(0xffffffffu, s2, 2);
                if (c4 == 0) {
                    int rloc = wm0 + mi*16 + g + 8*h;
                    red [rloc*4 + (warp & 3)] = s;
                    red2[rloc*4 + (warp & 3)] = s2;
                }
            }
        __syncthreads();
        if (tid < 128) {
            float s  = red [tid*4] + red [tid*4+1] + red [tid*4+2] + red [tid*4+3];
            float s2 = red2[tid*4] + red2[tid*4+1] + red2[tid*4+2] + red2[tid*4+3];
            float mu = s * (1.f/256.f);
            smu[tid] = mu;
            srs[tid] = rsqrtf(s2*(1.f/256.f) - mu*mu + 1e-5f);
        }
        __syncthreads();
        #pragma unroll
        for (int mi = 0; mi < 4; mi++) {
            #pragma unroll
            for (int h = 0; h < 2; h++) {
                const int rloc = wm0 + mi*16 + g + 8*h;
                const int m = m0 + rloc;
                float mu = smu[rloc], rs = srs[rloc];
                int win = m / 49, n = m % 49;
                int bq = win >> 6;
                int wr = (win >> 3) & 7;
                int wc = win & 7;
                int rr = n / 7, ccv = n % 7;
                int hh = wr*7 + rr + SHIFT3; if (hh >= 56) hh -= 56;
                int wwv = wc*7 + ccv + SHIFT3; if (wwv >= 56) wwv -= 56;
                size_t drow = (size_t)bq*HWS + hh*56 + wwv;
                #pragma unroll
                for (int ni = 0; ni < 8; ni++) {
                    const int col = wn0 + ni*8 + 2*c4;
                    float h0 = (acc[mi][ni][2*h+0] - mu)*rs*gamma[col  ] + beta2[col  ];
                    float h1 = (acc[mi][ni][2*h+1] - mu)*rs*gamma[col+1] + beta2[col+1];
                    *reinterpret_cast<__half2*>(&h2out[drow*CH + col]) = __floats2half2_rn(h0, h1);
                }
            }
        }
        return;
    }

    #pragma unroll
    for (int mi = 0; mi < 4; mi++) {
        #pragma unroll
        for (int h = 0; h < 2; h++) {
            const int m = m0 + wm0 + mi*16 + g + 8*h;
            int bq = 0, sp = 0;
            if (EPI == EPI_RES) { bq = m / HWS; sp = m % HWS; }
            #pragma unroll
            for (int ni = 0; ni < 8; ni++) {
                const int col = n0 + wn0 + ni*8 + 2*c4;
                float v0 = acc[mi][ni][2*h + 0] + bias[col];
                float v1 = acc[mi][ni][2*h + 1] + bias[col + 1];
                if (EPI == EPI_BIAS) {
                    __half2* C = (__half2*)Cp;
                    C[((size_t)m*N + col) >> 1] = __floats2half2_rn(v0, v1);
                } else if (EPI == EPI_GELU) {
                    __half2* C = (__half2*)Cp;
                    float g0 = 0.5f*v0*(1.f + erff(v0*0.70710678118654752f));
                    float g1 = 0.5f*v1*(1.f + erff(v1*0.70710678118654752f));
                    C[((size_t)m*N + col) >> 1] = __floats2half2_rn(g0, g1);
                } else { // EPI_RES: fp16 residual read, fp32 NCHW output
                    float* C = (float*)Cp;
                    const __half* aux = (const __half*)auxp;
                    __half2 a = *reinterpret_cast<const __half2*>(&aux[(size_t)m*N + col]);
                    C[((size_t)(bq*CH + col    ))*HWS + sp] = v0 + __low2float(a);
                    C[((size_t)(bq*CH + col + 1))*HWS + sp] = v1 + __high2float(a);
                }
            }
        }
    }
}

// ---------------- kernel 3: TC attention, CTA = (window, 4 heads), 256 thr ----------------
#define T_STRIDE 40
#define REG_HALFS (64*T_STRIDE)
#define ATT_SMEM  (12*REG_HALFS*2)      // 61440 B -> 3 CTAs/SM

__global__ __launch_bounds__(256) void attn_kernel(
    const __half* __restrict__ qkv, __half* __restrict__ o)
{
    extern __shared__ __half ash[];
    const int win  = blockIdx.x >> 1;
    const int hgrp = blockIdx.x & 1;
    const int tid  = threadIdx.x;
    const int warp = tid >> 5, lane = tid & 31;
    const int hloc = warp >> 1, half = warp & 1;
    const int head = hgrp*4 + hloc;
    const int g    = lane >> 2, c4 = lane & 3;
    const int fr   = ((lane >> 3) & 1) * 8 + (lane & 7);
    const int fk   = lane >> 4;

    __half* Qb = ash;
    __half* Kb = ash + 4*REG_HALFS;
    __half* Vb = ash + 8*REG_HALFS;

    // zero V token-pad rows 49..63 (div-free: i = h*128 + r*8... use power-of-2 split)
    // 4 heads x 15 rows x 5 chunks = 300 chunks; decompose i -> (h, row, q) via i = h*80 + row*5 + q
    for (int i = tid; i < 320; i += 256) {
        int h = i >> 6;            // 0..4 (h=4 masked below)
        int rem = i & 63;          // 0..63
        int row = 49 + (rem >> 2); // 49..64
        int q4 = rem & 3;          // chunks 0..3 (chunk 4 handled separately)
        if (h < 4 && row < 64)
            *(uint4*)(Vb + h*REG_HALFS + row*T_STRIDE + q4*8) = make_uint4(0,0,0,0);
    }
    // chunk 4 (last 8 halfs of each padded row): 4 heads x 15 rows = 60
    for (int i = tid; i < 60; i += 256) {
        int h = i >> 4, rem = i & 15;
        int row = 49 + rem;
        if (row < 64)
            *(uint4*)(Vb + h*REG_HALFS + row*T_STRIDE + 32) = make_uint4(0,0,0,0);
    }
    __syncthreads();

    // div-free loads: 3 sections x (49 tokens x 16 chunks)
    const __half* src = qkv + (size_t)win*49*QKVN + hgrp*128;
    #pragma unroll
    for (int sec = 0; sec < 3; sec++) {
        __half* base = (sec == 0) ? Qb : (sec == 1) ? Kb : Vb;
        const __half* s2 = src + sec*256;
        for (int idx = tid; idx < 49*16; idx += 256) {
            int n = idx >> 4, cc = idx & 15;
            int hl = cc >> 2, dq = (cc & 3)*8;
            uint4 v = *(const uint4*)(s2 + (size_t)n*QKVN + hl*32 + dq);
            *(uint4*)(base + hl*REG_HALFS + n*T_STRIDE + dq) = v;
        }
    }
    __syncthreads();

    const uint32_t Qsm = (uint32_t)__cvta_generic_to_shared(Qb + hloc*REG_HALFS)
                       + (half*32 + fr)*T_STRIDE*2;
    const uint32_t Ksm = (uint32_t)__cvta_generic_to_shared(Kb + hloc*REG_HALFS)
                       + fr*T_STRIDE*2;
    const uint32_t Vsm = (uint32_t)__cvta_generic_to_shared(Vb + hloc*REG_HALFS)
                       + fr*T_STRIDE*2;

    float acc[2][7][4];
    #pragma unroll
    for (int i = 0; i < 2; i++)
        #pragma unroll
        for (int j = 0; j < 7; j++)
            #pragma unroll
            for (int k = 0; k < 4; k++) acc[i][j][k] = 0.f;

    #pragma unroll
    for (int kk = 0; kk < 2; kk++) {
        const int kc = kk*2 + fk;
        uint32_t af[2][4], bf[4][4];
        #pragma unroll
        for (int mi = 0; mi < 2; mi++)
            ldsm4(af[mi][0], af[mi][1], af[mi][2], af[mi][3],
                  Qsm + mi*16*T_STRIDE*2 + kc*16);
        #pragma unroll
        for (int p = 0; p < 4; p++)
            ldsm4(bf[p][0], bf[p][1], bf[p][2], bf[p][3],
                  Ksm + p*16*T_STRIDE*2 + kc*16);
        #pragma unroll
        for (int mi = 0; mi < 2; mi++)
            #pragma unroll
            for (int ni = 0; ni < 7; ni++) {
                const int p = ni >> 1, sb = ni & 1;
                MMA16816(acc[mi][ni][0], acc[mi][ni][1], acc[mi][ni][2], acc[mi][ni][3],
                         af[mi][0], af[mi][1], af[mi][2], af[mi][3],
                         bf[p][sb], bf[p][2 + sb]);
            }
    }

    const float scale = 0.17677669529663687f;
    float mx[2][2], sum[2][2];
    #pragma unroll
    for (int mi = 0; mi < 2; mi++) { mx[mi][0] = mx[mi][1] = -1e30f; sum[mi][0] = sum[mi][1] = 0.f; }

    #pragma unroll
    for (int mi = 0; mi < 2; mi++)
        #pragma unroll
        for (int ni = 0; ni < 7; ni++)
            #pragma unroll
            for (int b = 0; b < 2; b++) {
                int j = ni*8 + 2*c4 + b;
                float v0 = acc[mi][ni][b]   * scale;
                float v1 = acc[mi][ni][2+b] * scale;
                if (j >= 49) { v0 = -1e30f; v1 = -1e30f; }
                acc[mi][ni][b] = v0; acc[mi][ni][2+b] = v1;
                mx[mi][0] = fmaxf(mx[mi][0], v0);
                mx[mi][1] = fmaxf(mx[mi][1], v1);
            }
    #pragma unroll
    for (int mi = 0; mi < 2; mi++)
        #pragma unroll
        for (int r = 0; r < 2; r++) {
            float m_ = mx[mi][r];
            m_ = fmaxf(m_, __shfl_xor_sync(0xffffffffu, m_, 1));
            m_ = fmaxf(m_, __shfl_xor_sync(0xffffffffu, m_, 2));
            mx[mi][r] = m_;
        }
    #pragma unroll
    for (int mi = 0; mi < 2; mi++)
        #pragma unroll
        for (int ni = 0; ni < 7; ni++)
            #pragma unroll
            for (int b = 0; b < 2; b++) {
                float e0 = __expf(acc[mi][ni][b]   - mx[mi][0]);
                float e1 = __expf(acc[mi][ni][2+b] - mx[mi][1]);
                acc[mi][ni][b] = e0; acc[mi][ni][2+b] = e1;
                sum[mi][0] += e0; sum[mi][1] += e1;
            }
    #pragma unroll
    for (int mi = 0; mi < 2; mi++)
        #pragma unroll
        for (int r = 0; r < 2; r++) {
            float s_ = sum[mi][r];
            s_ += __shfl_xor_sync(0xffffffffu, s_, 1);
            s_ += __shfl_xor_sync(0xffffffffu, s_, 2);
            sum[mi][r] = 1.f / s_;
        }

    uint32_t ph[2][7][2];
    #pragma unroll
    for (int mi = 0; mi < 2; mi++)
        #pragma unroll
        for (int ni = 0; ni < 7; ni++) {
            __half2 p0 = __floats2half2_rn(acc[mi][ni][0]*sum[mi][0], acc[mi][ni][1]*sum[mi][0]);
            __half2 p1 = __floats2half2_rn(acc[mi][ni][2]*sum[mi][1], acc[mi][ni][3]*sum[mi][1]);
            ph[mi][ni][0] = *reinterpret_cast<uint32_t*>(&p0);
            ph[mi][ni][1] = *reinterpret_cast<uint32_t*>(&p1);
        }

    float oacc[2][4][4];
    #pragma unroll
    for (int i = 0; i < 2; i++)
        #pragma unroll
        for (int j = 0; j < 4; j++)
            #pragma unroll
            for (int k = 0; k < 4; k++) oacc[i][j][k] = 0.f;

    #pragma unroll
    for (int kf = 0; kf < 4; kf++) {
        uint32_t bf[2][4];
        #pragma unroll
        for (int cp = 0; cp < 2; cp++)
            ldsm4t(bf[cp][0], bf[cp][1], bf[cp][2], bf[cp][3],
                   Vsm + kf*16*T_STRIDE*2 + (2*cp + fk)*16);
        #pragma unroll
        for (int mi = 0; mi < 2; mi++) {
            const int n0f = 2*kf, n1f = 2*kf + 1;
            uint32_t a0 = ph[mi][n0f][0], a1 = ph[mi][n0f][1];
            uint32_t a2 = (n1f < 7) ? ph[mi][n1f][0] : 0u;
            uint32_t a3 = (n1f < 7) ? ph[mi][n1f][1] : 0u;
            #pragma unroll
            for (int ni2 = 0; ni2 < 4; ni2++) {
                const int cp = ni2 >> 1, q = ni2 & 1;
                MMA16816(oacc[mi][ni2][0], oacc[mi][ni2][1], oacc[mi][ni2][2], oacc[mi][ni2][3],
                         a0, a1, a2, a3, bf[cp][2*q], bf[cp][2*q + 1]);
            }
        }
    }

    #pragma unroll
    for (int mi = 0; mi < 2; mi++) {
        const int i0 = half*32 + mi*16 + g, i1 = i0 + 8;
        #pragma unroll
        for (int ni2 = 0; ni2 < 4; ni2++) {
            const int col = head*HDIM + ni2*8 + 2*c4;
            if (i0 < 49) {
                __half2 v = __floats2half2_rn(oacc[mi][ni2][0], oacc[mi][ni2][1]);
                *reinterpret_cast<__half2*>(&o[((size_t)win*49 + i0)*CH + col]) = v;
            }
            if (i1 < 49) {
                __half2 v = __floats2half2_rn(oacc[mi][ni2][2], oacc[mi][ni2][3]);
                *reinterpret_cast<__half2*>(&o[((size_t)win*49 + i1)*CH + col]) = v;
            }
        }
    }
}

// ---------------- launch ----------------
extern "C" void kernel_launch(void* const* d_in, const int* in_sizes, int n_in,
                              void* d_out, int out_size)
{
    const float* x      = (const float*)d_in[0];
    const float* n1_g   = (const float*)d_in[1];
    const float* n1_b   = (const float*)d_in[2];
    const float* qkv_w  = (const float*)d_in[3];
    const float* qkv_b  = (const float*)d_in[4];
    const float* proj_w = (const float*)d_in[5];
    const float* proj_b = (const float*)d_in[6];
    const float* n2_g   = (const float*)d_in[7];
    const float* n2_b   = (const float*)d_in[8];
    const float* mlp_w1 = (const float*)d_in[9];
    const float* mlp_b1 = (const float*)d_in[10];
    const float* mlp_w2 = (const float*)d_in[11];
    const float* mlp_b2 = (const float*)d_in[12];

    __half *ywin, *qkvb, *ow, *x1, *h2, *hmid;
    __half *wqkv, *wproj, *w1, *w2;
    cudaGetSymbolAddress((void**)&ywin,  g_ywin);
    cudaGetSymbolAddress((void**)&qkvb,  g_qkv);
    cudaGetSymbolAddress((void**)&ow,    g_ow);
    cudaGetSymbolAddress((void**)&x1,    g_x1);
    cudaGetSymbolAddress((void**)&h2,    g_h2);
    cudaGetSymbolAddress((void**)&hmid,  g_hmid);
    cudaGetSymbolAddress((void**)&wqkv,  g_wqkv);
    cudaGetSymbolAddress((void**)&wproj, g_wproj);
    cudaGetSymbolAddress((void**)&w1,    g_w1);
    cudaGetSymbolAddress((void**)&w2,    g_w2);

    static bool attr_done = false;
    if (!attr_done) {
        cudaFuncSetAttribute(mma_gemm<EPI_BIAS>,   cudaFuncAttributeMaxDynamicSharedMemorySize, SMEM_DYN);
        cudaFuncSetAttribute(mma_gemm<EPI_PROJLN>, cudaFuncAttributeMaxDynamicSharedMemorySize, SMEM_DYN);
        cudaFuncSetAttribute(mma_gemm<EPI_GELU>,   cudaFuncAttributeMaxDynamicSharedMemorySize, SMEM_DYN);
        cudaFuncSetAttribute(mma_gemm<EPI_RES>,    cudaFuncAttributeMaxDynamicSharedMemorySize, SMEM_DYN);
        cudaFuncSetAttribute(attn_kernel,          cudaFuncAttributeMaxDynamicSharedMemorySize, ATT_SMEM);
        attr_done = true;
    }

    // 0) all weights: transpose + fp16 round -> [N][K]
    transpose_round_all<<<768, 256>>>(qkv_w, wqkv, proj_w, wproj, mlp_w1, w1, mlp_w2, w2);

    // 1) LN1 + shift + window partition
    ln1_kernel<<<BATCH*98, 256>>>(x, n1_g, n1_b, ywin);

    // 2) qkv = ywin @ qkv_w + qkv_b
    mma_gemm<EPI_BIAS><<<dim3(QKVN/256, TOK/128), 256, SMEM_DYN>>>(
        ywin, wqkv, qkv_b, qkvb, nullptr, nullptr, nullptr, nullptr, TOK, QKVN, CH);

    // 3) tensor-core windowed attention (2 CTAs per window, 4 heads each)
    attn_kernel<<<4096, 256, ATT_SMEM>>>(qkvb, ow);

    // 4) x1(fp16) = shortcut(x) + proj(ow); h2 = LN2(x1)   (fused)
    mma_gemm<EPI_PROJLN><<<dim3(CH/256, TOK/128), 256, SMEM_DYN>>>(
        ow, wproj, proj_b, x1, x, n2_g, n2_b, h2, TOK, CH, CH);

    // 5) hmid = gelu(h2 @ mlp_w1 + mlp_b1)
    mma_gemm<EPI_GELU><<<dim3(HIDDEN/256, TOK/128), 256, SMEM_DYN>>>(
        h2, w1, mlp_b1, hmid, nullptr, nullptr, nullptr, nullptr, TOK, HIDDEN, CH);

    // 6) out(NCHW) = x1 + hmid @ mlp_w2 + mlp_b2   (fused transpose, fp16 residual)
    mma_gemm<EPI_RES><<<dim3(CH/256, TOK/128), 256, SMEM_DYN>>>(
        hmid, w2, mlp_b2, (float*)d_out, x1, nullptr, nullptr, nullptr, TOK, CH, HIDDEN);
}

// round 13
// speedup vs baseline: 1.7817x; 1.0477x over previous
#include <cuda_runtime.h>
#include <cuda_fp16.h>
#include <math.h>
#include <stdint.h>

// ---------------- problem constants ----------------
#define BATCH 32
#define CH    256
#define HWS   3136
#define TOK   100352
#define SHIFT3 3
#define HEADS 8
#define HDIM  32
#define HIDDEN 1024
#define QKVN  768

// ---------------- scratch ----------------
__device__ __half g_ywin [(size_t)TOK*CH];
__device__ __half g_qkv  [(size_t)TOK*QKVN];
__device__ __half g_ow   [(size_t)TOK*CH];
__device__ __half g_x1   [(size_t)TOK*CH];     // fp16 residual
__device__ __half g_h2   [(size_t)TOK*CH];
__device__ __half g_hmid [(size_t)TOK*HIDDEN];
// fp16, TRANSPOSED weight copies: [N][K]
__device__ __half g_wqkv [QKVN*CH];
__device__ __half g_wproj[CH*CH];
__device__ __half g_w1   [HIDDEN*CH];
__device__ __half g_w2   [CH*HIDDEN];

__device__ __forceinline__ void cpasync16(uint32_t dst, const void* src) {
    asm volatile("cp.async.cg.shared.global [%0], [%1], 16;" :: "r"(dst), "l"(src));
}

__device__ __forceinline__ void ldsm4(uint32_t& r0, uint32_t& r1, uint32_t& r2, uint32_t& r3,
                                      uint32_t addr) {
    asm volatile("ldmatrix.sync.aligned.m8n8.x4.shared.b16 {%0,%1,%2,%3}, [%4];"
                 : "=r"(r0), "=r"(r1), "=r"(r2), "=r"(r3) : "r"(addr));
}

__device__ __forceinline__ void ldsm4t(uint32_t& r0, uint32_t& r1, uint32_t& r2, uint32_t& r3,
                                       uint32_t addr) {
    asm volatile("ldmatrix.sync.aligned.m8n8.x4.trans.shared.b16 {%0,%1,%2,%3}, [%4];"
                 : "=r"(r0), "=r"(r1), "=r"(r2), "=r"(r3) : "r"(addr));
}

#define MMA16816(d0,d1,d2,d3,a0,a1,a2,a3,b0,b1) \
    asm volatile( \
        "mma.sync.aligned.m16n8k16.row.col.f32.f16.f16.f32 " \
        "{%0,%1,%2,%3}, {%4,%5,%6,%7}, {%8,%9}, {%0,%1,%2,%3};" \
        : "+f"(d0), "+f"(d1), "+f"(d2), "+f"(d3) \
        : "r"(a0), "r"(a1), "r"(a2), "r"(a3), "r"(b0), "r"(b1))

// ---------------- prep: ALL weights transpose + fp16 round, one launch ----------------
__global__ __launch_bounds__(256) void transpose_round_all(
    const float* __restrict__ w0, __half* __restrict__ o0,
    const float* __restrict__ w1_, __half* __restrict__ o1,
    const float* __restrict__ w2_, __half* __restrict__ o2,
    const float* __restrict__ w3_, __half* __restrict__ o3)
{
    __shared__ float t[32][33];
    int blk = blockIdx.x;
    const float* w; __half* wt; int K, N, nb;
    if (blk < 192)      { w = w0;  wt = o0; K = CH;     N = QKVN;   nb = QKVN/32; }
    else if (blk < 256) { blk -= 192; w = w1_; wt = o1; K = CH;     N = CH;     nb = CH/32; }
    else if (blk < 512) { blk -= 256; w = w2_; wt = o2; K = CH;     N = HIDDEN; nb = HIDDEN/32; }
    else                { blk -= 512; w = w3_; wt = o3; K = HIDDEN; N = CH;     nb = CH/32; }
    const int k0 = (blk / nb) * 32, n0 = (blk % nb) * 32;
    const int x = threadIdx.x & 31, y = threadIdx.x >> 5;
    for (int yy = y; yy < 32; yy += 8)
        t[yy][x] = w[(size_t)(k0 + yy)*N + n0 + x];
    __syncthreads();
    for (int yy = y; yy < 32; yy += 8)
        wt[(size_t)(n0 + yy)*K + k0 + x] = __float2half_rn(t[x][yy]);
}

// ---------------- kernel 1: LN1 + shift + window partition ----------------
__global__ __launch_bounds__(256) void ln1_kernel(
    const float* __restrict__ x, const float* __restrict__ g, const float* __restrict__ bta,
    __half* __restrict__ ywin)
{
    __shared__ float ts[256*33];
    __shared__ float cmu[32], crs[32];
    const int blk = blockIdx.x;
    const int b   = blk / 98;
    const int hw0 = (blk % 98) * 32;
    const int tid = threadIdx.x;
    const float* xb = x + (size_t)b*CH*HWS;

    for (int idx = tid; idx < 256*32; idx += 256) {
        int ch = idx >> 5, j = idx & 31;
        ts[ch*33 + j] = xb[(size_t)ch*HWS + hw0 + j];
    }
    __syncthreads();

    {
        int col = tid >> 3, kk = tid & 7;
        float s = 0.f, s2 = 0.f;
        for (int ch = kk; ch < 256; ch += 8) {
            float v = ts[ch*33 + col];
            s += v; s2 += v*v;
        }
        #pragma unroll
        for (int o = 4; o; o >>= 1) {
            s  += __shfl_down_sync(0xffffffffu, s,  o, 8);
            s2 += __shfl_down_sync(0xffffffffu, s2, o, 8);
        }
        if (kk == 0) {
            float mu = s * (1.f/256.f);
            cmu[col] = mu;
            crs[col] = rsqrtf(s2*(1.f/256.f) - mu*mu + 1e-5f);
        }
    }
    __syncthreads();

    const float gg = g[tid], bb = bta[tid];
    for (int j = 0; j < 32; j++) {
        int hw = hw0 + j;
        int h = hw / 56, w = hw % 56;
        int hs = h + (56 - SHIFT3); if (hs >= 56) hs -= 56;
        int wsh = w + (56 - SHIFT3); if (wsh >= 56) wsh -= 56;
        int wi = hs / 7, r = hs % 7;
        int wj = wsh / 7, c = wsh % 7;
        int win = ((b << 3) + wi) * 8 + wj;
        int n = r*7 + c;
        ywin[((size_t)win*49 + n)*CH + tid] =
            __float2half_rn((ts[tid*33 + j] - cmu[j]) * crs[j] * gg + bb);
    }
}

// ---------------- fp16 mma GEMM: CTA 128x256, 16 warps @ 32x64, BK=64, 3-stage ----------------
#define BK 64
#define STAGES 3
#define A_STAGE_B (128*128)
#define B_STAGE_B (256*128)
#define STAGE_B   (A_STAGE_B + B_STAGE_B)
#define SMEM_DYN  (STAGES*STAGE_B)
#define GTHREADS  512

enum { EPI_BIAS = 0, EPI_PROJLN = 1, EPI_GELU = 2, EPI_RES = 3 };

template<int EPI>
__global__ __launch_bounds__(GTHREADS) void mma_gemm(
    const __half* __restrict__ A, const __half* __restrict__ BT,
    const float* __restrict__ bias, void* __restrict__ Cp,
    const void* __restrict__ auxp,
    const float* __restrict__ gamma, const float* __restrict__ beta2,
    __half* __restrict__ h2out,
    int M, int N, int K)
{
    extern __shared__ char sm[];
    const uint32_t smb = (uint32_t)__cvta_generic_to_shared(sm);

    const int tid  = threadIdx.x;
    const int lane = tid & 31, warp = tid >> 5;
    const int g    = lane >> 2, c4 = lane & 3;
    const int wm0  = (warp >> 2) * 32;    // 0..96
    const int wn0  = (warp & 3) * 64;     // 0..192
    const int m0   = blockIdx.y * 128, n0 = blockIdx.x * 256;

    const int fr  = ((lane >> 3) & 1) * 8 + (lane & 7);
    const int fk  = lane >> 4;

    int arow[2], asw[2], brow[4], bsw[4];
    #pragma unroll
    for (int i = 0; i < 2; i++) {
        int ra = wm0 + i*16 + fr;
        arow[i] = ra*128; asw[i] = ra & 7;
    }
    #pragma unroll
    for (int i = 0; i < 4; i++) {
        int rb = wn0 + i*16 + fr;
        brow[i] = rb*128; bsw[i] = rb & 7;
    }

    const int cr = tid >> 3, cc = tid & 7;   // 64 rows x 8 chunks per pass

    float acc[2][8][4];
    #pragma unroll
    for (int i = 0; i < 2; i++)
        #pragma unroll
        for (int j = 0; j < 8; j++)
            #pragma unroll
            for (int k = 0; k < 4; k++) acc[i][j][k] = 0.f;

    auto fill = [&](int t) {
        const int s = t % STAGES;
        const uint32_t ab = smb + (uint32_t)(s*STAGE_B);
        const uint32_t bb = ab + A_STAGE_B;
        const int k0 = t * BK;
        #pragma unroll
        for (int i = 0; i < 2; i++) {
            int rr = cr + 64*i;
            cpasync16(ab + (uint32_t)(rr*128) + (uint32_t)((cc ^ (rr & 7)) << 4),
                      &A[(size_t)(m0 + rr)*K + k0 + cc*8]);
        }
        #pragma unroll
        for (int i = 0; i < 4; i++) {
            int rr = cr + 64*i;
            cpasync16(bb + (uint32_t)(rr*128) + (uint32_t)((cc ^ (rr & 7)) << 4),
                      &BT[(size_t)(n0 + rr)*K + k0 + cc*8]);
        }
    };

    const int nt = K / BK;
    #pragma unroll
    for (int s = 0; s < STAGES-1; s++) {
        fill(s);
        asm volatile("cp.async.commit_group;");
    }

    for (int t = 0; t < nt; t++) {
        asm volatile("cp.async.wait_group %0;" :: "n"(STAGES-2));
        __syncthreads();
        if (t + STAGES - 1 < nt) fill(t + STAGES - 1);
        asm volatile("cp.async.commit_group;");

        const uint32_t ab = smb + (uint32_t)((t % STAGES)*STAGE_B);
        const uint32_t bb = ab + A_STAGE_B;

        #pragma unroll
        for (int kk = 0; kk < 4; kk++) {
            const int kc = kk*2 + fk;
            uint32_t af[2][4], bf[4][4];
            #pragma unroll
            for (int mi = 0; mi < 2; mi++)
                ldsm4(af[mi][0], af[mi][1], af[mi][2], af[mi][3],
                      ab + (uint32_t)arow[mi] + (uint32_t)((kc ^ asw[mi]) << 4));
            #pragma unroll
            for (int np = 0; np < 4; np++)
                ldsm4(bf[np][0], bf[np][1], bf[np][2], bf[np][3],
                      bb + (uint32_t)brow[np] + (uint32_t)((kc ^ bsw[np]) << 4));

            #pragma unroll
            for (int mi = 0; mi < 2; mi++)
                #pragma unroll
                for (int ni = 0; ni < 8; ni++) {
                    const int p = ni >> 1, sb = ni & 1;
                    MMA16816(acc[mi][ni][0], acc[mi][ni][1], acc[mi][ni][2], acc[mi][ni][3],
                             af[mi][0], af[mi][1], af[mi][2], af[mi][3],
                             bf[p][sb], bf[p][2 + sb]);
                }
        }
    }

    // -------- epilogue --------
    if (EPI == EPI_PROJLN) {
        asm volatile("cp.async.wait_group 0;" ::: "memory");
        __syncthreads();
        const float* aux = (const float*)auxp;   // shortcut x, NCHW fp32
        float* red  = (float*)sm;
        float* red2 = red + 512;
        float* smu  = red2 + 512;
        float* srs  = smu + 128;

        __half* C = (__half*)Cp;                 // x1, fp16
        float psum[2][2], psum2[2][2];
        #pragma unroll
        for (int mi = 0; mi < 2; mi++) { psum[mi][0]=psum[mi][1]=psum2[mi][0]=psum2[mi][1]=0.f; }

        #pragma unroll
        for (int mi = 0; mi < 2; mi++) {
            #pragma unroll
            for (int h = 0; h < 2; h++) {
                const int m = m0 + wm0 + mi*16 + g + 8*h;
                int win = m / 49, n = m % 49;
                int bq = win >> 6;
                int wr = (win >> 3) & 7;
                int wc = win & 7;
                int rr = n / 7, ccv = n % 7;
                int hh = wr*7 + rr + SHIFT3; if (hh >= 56) hh -= 56;
                int wwv = wc*7 + ccv + SHIFT3; if (wwv >= 56) wwv -= 56;
                int sp = hh*56 + wwv;
                size_t drow = (size_t)bq*HWS + sp;
                #pragma unroll
                for (int ni = 0; ni < 8; ni++) {
                    const int col = wn0 + ni*8 + 2*c4;
                    float v0 = acc[mi][ni][2*h+0] + bias[col] + aux[((size_t)(bq*CH + col    ))*HWS + sp];
                    float v1 = acc[mi][ni][2*h+1] + bias[col+1] + aux[((size_t)(bq*CH + col + 1))*HWS + sp];
                    acc[mi][ni][2*h+0] = v0; acc[mi][ni][2*h+1] = v1;
                    *reinterpret_cast<__half2*>(&C[drow*CH + col]) = __floats2half2_rn(v0, v1);
                    psum [mi][h] += v0 + v1;
                    psum2[mi][h] += v0*v0 + v1*v1;
                }
            }
        }
        #pragma unroll
        for (int mi = 0; mi < 2; mi++)
            #pragma unroll
            for (int h = 0; h < 2; h++) {
                float s = psum[mi][h], s2 = psum2[mi][h];
                s  += __shfl_xor_sync(0xffffffffu, s, 1);  s  += __shfl_xor_sync(0xffffffffu, s, 2);
                s2 += __shfl_xor_sync(0xffffffffu, s2, 1); s2 += __shfl_xor_sync(0xffffffffu, s2, 2);
                if (c4 == 0) {
                    int rloc = wm0 + mi*16 + g + 8*h;
                    red [rloc*4 + (warp & 3)] = s;
                    red2[rloc*4 + (warp & 3)] = s2;
                }
            }
        __syncthreads();
        if (tid < 128) {
            float s  = red [tid*4] + red [tid*4+1] + red [tid*4+2] + red [tid*4+3];
            float s2 = red2[tid*4] + red2[tid*4+1] + red2[tid*4+2] + red2[tid*4+3];
            float mu = s * (1.f/256.f);
            smu[tid] = mu;
            srs[tid] = rsqrtf(s2*(1.f/256.f) - mu*mu + 1e-5f);
        }
        __syncthreads();
        #pragma unroll
        for (int mi = 0; mi < 2; mi++) {
            #pragma unroll
            for (int h = 0; h < 2; h++) {
                const int rloc = wm0 + mi*16 + g + 8*h;
                const int m = m0 + rloc;
                float mu = smu[rloc], rs = srs[rloc];
                int win = m / 49, n = m % 49;
                int bq = win >> 6;
                int wr = (win >> 3) & 7;
                int wc = win & 7;
                int rr = n / 7, ccv = n % 7;
                int hh = wr*7 + rr + SHIFT3; if (hh >= 56) hh -= 56;
                int wwv = wc*7 + ccv + SHIFT3; if (wwv >= 56) wwv -= 56;
                size_t drow = (size_t)bq*HWS + hh*56 + wwv;
                #pragma unroll
                for (int ni = 0; ni < 8; ni++) {
                    const int col = wn0 + ni*8 + 2*c4;
                    float h0 = (acc[mi][ni][2*h+0] - mu)*rs*gamma[col  ] + beta2[col  ];
                    float h1 = (acc[mi][ni][2*h+1] - mu)*rs*gamma[col+1] + beta2[col+1];
                    *reinterpret_cast<__half2*>(&h2out[drow*CH + col]) = __floats2half2_rn(h0, h1);
                }
            }
        }
        return;
    }

    #pragma unroll
    for (int mi = 0; mi < 2; mi++) {
        #pragma unroll
        for (int h = 0; h < 2; h++) {
            const int m = m0 + wm0 + mi*16 + g + 8*h;
            int bq = 0, sp = 0;
            if (EPI == EPI_RES) { bq = m / HWS; sp = m % HWS; }
            #pragma unroll
            for (int ni = 0; ni < 8; ni++) {
                const int col = n0 + wn0 + ni*8 + 2*c4;
                float v0 = acc[mi][ni][2*h + 0] + bias[col];
                float v1 = acc[mi][ni][2*h + 1] + bias[col + 1];
                if (EPI == EPI_BIAS) {
                    __half2* C = (__half2*)Cp;
                    C[((size_t)m*N + col) >> 1] = __floats2half2_rn(v0, v1);
                } else if (EPI == EPI_GELU) {
                    __half2* C = (__half2*)Cp;
                    float g0 = 0.5f*v0*(1.f + erff(v0*0.70710678118654752f));
                    float g1 = 0.5f*v1*(1.f + erff(v1*0.70710678118654752f));
                    C[((size_t)m*N + col) >> 1] = __floats2half2_rn(g0, g1);
                } else { // EPI_RES: fp16 residual read, fp32 NCHW output
                    float* C = (float*)Cp;
                    const __half* aux = (const __half*)auxp;
                    __half2 a = *reinterpret_cast<const __half2*>(&aux[(size_t)m*N + col]);
                    C[((size_t)(bq*CH + col    ))*HWS + sp] = v0 + __low2float(a);
                    C[((size_t)(bq*CH + col + 1))*HWS + sp] = v1 + __high2float(a);
                }
            }
        }
    }
}

// ---------------- kernel 3: TC attention, CTA = (window, 4 heads), 256 thr ----------------
#define T_STRIDE 40
#define REG_HALFS (64*T_STRIDE)
#define ATT_SMEM  (12*REG_HALFS*2)      // 61440 B -> 3 CTAs/SM

__global__ __launch_bounds__(256) void attn_kernel(
    const __half* __restrict__ qkv, __half* __restrict__ o)
{
    extern __shared__ __half ash[];
    const int win  = blockIdx.x >> 1;
    const int hgrp = blockIdx.x & 1;
    const int tid  = threadIdx.x;
    const int warp = tid >> 5, lane = tid & 31;
    const int hloc = warp >> 1, half = warp & 1;
    const int head = hgrp*4 + hloc;
    const int g    = lane >> 2, c4 = lane & 3;
    const int fr   = ((lane >> 3) & 1) * 8 + (lane & 7);
    const int fk   = lane >> 4;

    __half* Qb = ash;
    __half* Kb = ash + 4*REG_HALFS;
    __half* Vb = ash + 8*REG_HALFS;

    for (int i = tid; i < 300; i += 256) {
        int h = i / 75, rem = i % 75;
        int row = 49 + rem / 5, q = rem % 5;
        *(uint4*)(Vb + h*REG_HALFS + row*T_STRIDE + q*8) = make_uint4(0,0,0,0);
    }
    __syncthreads();

    const __half* src = qkv + (size_t)win*49*QKVN;
    for (int idx = tid; idx < 49*48; idx += 256) {
        int n = idx / 48, ck = idx % 48;
        int sec = ck >> 4;
        int cc  = ck & 15;
        int hl  = cc >> 2, dq = (cc & 3)*8;
        int col = sec*256 + (hgrp*4 + hl)*32 + dq;
        uint4 v = *(const uint4*)(src + (size_t)n*QKVN + col);
        __half* base = (sec == 0) ? Qb : (sec == 1) ? Kb : Vb;
        *(uint4*)(base + hl*REG_HALFS + n*T_STRIDE + dq) = v;
    }
    __syncthreads();

    const uint32_t Qsm = (uint32_t)__cvta_generic_to_shared(Qb + hloc*REG_HALFS)
                       + (half*32 + fr)*T_STRIDE*2;
    const uint32_t Ksm = (uint32_t)__cvta_generic_to_shared(Kb + hloc*REG_HALFS)
                       + fr*T_STRIDE*2;
    const uint32_t Vsm = (uint32_t)__cvta_generic_to_shared(Vb + hloc*REG_HALFS)
                       + fr*T_STRIDE*2;

    float acc[2][7][4];
    #pragma unroll
    for (int i = 0; i < 2; i++)
        #pragma unroll
        for (int j = 0; j < 7; j++)
            #pragma unroll
            for (int k = 0; k < 4; k++) acc[i][j][k] = 0.f;

    #pragma unroll
    for (int kk = 0; kk < 2; kk++) {
        const int kc = kk*2 + fk;
        uint32_t af[2][4], bf[4][4];
        #pragma unroll
        for (int mi = 0; mi < 2; mi++)
            ldsm4(af[mi][0], af[mi][1], af[mi][2], af[mi][3],
                  Qsm + mi*16*T_STRIDE*2 + kc*16);
        #pragma unroll
        for (int p = 0; p < 4; p++)
            ldsm4(bf[p][0], bf[p][1], bf[p][2], bf[p][3],
                  Ksm + p*16*T_STRIDE*2 + kc*16);
        #pragma unroll
        for (int mi = 0; mi < 2; mi++)
            #pragma unroll
            for (int ni = 0; ni < 7; ni++) {
                const int p = ni >> 1, sb = ni & 1;
                MMA16816(acc[mi][ni][0], acc[mi][ni][1], acc[mi][ni][2], acc[mi][ni][3],
                         af[mi][0], af[mi][1], af[mi][2], af[mi][3],
                         bf[p][sb], bf[p][2 + sb]);
            }
    }

    const float scale = 0.17677669529663687f;
    float mx[2][2], sum[2][2];
    #pragma unroll
    for (int mi = 0; mi < 2; mi++) { mx[mi][0] = mx[mi][1] = -1e30f; sum[mi][0] = sum[mi][1] = 0.f; }

    #pragma unroll
    for (int mi = 0; mi < 2; mi++)
        #pragma unroll
        for (int ni = 0; ni < 7; ni++)
            #pragma unroll
            for (int b = 0; b < 2; b++) {
                int j = ni*8 + 2*c4 + b;
                float v0 = acc[mi][ni][b]   * scale;
                float v1 = acc[mi][ni][2+b] * scale;
                if (j >= 49) { v0 = -1e30f; v1 = -1e30f; }
                acc[mi][ni][b] = v0; acc[mi][ni][2+b] = v1;
                mx[mi][0] = fmaxf(mx[mi][0], v0);
                mx[mi][1] = fmaxf(mx[mi][1], v1);
            }
    #pragma unroll
    for (int mi = 0; mi < 2; mi++)
        #pragma unroll
        for (int r = 0; r < 2; r++) {
            float m_ = mx[mi][r];
            m_ = fmaxf(m_, __shfl_xor_sync(0xffffffffu, m_, 1));
            m_ = fmaxf(m_, __shfl_xor_sync(0xffffffffu, m_, 2));
            mx[mi][r] = m_;
        }
    #pragma unroll
    for (int mi = 0; mi < 2; mi++)
        #pragma unroll
        for (int ni = 0; ni < 7; ni++)
            #pragma unroll
            for (int b = 0; b < 2; b++) {
                float e0 = __expf(acc[mi][ni][b]   - mx[mi][0]);
                float e1 = __expf(acc[mi][ni][2+b] - mx[mi][1]);
                acc[mi][ni][b] = e0; acc[mi][ni][2+b] = e1;
                sum[mi][0] += e0; sum[mi][1] += e1;
            }
    #pragma unroll
    for (int mi = 0; mi < 2; mi++)
        #pragma unroll
        for (int r = 0; r < 2; r++) {
            float s_ = sum[mi][r];
            s_ += __shfl_xor_sync(0xffffffffu, s_, 1);
            s_ += __shfl_xor_sync(0xffffffffu, s_, 2);
            sum[mi][r] = 1.f / s_;
        }

    uint32_t ph[2][7][2];
    #pragma unroll
    for (int mi = 0; mi < 2; mi++)
        #pragma unroll
        for (int ni = 0; ni < 7; ni++) {
            __half2 p0 = __floats2half2_rn(acc[mi][ni][0]*sum[mi][0], acc[mi][ni][1]*sum[mi][0]);
            __half2 p1 = __floats2half2_rn(acc[mi][ni][2]*sum[mi][1], acc[mi][ni][3]*sum[mi][1]);
            ph[mi][ni][0] = *reinterpret_cast<uint32_t*>(&p0);
            ph[mi][ni][1] = *reinterpret_cast<uint32_t*>(&p1);
        }

    float oacc[2][4][4];
    #pragma unroll
    for (int i = 0; i < 2; i++)
        #pragma unroll
        for (int j = 0; j < 4; j++)
            #pragma unroll
            for (int k = 0; k < 4; k++) oacc[i][j][k] = 0.f;

    #pragma unroll
    for (int kf = 0; kf < 4; kf++) {
        uint32_t bf[2][4];
        #pragma unroll
        for (int cp = 0; cp < 2; cp++)
            ldsm4t(bf[cp][0], bf[cp][1], bf[cp][2], bf[cp][3],
                   Vsm + kf*16*T_STRIDE*2 + (2*cp + fk)*16);
        #pragma unroll
        for (int mi = 0; mi < 2; mi++) {
            const int n0f = 2*kf, n1f = 2*kf + 1;
            uint32_t a0 = ph[mi][n0f][0], a1 = ph[mi][n0f][1];
            uint32_t a2 = (n1f < 7) ? ph[mi][n1f][0] : 0u;
            uint32_t a3 = (n1f < 7) ? ph[mi][n1f][1] : 0u;
            #pragma unroll
            for (int ni2 = 0; ni2 < 4; ni2++) {
                const int cp = ni2 >> 1, q = ni2 & 1;
                MMA16816(oacc[mi][ni2][0], oacc[mi][ni2][1], oacc[mi][ni2][2], oacc[mi][ni2][3],
                         a0, a1, a2, a3, bf[cp][2*q], bf[cp][2*q + 1]);
            }
        }
    }

    #pragma unroll
    for (int mi = 0; mi < 2; mi++) {
        const int i0 = half*32 + mi*16 + g, i1 = i0 + 8;
        #pragma unroll
        for (int ni2 = 0; ni2 < 4; ni2++) {
            const int col = head*HDIM + ni2*8 + 2*c4;
            if (i0 < 49) {
                __half2 v = __floats2half2_rn(oacc[mi][ni2][0], oacc[mi][ni2][1]);
                *reinterpret_cast<__half2*>(&o[((size_t)win*49 + i0)*CH + col]) = v;
            }
            if (i1 < 49) {
                __half2 v = __floats2half2_rn(oacc[mi][ni2][2], oacc[mi][ni2][3]);
                *reinterpret_cast<__half2*>(&o[((size_t)win*49 + i1)*CH + col]) = v;
            }
        }
    }
}

// ---------------- launch ----------------
extern "C" void kernel_launch(void* const* d_in, const int* in_sizes, int n_in,
                              void* d_out, int out_size)
{
    const float* x      = (const float*)d_in[0];
    const float* n1_g   = (const float*)d_in[1];
    const float* n1_b   = (const float*)d_in[2];
    const float* qkv_w  = (const float*)d_in[3];
    const float* qkv_b  = (const float*)d_in[4];
    const float* proj_w = (const float*)d_in[5];
    const float* proj_b = (const float*)d_in[6];
    const float* n2_g   = (const float*)d_in[7];
    const float* n2_b   = (const float*)d_in[8];
    const float* mlp_w1 = (const float*)d_in[9];
    const float* mlp_b1 = (const float*)d_in[10];
    const float* mlp_w2 = (const float*)d_in[11];
    const float* mlp_b2 = (const float*)d_in[12];

    __half *ywin, *qkvb, *ow, *x1, *h2, *hmid;
    __half *wqkv, *wproj, *w1, *w2;
    cudaGetSymbolAddress((void**)&ywin,  g_ywin);
    cudaGetSymbolAddress((void**)&qkvb,  g_qkv);
    cudaGetSymbolAddress((void**)&ow,    g_ow);
    cudaGetSymbolAddress((void**)&x1,    g_x1);
    cudaGetSymbolAddress((void**)&h2,    g_h2);
    cudaGetSymbolAddress((void**)&hmid,  g_hmid);
    cudaGetSymbolAddress((void**)&wqkv,  g_wqkv);
    cudaGetSymbolAddress((void**)&wproj, g_wproj);
    cudaGetSymbolAddress((void**)&w1,    g_w1);
    cudaGetSymbolAddress((void**)&w2,    g_w2);

    static bool attr_done = false;
    if (!attr_done) {
        cudaFuncSetAttribute(mma_gemm<EPI_BIAS>,   cudaFuncAttributeMaxDynamicSharedMemorySize, SMEM_DYN);
        cudaFuncSetAttribute(mma_gemm<EPI_PROJLN>, cudaFuncAttributeMaxDynamicSharedMemorySize, SMEM_DYN);
        cudaFuncSetAttribute(mma_gemm<EPI_GELU>,   cudaFuncAttributeMaxDynamicSharedMemorySize, SMEM_DYN);
        cudaFuncSetAttribute(mma_gemm<EPI_RES>,    cudaFuncAttributeMaxDynamicSharedMemorySize, SMEM_DYN);
        cudaFuncSetAttribute(attn_kernel,          cudaFuncAttributeMaxDynamicSharedMemorySize, ATT_SMEM);
        attr_done = true;
    }

    // 0) all weights: transpose + fp16 round -> [N][K]
    transpose_round_all<<<768, 256>>>(qkv_w, wqkv, proj_w, wproj, mlp_w1, w1, mlp_w2, w2);

    // 1) LN1 + shift + window partition
    ln1_kernel<<<BATCH*98, 256>>>(x, n1_g, n1_b, ywin);

    // 2) qkv = ywin @ qkv_w + qkv_b
    mma_gemm<EPI_BIAS><<<dim3(QKVN/256, TOK/128), GTHREADS, SMEM_DYN>>>(
        ywin, wqkv, qkv_b, qkvb, nullptr, nullptr, nullptr, nullptr, TOK, QKVN, CH);

    // 3) tensor-core windowed attention (2 CTAs per window, 4 heads each)
    attn_kernel<<<4096, 256, ATT_SMEM>>>(qkvb, ow);

    // 4) x1(fp16) = shortcut(x) + proj(ow); h2 = LN2(x1)   (fused)
    mma_gemm<EPI_PROJLN><<<dim3(CH/256, TOK/128), GTHREADS, SMEM_DYN>>>(
        ow, wproj, proj_b, x1, x, n2_g, n2_b, h2, TOK, CH, CH);

    // 5) hmid = gelu(h2 @ mlp_w1 + mlp_b1)
    mma_gemm<EPI_GELU><<<dim3(HIDDEN/256, TOK/128), GTHREADS, SMEM_DYN>>>(
        h2, w1, mlp_b1, hmid, nullptr, nullptr, nullptr, nullptr, TOK, HIDDEN, CH);

    // 6) out(NCHW) = x1 + hmid @ mlp_w2 + mlp_b2   (fused transpose, fp16 residual)
    mma_gemm<EPI_RES><<<dim3(CH/256, TOK/128), GTHREADS, SMEM_DYN>>>(
        hmid, w2, mlp_b2, (float*)d_out, x1, nullptr, nullptr, nullptr, TOK, CH, HIDDEN);
}

// round 14
// speedup vs baseline: 1.8080x; 1.0148x over previous
#include <cuda_runtime.h>
#include <cuda_fp16.h>
#include <math.h>
#include <stdint.h>

// ---------------- problem constants ----------------
#define BATCH 32
#define CH    256
#define HWS   3136
#define TOK   100352
#define SHIFT3 3
#define HEADS 8
#define HDIM  32
#define HIDDEN 1024
#define QKVN  768

// ---------------- scratch ----------------
__device__ __half g_ywin [(size_t)TOK*CH];
__device__ __half g_xh   [(size_t)TOK*CH];     // fp16 shortcut, (b,hw,c)
__device__ __half g_qkv  [(size_t)TOK*QKVN];
__device__ __half g_ow   [(size_t)TOK*CH];
__device__ __half g_x1   [(size_t)TOK*CH];     // fp16 residual
__device__ __half g_h2   [(size_t)TOK*CH];
__device__ __half g_hmid [(size_t)TOK*HIDDEN];
// fp16, TRANSPOSED weight copies: [N][K]
__device__ __half g_wqkv [QKVN*CH];
__device__ __half g_wproj[CH*CH];
__device__ __half g_w1   [HIDDEN*CH];
__device__ __half g_w2   [CH*HIDDEN];

__device__ __forceinline__ void cpasync16(uint32_t dst, const void* src) {
    asm volatile("cp.async.cg.shared.global [%0], [%1], 16;" :: "r"(dst), "l"(src));
}

__device__ __forceinline__ void ldsm4(uint32_t& r0, uint32_t& r1, uint32_t& r2, uint32_t& r3,
                                      uint32_t addr) {
    asm volatile("ldmatrix.sync.aligned.m8n8.x4.shared.b16 {%0,%1,%2,%3}, [%4];"
                 : "=r"(r0), "=r"(r1), "=r"(r2), "=r"(r3) : "r"(addr));
}

__device__ __forceinline__ void ldsm4t(uint32_t& r0, uint32_t& r1, uint32_t& r2, uint32_t& r3,
                                       uint32_t addr) {
    asm volatile("ldmatrix.sync.aligned.m8n8.x4.trans.shared.b16 {%0,%1,%2,%3}, [%4];"
                 : "=r"(r0), "=r"(r1), "=r"(r2), "=r"(r3) : "r"(addr));
}

#define MMA16816(d0,d1,d2,d3,a0,a1,a2,a3,b0,b1) \
    asm volatile( \
        "mma.sync.aligned.m16n8k16.row.col.f32.f16.f16.f32 " \
        "{%0,%1,%2,%3}, {%4,%5,%6,%7}, {%8,%9}, {%0,%1,%2,%3};" \
        : "+f"(d0), "+f"(d1), "+f"(d2), "+f"(d3) \
        : "r"(a0), "r"(a1), "r"(a2), "r"(a3), "r"(b0), "r"(b1))

// ---------------- prep: ALL weights transpose + fp16 round, one launch ----------------
__global__ __launch_bounds__(256) void transpose_round_all(
    const float* __restrict__ w0, __half* __restrict__ o0,
    const float* __restrict__ w1_, __half* __restrict__ o1,
    const float* __restrict__ w2_, __half* __restrict__ o2,
    const float* __restrict__ w3_, __half* __restrict__ o3)
{
    __shared__ float t[32][33];
    int blk = blockIdx.x;
    const float* w; __half* wt; int K, N, nb;
    if (blk < 192)      { w = w0;  wt = o0; K = CH;     N = QKVN;   nb = QKVN/32; }
    else if (blk < 256) { blk -= 192; w = w1_; wt = o1; K = CH;     N = CH;     nb = CH/32; }
    else if (blk < 512) { blk -= 256; w = w2_; wt = o2; K = CH;     N = HIDDEN; nb = HIDDEN/32; }
    else                { blk -= 512; w = w3_; wt = o3; K = HIDDEN; N = CH;     nb = CH/32; }
    const int k0 = (blk / nb) * 32, n0 = (blk % nb) * 32;
    const int x = threadIdx.x & 31, y = threadIdx.x >> 5;
    for (int yy = y; yy < 32; yy += 8)
        t[yy][x] = w[(size_t)(k0 + yy)*N + n0 + x];
    __syncthreads();
    for (int yy = y; yy < 32; yy += 8)
        wt[(size_t)(n0 + yy)*K + k0 + x] = __float2half_rn(t[x][yy]);
}

// ---------------- kernel 1: LN1 + shift + window partition + fp16 NHWC shortcut ----------------
__global__ __launch_bounds__(256) void ln1_kernel(
    const float* __restrict__ x, const float* __restrict__ g, const float* __restrict__ bta,
    __half* __restrict__ ywin, __half* __restrict__ xh)
{
    __shared__ float ts[256*33];
    __shared__ float cmu[32], crs[32];
    const int blk = blockIdx.x;
    const int b   = blk / 98;
    const int hw0 = (blk % 98) * 32;
    const int tid = threadIdx.x;
    const float* xb = x + (size_t)b*CH*HWS;

    for (int idx = tid; idx < 256*32; idx += 256) {
        int ch = idx >> 5, j = idx & 31;
        ts[ch*33 + j] = xb[(size_t)ch*HWS + hw0 + j];
    }
    __syncthreads();

    {
        int col = tid >> 3, kk = tid & 7;
        float s = 0.f, s2 = 0.f;
        for (int ch = kk; ch < 256; ch += 8) {
            float v = ts[ch*33 + col];
            s += v; s2 += v*v;
        }
        #pragma unroll
        for (int o = 4; o; o >>= 1) {
            s  += __shfl_down_sync(0xffffffffu, s,  o, 8);
            s2 += __shfl_down_sync(0xffffffffu, s2, o, 8);
        }
        if (kk == 0) {
            float mu = s * (1.f/256.f);
            cmu[col] = mu;
            crs[col] = rsqrtf(s2*(1.f/256.f) - mu*mu + 1e-5f);
        }
    }
    __syncthreads();

    const float gg = g[tid], bb = bta[tid];
    for (int j = 0; j < 32; j++) {
        int hw = hw0 + j;
        int h = hw / 56, w = hw % 56;
        int hs = h + (56 - SHIFT3); if (hs >= 56) hs -= 56;
        int wsh = w + (56 - SHIFT3); if (wsh >= 56) wsh -= 56;
        int wi = hs / 7, r = hs % 7;
        int wj = wsh / 7, c = wsh % 7;
        int win = ((b << 3) + wi) * 8 + wj;
        int n = r*7 + c;
        float v = ts[tid*33 + j];
        xh[((size_t)b*HWS + hw)*CH + tid] = __float2half_rn(v);
        ywin[((size_t)win*49 + n)*CH + tid] =
            __float2half_rn((v - cmu[j]) * crs[j] * gg + bb);
    }
}

// ---------------- fp16 mma GEMM: CTA 128x256, 16 warps @ 32x64, BK=64, 3-stage ----------------
#define BK 64
#define STAGES 3
#define A_STAGE_B (128*128)
#define B_STAGE_B (256*128)
#define STAGE_B   (A_STAGE_B + B_STAGE_B)
#define SMEM_DYN  (STAGES*STAGE_B)
#define GTHREADS  512

enum { EPI_BIAS = 0, EPI_PROJLN = 1, EPI_GELU = 2, EPI_RES = 3 };

template<int EPI>
__global__ __launch_bounds__(GTHREADS) void mma_gemm(
    const __half* __restrict__ A, const __half* __restrict__ BT,
    const float* __restrict__ bias, void* __restrict__ Cp,
    const void* __restrict__ auxp,
    const float* __restrict__ gamma, const float* __restrict__ beta2,
    __half* __restrict__ h2out,
    int M, int N, int K)
{
    extern __shared__ char sm[];
    const uint32_t smb = (uint32_t)__cvta_generic_to_shared(sm);

    const int tid  = threadIdx.x;
    const int lane = tid & 31, warp = tid >> 5;
    const int g    = lane >> 2, c4 = lane & 3;
    const int wm0  = (warp >> 2) * 32;    // 0..96
    const int wn0  = (warp & 3) * 64;     // 0..192
    const int m0   = blockIdx.y * 128, n0 = blockIdx.x * 256;

    const int fr  = ((lane >> 3) & 1) * 8 + (lane & 7);
    const int fk  = lane >> 4;

    int arow[2], asw[2], brow[4], bsw[4];
    #pragma unroll
    for (int i = 0; i < 2; i++) {
        int ra = wm0 + i*16 + fr;
        arow[i] = ra*128; asw[i] = ra & 7;
    }
    #pragma unroll
    for (int i = 0; i < 4; i++) {
        int rb = wn0 + i*16 + fr;
        brow[i] = rb*128; bsw[i] = rb & 7;
    }

    const int cr = tid >> 3, cc = tid & 7;

    float acc[2][8][4];
    #pragma unroll
    for (int i = 0; i < 2; i++)
        #pragma unroll
        for (int j = 0; j < 8; j++)
            #pragma unroll
            for (int k = 0; k < 4; k++) acc[i][j][k] = 0.f;

    auto fill = [&](int t) {
        const int s = t % STAGES;
        const uint32_t ab = smb + (uint32_t)(s*STAGE_B);
        const uint32_t bb = ab + A_STAGE_B;
        const int k0 = t * BK;
        #pragma unroll
        for (int i = 0; i < 2; i++) {
            int rr = cr + 64*i;
            cpasync16(ab + (uint32_t)(rr*128) + (uint32_t)((cc ^ (rr & 7)) << 4),
                      &A[(size_t)(m0 + rr)*K + k0 + cc*8]);
        }
        #pragma unroll
        for (int i = 0; i < 4; i++) {
            int rr = cr + 64*i;
            cpasync16(bb + (uint32_t)(rr*128) + (uint32_t)((cc ^ (rr & 7)) << 4),
                      &BT[(size_t)(n0 + rr)*K + k0 + cc*8]);
        }
    };

    const int nt = K / BK;
    #pragma unroll
    for (int s = 0; s < STAGES-1; s++) {
        fill(s);
        asm volatile("cp.async.commit_group;");
    }

    for (int t = 0; t < nt; t++) {
        asm volatile("cp.async.wait_group %0;" :: "n"(STAGES-2));
        __syncthreads();
        if (t + STAGES - 1 < nt) fill(t + STAGES - 1);
        asm volatile("cp.async.commit_group;");

        const uint32_t ab = smb + (uint32_t)((t % STAGES)*STAGE_B);
        const uint32_t bb = ab + A_STAGE_B;

        #pragma unroll
        for (int kk = 0; kk < 4; kk++) {
            const int kc = kk*2 + fk;
            uint32_t af[2][4], bf[4][4];
            #pragma unroll
            for (int mi = 0; mi < 2; mi++)
                ldsm4(af[mi][0], af[mi][1], af[mi][2], af[mi][3],
                      ab + (uint32_t)arow[mi] + (uint32_t)((kc ^ asw[mi]) << 4));
            #pragma unroll
            for (int np = 0; np < 4; np++)
                ldsm4(bf[np][0], bf[np][1], bf[np][2], bf[np][3],
                      bb + (uint32_t)brow[np] + (uint32_t)((kc ^ bsw[np]) << 4));

            #pragma unroll
            for (int mi = 0; mi < 2; mi++)
                #pragma unroll
                for (int ni = 0; ni < 8; ni++) {
                    const int p = ni >> 1, sb = ni & 1;
                    MMA16816(acc[mi][ni][0], acc[mi][ni][1], acc[mi][ni][2], acc[mi][ni][3],
                             af[mi][0], af[mi][1], af[mi][2], af[mi][3],
                             bf[p][sb], bf[p][2 + sb]);
                }
        }
    }

    // -------- epilogue --------
    if (EPI == EPI_PROJLN) {
        asm volatile("cp.async.wait_group 0;" ::: "memory");
        __syncthreads();
        const __half* aux = (const __half*)auxp;   // fp16 shortcut, (b,hw,c)
        float* red  = (float*)sm;
        float* red2 = red + 512;
        float* smu  = red2 + 512;
        float* srs  = smu + 128;

        __half* C = (__half*)Cp;                 // x1, fp16
        float psum[2][2], psum2[2][2];
        #pragma unroll
        for (int mi = 0; mi < 2; mi++) { psum[mi][0]=psum[mi][1]=psum2[mi][0]=psum2[mi][1]=0.f; }

        #pragma unroll
        for (int mi = 0; mi < 2; mi++) {
            #pragma unroll
            for (int h = 0; h < 2; h++) {
                const int m = m0 + wm0 + mi*16 + g + 8*h;
                int win = m / 49, n = m % 49;
                int bq = win >> 6;
                int wr = (win >> 3) & 7;
                int wc = win & 7;
                int rr = n / 7, ccv = n % 7;
                int hh = wr*7 + rr + SHIFT3; if (hh >= 56) hh -= 56;
                int wwv = wc*7 + ccv + SHIFT3; if (wwv >= 56) wwv -= 56;
                int sp = hh*56 + wwv;
                size_t drow = (size_t)bq*HWS + sp;
                #pragma unroll
                for (int ni = 0; ni < 8; ni++) {
                    const int col = wn0 + ni*8 + 2*c4;
                    __half2 a = *reinterpret_cast<const __half2*>(&aux[drow*CH + col]);
                    float v0 = acc[mi][ni][2*h+0] + bias[col]   + __low2float(a);
                    float v1 = acc[mi][ni][2*h+1] + bias[col+1] + __high2float(a);
                    acc[mi][ni][2*h+0] = v0; acc[mi][ni][2*h+1] = v1;
                    *reinterpret_cast<__half2*>(&C[drow*CH + col]) = __floats2half2_rn(v0, v1);
                    psum [mi][h] += v0 + v1;
                    psum2[mi][h] += v0*v0 + v1*v1;
                }
            }
        }
        #pragma unroll
        for (int mi = 0; mi < 2; mi++)
            #pragma unroll
            for (int h = 0; h < 2; h++) {
                float s = psum[mi][h], s2 = psum2[mi][h];
                s  += __shfl_xor_sync(0xffffffffu, s, 1);  s  += __shfl_xor_sync(0xffffffffu, s, 2);
                s2 += __shfl_xor_sync(0xffffffffu, s2, 1); s2 += __shfl_xor_sync(0xffffffffu, s2, 2);
                if (c4 == 0) {
                    int rloc = wm0 + mi*16 + g + 8*h;
                    red [rloc*4 + (warp & 3)] = s;
                    red2[rloc*4 + (warp & 3)] = s2;
                }
            }
        __syncthreads();
        if (tid < 128) {
            float s  = red [tid*4] + red [tid*4+1] + red [tid*4+2] + red [tid*4+3];
            float s2 = red2[tid*4] + red2[tid*4+1] + red2[tid*4+2] + red2[tid*4+3];
            float mu = s * (1.f/256.f);
            smu[tid] = mu;
            srs[tid] = rsqrtf(s2*(1.f/256.f) - mu*mu + 1e-5f);
        }
        __syncthreads();
        #pragma unroll
        for (int mi = 0; mi < 2; mi++) {
            #pragma unroll
            for (int h = 0; h < 2; h++) {
                const int rloc = wm0 + mi*16 + g + 8*h;
                const int m = m0 + rloc;
                float mu = smu[rloc], rs = srs[rloc];
                int win = m / 49, n = m % 49;
                int bq = win >> 6;
                int wr = (win >> 3) & 7;
                int wc = win & 7;
                int rr = n / 7, ccv = n % 7;
                int hh = wr*7 + rr + SHIFT3; if (hh >= 56) hh -= 56;
                int wwv = wc*7 + ccv + SHIFT3; if (wwv >= 56) wwv -= 56;
                size_t drow = (size_t)bq*HWS + hh*56 + wwv;
                #pragma unroll
                for (int ni = 0; ni < 8; ni++) {
                    const int col = wn0 + ni*8 + 2*c4;
                    float h0 = (acc[mi][ni][2*h+0] - mu)*rs*gamma[col  ] + beta2[col  ];
                    float h1 = (acc[mi][ni][2*h+1] - mu)*rs*gamma[col+1] + beta2[col+1];
                    *reinterpret_cast<__half2*>(&h2out[drow*CH + col]) = __floats2half2_rn(h0, h1);
                }
            }
        }
        return;
    }

    if (EPI == EPI_RES) {
        // stage output tile [256 cols][128 m] in smem, then coalesced NCHW writes
        asm volatile("cp.async.wait_group 0;" ::: "memory");
        __syncthreads();
        float* ts = (float*)sm;   // stride 132 floats per col-row: 256*132*4 = 135168 B
        const __half* aux = (const __half*)auxp;
        float* C = (float*)Cp;

        #pragma unroll
        for (int mi = 0; mi < 2; mi++) {
            #pragma unroll
            for (int h = 0; h < 2; h++) {
                const int mloc = wm0 + mi*16 + g + 8*h;
                const int m = m0 + mloc;
                #pragma unroll
                for (int ni = 0; ni < 8; ni++) {
                    const int col = wn0 + ni*8 + 2*c4;   // n0 == 0 (grid.x == 1)
                    __half2 a = *reinterpret_cast<const __half2*>(&aux[(size_t)m*N + col]);
                    ts[ col   *132 + mloc] = acc[mi][ni][2*h+0] + bias[col]   + __low2float(a);
                    ts[(col+1)*132 + mloc] = acc[mi][ni][2*h+1] + bias[col+1] + __high2float(a);
                }
            }
        }
        __syncthreads();
        // copy out: 256 cols x 32 float4
        for (int i = tid; i < 256*32; i += GTHREADS) {
            const int colr = i >> 5, q = i & 31;
            const int m = m0 + q*4;
            const int bq = m / HWS;
            const int sp = m - bq*HWS;
            float4 v = *reinterpret_cast<const float4*>(&ts[colr*132 + q*4]);
            *reinterpret_cast<float4*>(&C[((size_t)(bq*CH + colr))*HWS + sp]) = v;
        }
        return;
    }

    #pragma unroll
    for (int mi = 0; mi < 2; mi++) {
        #pragma unroll
        for (int h = 0; h < 2; h++) {
            const int m = m0 + wm0 + mi*16 + g + 8*h;
            #pragma unroll
            for (int ni = 0; ni < 8; ni++) {
                const int col = n0 + wn0 + ni*8 + 2*c4;
                float v0 = acc[mi][ni][2*h + 0] + bias[col];
                float v1 = acc[mi][ni][2*h + 1] + bias[col + 1];
                if (EPI == EPI_BIAS) {
                    __half2* C = (__half2*)Cp;
                    C[((size_t)m*N + col) >> 1] = __floats2half2_rn(v0, v1);
                } else { // EPI_GELU
                    __half2* C = (__half2*)Cp;
                    float g0 = 0.5f*v0*(1.f + erff(v0*0.70710678118654752f));
                    float g1 = 0.5f*v1*(1.f + erff(v1*0.70710678118654752f));
                    C[((size_t)m*N + col) >> 1] = __floats2half2_rn(g0, g1);
                }
            }
        }
    }
}

// ---------------- kernel 3: TC attention, CTA = (window, 4 heads), 256 thr ----------------
#define T_STRIDE 40
#define REG_HALFS (64*T_STRIDE)
#define ATT_SMEM  (12*REG_HALFS*2)      // 61440 B -> 3 CTAs/SM

__global__ __launch_bounds__(256) void attn_kernel(
    const __half* __restrict__ qkv, __half* __restrict__ o)
{
    extern __shared__ __half ash[];
    const int win  = blockIdx.x >> 1;
    const int hgrp = blockIdx.x & 1;
    const int tid  = threadIdx.x;
    const int warp = tid >> 5, lane = tid & 31;
    const int hloc = warp >> 1, half = warp & 1;
    const int head = hgrp*4 + hloc;
    const int g    = lane >> 2, c4 = lane & 3;
    const int fr   = ((lane >> 3) & 1) * 8 + (lane & 7);
    const int fk   = lane >> 4;

    __half* Qb = ash;
    __half* Kb = ash + 4*REG_HALFS;
    __half* Vb = ash + 8*REG_HALFS;

    for (int i = tid; i < 300; i += 256) {
        int h = i / 75, rem = i % 75;
        int row = 49 + rem / 5, q = rem % 5;
        *(uint4*)(Vb + h*REG_HALFS + row*T_STRIDE + q*8) = make_uint4(0,0,0,0);
    }
    __syncthreads();

    const __half* src = qkv + (size_t)win*49*QKVN;
    for (int idx = tid; idx < 49*48; idx += 256) {
        int n = idx / 48, ck = idx % 48;
        int sec = ck >> 4;
        int cc  = ck & 15;
        int hl  = cc >> 2, dq = (cc & 3)*8;
        int col = sec*256 + (hgrp*4 + hl)*32 + dq;
        uint4 v = *(const uint4*)(src + (size_t)n*QKVN + col);
        __half* base = (sec == 0) ? Qb : (sec == 1) ? Kb : Vb;
        *(uint4*)(base + hl*REG_HALFS + n*T_STRIDE + dq) = v;
    }
    __syncthreads();

    const uint32_t Qsm = (uint32_t)__cvta_generic_to_shared(Qb + hloc*REG_HALFS)
                       + (half*32 + fr)*T_STRIDE*2;
    const uint32_t Ksm = (uint32_t)__cvta_generic_to_shared(Kb + hloc*REG_HALFS)
                       + fr*T_STRIDE*2;
    const uint32_t Vsm = (uint32_t)__cvta_generic_to_shared(Vb + hloc*REG_HALFS)
                       + fr*T_STRIDE*2;

    float acc[2][7][4];
    #pragma unroll
    for (int i = 0; i < 2; i++)
        #pragma unroll
        for (int j = 0; j < 7; j++)
            #pragma unroll
            for (int k = 0; k < 4; k++) acc[i][j][k] = 0.f;

    #pragma unroll
    for (int kk = 0; kk < 2; kk++) {
        const int kc = kk*2 + fk;
        uint32_t af[2][4], bf[4][4];
        #pragma unroll
        for (int mi = 0; mi < 2; mi++)
            ldsm4(af[mi][0], af[mi][1], af[mi][2], af[mi][3],
                  Qsm + mi*16*T_STRIDE*2 + kc*16);
        #pragma unroll
        for (int p = 0; p < 4; p++)
            ldsm4(bf[p][0], bf[p][1], bf[p][2], bf[p][3],
                  Ksm + p*16*T_STRIDE*2 + kc*16);
        #pragma unroll
        for (int mi = 0; mi < 2; mi++)
            #pragma unroll
            for (int ni = 0; ni < 7; ni++) {
                const int p = ni >> 1, sb = ni & 1;
                MMA16816(acc[mi][ni][0], acc[mi][ni][1], acc[mi][ni][2], acc[mi][ni][3],
                         af[mi][0], af[mi][1], af[mi][2], af[mi][3],
                         bf[p][sb], bf[p][2 + sb]);
            }
    }

    const float scale = 0.17677669529663687f;
    float mx[2][2], sum[2][2];
    #pragma unroll
    for (int mi = 0; mi < 2; mi++) { mx[mi][0] = mx[mi][1] = -1e30f; sum[mi][0] = sum[mi][1] = 0.f; }

    #pragma unroll
    for (int mi = 0; mi < 2; mi++)
        #pragma unroll
        for (int ni = 0; ni < 7; ni++)
            #pragma unroll
            for (int b = 0; b < 2; b++) {
                int j = ni*8 + 2*c4 + b;
                float v0 = acc[mi][ni][b]   * scale;
                float v1 = acc[mi][ni][2+b] * scale;
                if (j >= 49) { v0 = -1e30f; v1 = -1e30f; }
                acc[mi][ni][b] = v0; acc[mi][ni][2+b] = v1;
                mx[mi][0] = fmaxf(mx[mi][0], v0);
                mx[mi][1] = fmaxf(mx[mi][1], v1);
            }
    #pragma unroll
    for (int mi = 0; mi < 2; mi++)
        #pragma unroll
        for (int r = 0; r < 2; r++) {
            float m_ = mx[mi][r];
            m_ = fmaxf(m_, __shfl_xor_sync(0xffffffffu, m_, 1));
            m_ = fmaxf(m_, __shfl_xor_sync(0xffffffffu, m_, 2));
            mx[mi][r] = m_;
        }
    #pragma unroll
    for (int mi = 0; mi < 2; mi++)
        #pragma unroll
        for (int ni = 0; ni < 7; ni++)
            #pragma unroll
            for (int b = 0; b < 2; b++) {
                float e0 = __expf(acc[mi][ni][b]   - mx[mi][0]);
                float e1 = __expf(acc[mi][ni][2+b] - mx[mi][1]);
                acc[mi][ni][b] = e0; acc[mi][ni][2+b] = e1;
                sum[mi][0] += e0; sum[mi][1] += e1;
            }
    #pragma unroll
    for (int mi = 0; mi < 2; mi++)
        #pragma unroll
        for (int r = 0; r < 2; r++) {
            float s_ = sum[mi][r];
            s_ += __shfl_xor_sync(0xffffffffu, s_, 1);
            s_ += __shfl_xor_sync(0xffffffffu, s_, 2);
            sum[mi][r] = 1.f / s_;
        }

    uint32_t ph[2][7][2];
    #pragma unroll
    for (int mi = 0; mi < 2; mi++)
        #pragma unroll
        for (int ni = 0; ni < 7; ni++) {
            __half2 p0 = __floats2half2_rn(acc[mi][ni][0]*sum[mi][0], acc[mi][ni][1]*sum[mi][0]);
            __half2 p1 = __floats2half2_rn(acc[mi][ni][2]*sum[mi][1], acc[mi][ni][3]*sum[mi][1]);
            ph[mi][ni][0] = *reinterpret_cast<uint32_t*>(&p0);
            ph[mi][ni][1] = *reinterpret_cast<uint32_t*>(&p1);
        }

    float oacc[2][4][4];
    #pragma unroll
    for (int i = 0; i < 2; i++)
        #pragma unroll
        for (int j = 0; j < 4; j++)
            #pragma unroll
            for (int k = 0; k < 4; k++) oacc[i][j][k] = 0.f;

    #pragma unroll
    for (int kf = 0; kf < 4; kf++) {
        uint32_t bf[2][4];
        #pragma unroll
        for (int cp = 0; cp < 2; cp++)
            ldsm4t(bf[cp][0], bf[cp][1], bf[cp][2], bf[cp][3],
                   Vsm + kf*16*T_STRIDE*2 + (2*cp + fk)*16);
        #pragma unroll
        for (int mi = 0; mi < 2; mi++) {
            const int n0f = 2*kf, n1f = 2*kf + 1;
            uint32_t a0 = ph[mi][n0f][0], a1 = ph[mi][n0f][1];
            uint32_t a2 = (n1f < 7) ? ph[mi][n1f][0] : 0u;
            uint32_t a3 = (n1f < 7) ? ph[mi][n1f][1] : 0u;
            #pragma unroll
            for (int ni2 = 0; ni2 < 4; ni2++) {
                const int cp = ni2 >> 1, q = ni2 & 1;
                MMA16816(oacc[mi][ni2][0], oacc[mi][ni2][1], oacc[mi][ni2][2], oacc[mi][ni2][3],
                         a0, a1, a2, a3, bf[cp][2*q], bf[cp][2*q + 1]);
            }
        }
    }

    #pragma unroll
    for (int mi = 0; mi < 2; mi++) {
        const int i0 = half*32 + mi*16 + g, i1 = i0 + 8;
        #pragma unroll
        for (int ni2 = 0; ni2 < 4; ni2++) {
            const int col = head*HDIM + ni2*8 + 2*c4;
            if (i0 < 49) {
                __half2 v = __floats2half2_rn(oacc[mi][ni2][0], oacc[mi][ni2][1]);
                *reinterpret_cast<__half2*>(&o[((size_t)win*49 + i0)*CH + col]) = v;
            }
            if (i1 < 49) {
                __half2 v = __floats2half2_rn(oacc[mi][ni2][2], oacc[mi][ni2][3]);
                *reinterpret_cast<__half2*>(&o[((size_t)win*49 + i1)*CH + col]) = v;
            }
        }
    }
}

// ---------------- launch ----------------
extern "C" void kernel_launch(void* const* d_in, const int* in_sizes, int n_in,
                              void* d_out, int out_size)
{
    const float* x      = (const float*)d_in[0];
    const float* n1_g   = (const float*)d_in[1];
    const float* n1_b   = (const float*)d_in[2];
    const float* qkv_w  = (const float*)d_in[3];
    const float* qkv_b  = (const float*)d_in[4];
    const float* proj_w = (const float*)d_in[5];
    const float* proj_b = (const float*)d_in[6];
    const float* n2_g   = (const float*)d_in[7];
    const float* n2_b   = (const float*)d_in[8];
    const float* mlp_w1 = (const float*)d_in[9];
    const float* mlp_b1 = (const float*)d_in[10];
    const float* mlp_w2 = (const float*)d_in[11];
    const float* mlp_b2 = (const float*)d_in[12];

    __half *ywin, *xh, *qkvb, *ow, *x1, *h2, *hmid;
    __half *wqkv, *wproj, *w1, *w2;
    cudaGetSymbolAddress((void**)&ywin,  g_ywin);
    cudaGetSymbolAddress((void**)&xh,    g_xh);
    cudaGetSymbolAddress((void**)&qkvb,  g_qkv);
    cudaGetSymbolAddress((void**)&ow,    g_ow);
    cudaGetSymbolAddress((void**)&x1,    g_x1);
    cudaGetSymbolAddress((void**)&h2,    g_h2);
    cudaGetSymbolAddress((void**)&hmid,  g_hmid);
    cudaGetSymbolAddress((void**)&wqkv,  g_wqkv);
    cudaGetSymbolAddress((void**)&wproj, g_wproj);
    cudaGetSymbolAddress((void**)&w1,    g_w1);
    cudaGetSymbolAddress((void**)&w2,    g_w2);

    static bool attr_done = false;
    if (!attr_done) {
        cudaFuncSetAttribute(mma_gemm<EPI_BIAS>,   cudaFuncAttributeMaxDynamicSharedMemorySize, SMEM_DYN);
        cudaFuncSetAttribute(mma_gemm<EPI_PROJLN>, cudaFuncAttributeMaxDynamicSharedMemorySize, SMEM_DYN);
        cudaFuncSetAttribute(mma_gemm<EPI_GELU>,   cudaFuncAttributeMaxDynamicSharedMemorySize, SMEM_DYN);
        cudaFuncSetAttribute(mma_gemm<EPI_RES>,    cudaFuncAttributeMaxDynamicSharedMemorySize, SMEM_DYN);
        cudaFuncSetAttribute(attn_kernel,          cudaFuncAttributeMaxDynamicSharedMemorySize, ATT_SMEM);
        attr_done = true;
    }

    // 0) all weights: transpose + fp16 round -> [N][K]
    transpose_round_all<<<768, 256>>>(qkv_w, wqkv, proj_w, wproj, mlp_w1, w1, mlp_w2, w2);

    // 1) LN1 + shift + window partition + fp16 shortcut
    ln1_kernel<<<BATCH*98, 256>>>(x, n1_g, n1_b, ywin, xh);

    // 2) qkv = ywin @ qkv_w + qkv_b
    mma_gemm<EPI_BIAS><<<dim3(QKVN/256, TOK/128), GTHREADS, SMEM_DYN>>>(
        ywin, wqkv, qkv_b, qkvb, nullptr, nullptr, nullptr, nullptr, TOK, QKVN, CH);

    // 3) tensor-core windowed attention (2 CTAs per window, 4 heads each)
    attn_kernel<<<4096, 256, ATT_SMEM>>>(qkvb, ow);

    // 4) x1(fp16) = shortcut(xh) + proj(ow); h2 = LN2(x1)   (fused)
    mma_gemm<EPI_PROJLN><<<dim3(CH/256, TOK/128), GTHREADS, SMEM_DYN>>>(
        ow, wproj, proj_b, x1, xh, n2_g, n2_b, h2, TOK, CH, CH);

    // 5) hmid = gelu(h2 @ mlp_w1 + mlp_b1)
    mma_gemm<EPI_GELU><<<dim3(HIDDEN/256, TOK/128), GTHREADS, SMEM_DYN>>>(
        h2, w1, mlp_b1, hmid, nullptr, nullptr, nullptr, nullptr, TOK, HIDDEN, CH);

    // 6) out(NCHW) = x1 + hmid @ mlp_w2 + mlp_b2   (smem-staged coalesced transpose)
    mma_gemm<EPI_RES><<<dim3(CH/256, TOK/128), GTHREADS, SMEM_DYN>>>(
        hmid, w2, mlp_b2, (float*)d_out, x1, nullptr, nullptr, nullptr, TOK, CH, HIDDEN);
}

// round 15
// speedup vs baseline: 1.8659x; 1.0320x over previous
#include <cuda_runtime.h>
#include <cuda_fp16.h>
#include <math.h>
#include <stdint.h>

// ---------------- problem constants ----------------
#define BATCH 32
#define CH    256
#define HWS   3136
#define TOK   100352
#define SHIFT3 3
#define HEADS 8
#define HDIM  32
#define HIDDEN 1024
#define QKVN  768

// ---------------- scratch ----------------
__device__ __half g_ywin [(size_t)TOK*CH];
__device__ __half g_xh   [(size_t)TOK*CH];     // fp16 shortcut, (b,hw,c)
__device__ __half g_qkv  [(size_t)TOK*QKVN];
__device__ __half g_ow   [(size_t)TOK*CH];
__device__ __half g_x1   [(size_t)TOK*CH];     // fp16 residual
__device__ __half g_h2   [(size_t)TOK*CH];
__device__ __half g_hmid [(size_t)TOK*HIDDEN];
// fp16, TRANSPOSED weight copies: [N][K]
__device__ __half g_wqkv [QKVN*CH];
__device__ __half g_wproj[CH*CH];
__device__ __half g_w1   [HIDDEN*CH];
__device__ __half g_w2   [CH*HIDDEN];

__device__ __forceinline__ void cpasync16(uint32_t dst, const void* src) {
    asm volatile("cp.async.cg.shared.global [%0], [%1], 16;" :: "r"(dst), "l"(src));
}

__device__ __forceinline__ void ldsm4(uint32_t& r0, uint32_t& r1, uint32_t& r2, uint32_t& r3,
                                      uint32_t addr) {
    asm volatile("ldmatrix.sync.aligned.m8n8.x4.shared.b16 {%0,%1,%2,%3}, [%4];"
                 : "=r"(r0), "=r"(r1), "=r"(r2), "=r"(r3) : "r"(addr));
}

__device__ __forceinline__ void ldsm4t(uint32_t& r0, uint32_t& r1, uint32_t& r2, uint32_t& r3,
                                       uint32_t addr) {
    asm volatile("ldmatrix.sync.aligned.m8n8.x4.trans.shared.b16 {%0,%1,%2,%3}, [%4];"
                 : "=r"(r0), "=r"(r1), "=r"(r2), "=r"(r3) : "r"(addr));
}

#define MMA16816(d0,d1,d2,d3,a0,a1,a2,a3,b0,b1) \
    asm volatile( \
        "mma.sync.aligned.m16n8k16.row.col.f32.f16.f16.f32 " \
        "{%0,%1,%2,%3}, {%4,%5,%6,%7}, {%8,%9}, {%0,%1,%2,%3};" \
        : "+f"(d0), "+f"(d1), "+f"(d2), "+f"(d3) \
        : "r"(a0), "r"(a1), "r"(a2), "r"(a3), "r"(b0), "r"(b1))

// ---------------- prep: ALL weights transpose + fp16 round, one launch ----------------
__global__ __launch_bounds__(256) void transpose_round_all(
    const float* __restrict__ w0, __half* __restrict__ o0,
    const float* __restrict__ w1_, __half* __restrict__ o1,
    const float* __restrict__ w2_, __half* __restrict__ o2,
    const float* __restrict__ w3_, __half* __restrict__ o3)
{
    __shared__ float t[32][33];
    int blk = blockIdx.x;
    const float* w; __half* wt; int K, N, nb;
    if (blk < 192)      { w = w0;  wt = o0; K = CH;     N = QKVN;   nb = QKVN/32; }
    else if (blk < 256) { blk -= 192; w = w1_; wt = o1; K = CH;     N = CH;     nb = CH/32; }
    else if (blk < 512) { blk -= 256; w = w2_; wt = o2; K = CH;     N = HIDDEN; nb = HIDDEN/32; }
    else                { blk -= 512; w = w3_; wt = o3; K = HIDDEN; N = CH;     nb = CH/32; }
    const int k0 = (blk / nb) * 32, n0 = (blk % nb) * 32;
    const int x = threadIdx.x & 31, y = threadIdx.x >> 5;
    for (int yy = y; yy < 32; yy += 8)
        t[yy][x] = w[(size_t)(k0 + yy)*N + n0 + x];
    __syncthreads();
    for (int yy = y; yy < 32; yy += 8)
        wt[(size_t)(n0 + yy)*K + k0 + x] = __float2half_rn(t[x][yy]);
}

// ---------------- kernel 1: LN1 + shift + window partition + fp16 NHWC shortcut ----------------
__global__ __launch_bounds__(256) void ln1_kernel(
    const float* __restrict__ x, const float* __restrict__ g, const float* __restrict__ bta,
    __half* __restrict__ ywin, __half* __restrict__ xh)
{
    __shared__ float ts[256*33];
    __shared__ float cmu[32], crs[32];
    const int blk = blockIdx.x;
    const int b   = blk / 98;
    const int hw0 = (blk % 98) * 32;
    const int tid = threadIdx.x;
    const float* xb = x + (size_t)b*CH*HWS;

    for (int idx = tid; idx < 256*32; idx += 256) {
        int ch = idx >> 5, j = idx & 31;
        ts[ch*33 + j] = xb[(size_t)ch*HWS + hw0 + j];
    }
    __syncthreads();

    {
        int col = tid >> 3, kk = tid & 7;
        float s = 0.f, s2 = 0.f;
        for (int ch = kk; ch < 256; ch += 8) {
            float v = ts[ch*33 + col];
            s += v; s2 += v*v;
        }
        #pragma unroll
        for (int o = 4; o; o >>= 1) {
            s  += __shfl_down_sync(0xffffffffu, s,  o, 8);
            s2 += __shfl_down_sync(0xffffffffu, s2, o, 8);
        }
        if (kk == 0) {
            float mu = s * (1.f/256.f);
            cmu[col] = mu;
            crs[col] = rsqrtf(s2*(1.f/256.f) - mu*mu + 1e-5f);
        }
    }
    __syncthreads();

    const float gg = g[tid], bb = bta[tid];
    for (int j = 0; j < 32; j++) {
        int hw = hw0 + j;
        int h = hw / 56, w = hw % 56;
        int hs = h + (56 - SHIFT3); if (hs >= 56) hs -= 56;
        int wsh = w + (56 - SHIFT3); if (wsh >= 56) wsh -= 56;
        int wi = hs / 7, r = hs % 7;
        int wj = wsh / 7, c = wsh % 7;
        int win = ((b << 3) + wi) * 8 + wj;
        int n = r*7 + c;
        float v = ts[tid*33 + j];
        xh[((size_t)b*HWS + hw)*CH + tid] = __float2half_rn(v);
        ywin[((size_t)win*49 + n)*CH + tid] =
            __float2half_rn((v - cmu[j]) * crs[j] * gg + bb);
    }
}

// ---------------- fp16 mma GEMM: CTA 128x256, 16 warps @ 32x64, BK=64, 4-stage ----------------
#define BK 64
#define STAGES 4
#define A_STAGE_B (128*128)
#define B_STAGE_B (256*128)
#define STAGE_B   (A_STAGE_B + B_STAGE_B)
#define SMEM_DYN  (STAGES*STAGE_B)     // 192 KB
#define GTHREADS  512

enum { EPI_BIAS = 0, EPI_PROJLN = 1, EPI_GELU = 2, EPI_RES = 3 };

template<int EPI>
__global__ __launch_bounds__(GTHREADS) void mma_gemm(
    const __half* __restrict__ A, const __half* __restrict__ BT,
    const float* __restrict__ bias, void* __restrict__ Cp,
    const void* __restrict__ auxp,
    const float* __restrict__ gamma, const float* __restrict__ beta2,
    __half* __restrict__ h2out,
    int M, int N, int K)
{
    extern __shared__ char sm[];
    const uint32_t smb = (uint32_t)__cvta_generic_to_shared(sm);

    const int tid  = threadIdx.x;
    const int lane = tid & 31, warp = tid >> 5;
    const int g    = lane >> 2, c4 = lane & 3;
    const int wm0  = (warp >> 2) * 32;
    const int wn0  = (warp & 3) * 64;
    const int m0   = blockIdx.y * 128, n0 = blockIdx.x * 256;

    const int fr  = ((lane >> 3) & 1) * 8 + (lane & 7);
    const int fk  = lane >> 4;

    int arow[2], asw[2], brow[4], bsw[4];
    #pragma unroll
    for (int i = 0; i < 2; i++) {
        int ra = wm0 + i*16 + fr;
        arow[i] = ra*128; asw[i] = ra & 7;
    }
    #pragma unroll
    for (int i = 0; i < 4; i++) {
        int rb = wn0 + i*16 + fr;
        brow[i] = rb*128; bsw[i] = rb & 7;
    }

    const int cr = tid >> 3, cc = tid & 7;

    float acc[2][8][4];
    #pragma unroll
    for (int i = 0; i < 2; i++)
        #pragma unroll
        for (int j = 0; j < 8; j++)
            #pragma unroll
            for (int k = 0; k < 4; k++) acc[i][j][k] = 0.f;

    auto fill = [&](int t) {
        const int s = t % STAGES;
        const uint32_t ab = smb + (uint32_t)(s*STAGE_B);
        const uint32_t bb = ab + A_STAGE_B;
        const int k0 = t * BK;
        #pragma unroll
        for (int i = 0; i < 2; i++) {
            int rr = cr + 64*i;
            cpasync16(ab + (uint32_t)(rr*128) + (uint32_t)((cc ^ (rr & 7)) << 4),
                      &A[(size_t)(m0 + rr)*K + k0 + cc*8]);
        }
        #pragma unroll
        for (int i = 0; i < 4; i++) {
            int rr = cr + 64*i;
            cpasync16(bb + (uint32_t)(rr*128) + (uint32_t)((cc ^ (rr & 7)) << 4),
                      &BT[(size_t)(n0 + rr)*K + k0 + cc*8]);
        }
    };

    const int nt = K / BK;
    #pragma unroll
    for (int s = 0; s < STAGES-1; s++) {
        if (s < nt) fill(s);
        asm volatile("cp.async.commit_group;");
    }

    for (int t = 0; t < nt; t++) {
        asm volatile("cp.async.wait_group %0;" :: "n"(STAGES-2));
        __syncthreads();
        if (t + STAGES - 1 < nt) fill(t + STAGES - 1);
        asm volatile("cp.async.commit_group;");

        const uint32_t ab = smb + (uint32_t)((t % STAGES)*STAGE_B);
        const uint32_t bb = ab + A_STAGE_B;

        #pragma unroll
        for (int kk = 0; kk < 4; kk++) {
            const int kc = kk*2 + fk;
            uint32_t af[2][4], bf[4][4];
            #pragma unroll
            for (int mi = 0; mi < 2; mi++)
                ldsm4(af[mi][0], af[mi][1], af[mi][2], af[mi][3],
                      ab + (uint32_t)arow[mi] + (uint32_t)((kc ^ asw[mi]) << 4));
            #pragma unroll
            for (int np = 0; np < 4; np++)
                ldsm4(bf[np][0], bf[np][1], bf[np][2], bf[np][3],
                      bb + (uint32_t)brow[np] + (uint32_t)((kc ^ bsw[np]) << 4));

            #pragma unroll
            for (int mi = 0; mi < 2; mi++)
                #pragma unroll
                for (int ni = 0; ni < 8; ni++) {
                    const int p = ni >> 1, sb = ni & 1;
                    MMA16816(acc[mi][ni][0], acc[mi][ni][1], acc[mi][ni][2], acc[mi][ni][3],
                             af[mi][0], af[mi][1], af[mi][2], af[mi][3],
                             bf[p][sb], bf[p][2 + sb]);
                }
        }
    }

    // -------- epilogue --------
    if (EPI == EPI_PROJLN) {
        asm volatile("cp.async.wait_group 0;" ::: "memory");
        __syncthreads();
        const __half* aux = (const __half*)auxp;   // fp16 shortcut, (b,hw,c)
        float* red  = (float*)sm;
        float* red2 = red + 512;
        float* smu  = red2 + 512;
        float* srs  = smu + 128;

        __half* C = (__half*)Cp;
        float psum[2][2], psum2[2][2];
        #pragma unroll
        for (int mi = 0; mi < 2; mi++) { psum[mi][0]=psum[mi][1]=psum2[mi][0]=psum2[mi][1]=0.f; }

        #pragma unroll
        for (int mi = 0; mi < 2; mi++) {
            #pragma unroll
            for (int h = 0; h < 2; h++) {
                const int m = m0 + wm0 + mi*16 + g + 8*h;
                int win = m / 49, n = m % 49;
                int bq = win >> 6;
                int wr = (win >> 3) & 7;
                int wc = win & 7;
                int rr = n / 7, ccv = n % 7;
                int hh = wr*7 + rr + SHIFT3; if (hh >= 56) hh -= 56;
                int wwv = wc*7 + ccv + SHIFT3; if (wwv >= 56) wwv -= 56;
                int sp = hh*56 + wwv;
                size_t drow = (size_t)bq*HWS + sp;
                #pragma unroll
                for (int ni = 0; ni < 8; ni++) {
                    const int col = wn0 + ni*8 + 2*c4;
                    __half2 a = *reinterpret_cast<const __half2*>(&aux[drow*CH + col]);
                    float v0 = acc[mi][ni][2*h+0] + bias[col]   + __low2float(a);
                    float v1 = acc[mi][ni][2*h+1] + bias[col+1] + __high2float(a);
                    acc[mi][ni][2*h+0] = v0; acc[mi][ni][2*h+1] = v1;
                    *reinterpret_cast<__half2*>(&C[drow*CH + col]) = __floats2half2_rn(v0, v1);
                    psum [mi][h] += v0 + v1;
                    psum2[mi][h] += v0*v0 + v1*v1;
                }
            }
        }
        #pragma unroll
        for (int mi = 0; mi < 2; mi++)
            #pragma unroll
            for (int h = 0; h < 2; h++) {
                float s = psum[mi][h], s2 = psum2[mi][h];
                s  += __shfl_xor_sync(0xffffffffu, s, 1);  s  += __shfl_xor_sync(0xffffffffu, s, 2);
                s2 += __shfl_xor_sync(0xffffffffu, s2, 1); s2 += __shfl_xor_sync(0xffffffffu, s2, 2);
                if (c4 == 0) {
                    int rloc = wm0 + mi*16 + g + 8*h;
                    red [rloc*4 + (warp & 3)] = s;
                    red2[rloc*4 + (warp & 3)] = s2;
                }
            }
        __syncthreads();
        if (tid < 128) {
            float s  = red [tid*4] + red [tid*4+1] + red [tid*4+2] + red [tid*4+3];
            float s2 = red2[tid*4] + red2[tid*4+1] + red2[tid*4+2] + red2[tid*4+3];
            float mu = s * (1.f/256.f);
            smu[tid] = mu;
            srs[tid] = rsqrtf(s2*(1.f/256.f) - mu*mu + 1e-5f);
        }
        __syncthreads();
        #pragma unroll
        for (int mi = 0; mi < 2; mi++) {
            #pragma unroll
            for (int h = 0; h < 2; h++) {
                const int rloc = wm0 + mi*16 + g + 8*h;
                const int m = m0 + rloc;
                float mu = smu[rloc], rs = srs[rloc];
                int win = m / 49, n = m % 49;
                int bq = win >> 6;
                int wr = (win >> 3) & 7;
                int wc = win & 7;
                int rr = n / 7, ccv = n % 7;
                int hh = wr*7 + rr + SHIFT3; if (hh >= 56) hh -= 56;
                int wwv = wc*7 + ccv + SHIFT3; if (wwv >= 56) wwv -= 56;
                size_t drow = (size_t)bq*HWS + hh*56 + wwv;
                #pragma unroll
                for (int ni = 0; ni < 8; ni++) {
                    const int col = wn0 + ni*8 + 2*c4;
                    float h0 = (acc[mi][ni][2*h+0] - mu)*rs*gamma[col  ] + beta2[col  ];
                    float h1 = (acc[mi][ni][2*h+1] - mu)*rs*gamma[col+1] + beta2[col+1];
                    *reinterpret_cast<__half2*>(&h2out[drow*CH + col]) = __floats2half2_rn(h0, h1);
                }
            }
        }
        return;
    }

    if (EPI == EPI_RES) {
        asm volatile("cp.async.wait_group 0;" ::: "memory");
        __syncthreads();
        float* ts = (float*)sm;
        const __half* aux = (const __half*)auxp;
        float* C = (float*)Cp;

        #pragma unroll
        for (int mi = 0; mi < 2; mi++) {
            #pragma unroll
            for (int h = 0; h < 2; h++) {
                const int mloc = wm0 + mi*16 + g + 8*h;
                const int m = m0 + mloc;
                #pragma unroll
                for (int ni = 0; ni < 8; ni++) {
                    const int col = wn0 + ni*8 + 2*c4;
                    __half2 a = *reinterpret_cast<const __half2*>(&aux[(size_t)m*N + col]);
                    ts[ col   *132 + mloc] = acc[mi][ni][2*h+0] + bias[col]   + __low2float(a);
                    ts[(col+1)*132 + mloc] = acc[mi][ni][2*h+1] + bias[col+1] + __high2float(a);
                }
            }
        }
        __syncthreads();
        for (int i = tid; i < 256*32; i += GTHREADS) {
            const int colr = i >> 5, q = i & 31;
            const int m = m0 + q*4;
            const int bq = m / HWS;
            const int sp = m - bq*HWS;
            float4 v = *reinterpret_cast<const float4*>(&ts[colr*132 + q*4]);
            *reinterpret_cast<float4*>(&C[((size_t)(bq*CH + colr))*HWS + sp]) = v;
        }
        return;
    }

    #pragma unroll
    for (int mi = 0; mi < 2; mi++) {
        #pragma unroll
        for (int h = 0; h < 2; h++) {
            const int m = m0 + wm0 + mi*16 + g + 8*h;
            #pragma unroll
            for (int ni = 0; ni < 8; ni++) {
                const int col = n0 + wn0 + ni*8 + 2*c4;
                float v0 = acc[mi][ni][2*h + 0] + bias[col];
                float v1 = acc[mi][ni][2*h + 1] + bias[col + 1];
                if (EPI == EPI_BIAS) {
                    __half2* C = (__half2*)Cp;
                    C[((size_t)m*N + col) >> 1] = __floats2half2_rn(v0, v1);
                } else { // EPI_GELU
                    __half2* C = (__half2*)Cp;
                    float g0 = 0.5f*v0*(1.f + erff(v0*0.70710678118654752f));
                    float g1 = 0.5f*v1*(1.f + erff(v1*0.70710678118654752f));
                    C[((size_t)m*N + col) >> 1] = __floats2half2_rn(g0, g1);
                }
            }
        }
    }
}

// ---------------- kernel 3: TC attention, CTA = (window, 4 heads), 256 thr ----------------
// per-head-pair loading + named barriers (no CTA-wide syncs)
#define T_STRIDE 40
#define REG_HALFS (64*T_STRIDE)
#define ATT_SMEM  (12*REG_HALFS*2)      // 61440 B -> 3 CTAs/SM

__global__ __launch_bounds__(256) void attn_kernel(
    const __half* __restrict__ qkv, __half* __restrict__ o)
{
    extern __shared__ __half ash[];
    const int win  = blockIdx.x >> 1;
    const int hgrp = blockIdx.x & 1;
    const int tid  = threadIdx.x;
    const int warp = tid >> 5, lane = tid & 31;
    const int hloc = warp >> 1, half = warp & 1;
    const int head = hgrp*4 + hloc;
    const int g    = lane >> 2, c4 = lane & 3;
    const int fr   = ((lane >> 3) & 1) * 8 + (lane & 7);
    const int fk   = lane >> 4;
    const int tid64 = tid & 63;

    __half* Qb = ash;
    __half* Kb = ash + 4*REG_HALFS;
    __half* Vb = ash + 8*REG_HALFS;

    // each head-pair (2 warps) loads ONLY its head's tiles
    // zero own V token-pad rows 49..63 (15 rows x 5 chunks = 75)
    for (int i = tid64; i < 75; i += 64) {
        int row = 49 + i / 5, q = i % 5;
        *(uint4*)(Vb + hloc*REG_HALFS + row*T_STRIDE + q*8) = make_uint4(0,0,0,0);
    }
    // load own Q/K/V: 3 sections x 49 tokens x 4 chunks = 588
    {
        const __half* srch = qkv + (size_t)win*49*QKVN + head*32;
        for (int idx = tid64; idx < 588; idx += 64) {
            int sec = idx / 196;
            int rem = idx - sec*196;
            int n = rem >> 2, dq = (rem & 3)*8;
            uint4 v = *(const uint4*)(srch + (size_t)n*QKVN + sec*256 + dq);
            __half* base = (sec == 0) ? Qb : (sec == 1) ? Kb : Vb;
            *(uint4*)(base + hloc*REG_HALFS + n*T_STRIDE + dq) = v;
        }
    }
    // named barrier over this head pair's 64 threads
    asm volatile("bar.sync %0, 64;" :: "r"(hloc + 1) : "memory");

    const uint32_t Qsm = (uint32_t)__cvta_generic_to_shared(Qb + hloc*REG_HALFS)
                       + (half*32 + fr)*T_STRIDE*2;
    const uint32_t Ksm = (uint32_t)__cvta_generic_to_shared(Kb + hloc*REG_HALFS)
                       + fr*T_STRIDE*2;
    const uint32_t Vsm = (uint32_t)__cvta_generic_to_shared(Vb + hloc*REG_HALFS)
                       + fr*T_STRIDE*2;

    float acc[2][7][4];
    #pragma unroll
    for (int i = 0; i < 2; i++)
        #pragma unroll
        for (int j = 0; j < 7; j++)
            #pragma unroll
            for (int k = 0; k < 4; k++) acc[i][j][k] = 0.f;

    #pragma unroll
    for (int kk = 0; kk < 2; kk++) {
        const int kc = kk*2 + fk;
        uint32_t af[2][4], bf[4][4];
        #pragma unroll
        for (int mi = 0; mi < 2; mi++)
            ldsm4(af[mi][0], af[mi][1], af[mi][2], af[mi][3],
                  Qsm + mi*16*T_STRIDE*2 + kc*16);
        #pragma unroll
        for (int p = 0; p < 4; p++)
            ldsm4(bf[p][0], bf[p][1], bf[p][2], bf[p][3],
                  Ksm + p*16*T_STRIDE*2 + kc*16);
        #pragma unroll
        for (int mi = 0; mi < 2; mi++)
            #pragma unroll
            for (int ni = 0; ni < 7; ni++) {
                const int p = ni >> 1, sb = ni & 1;
                MMA16816(acc[mi][ni][0], acc[mi][ni][1], acc[mi][ni][2], acc[mi][ni][3],
                         af[mi][0], af[mi][1], af[mi][2], af[mi][3],
                         bf[p][sb], bf[p][2 + sb]);
            }
    }

    const float scale = 0.17677669529663687f;
    float mx[2][2], sum[2][2];
    #pragma unroll
    for (int mi = 0; mi < 2; mi++) { mx[mi][0] = mx[mi][1] = -1e30f; sum[mi][0] = sum[mi][1] = 0.f; }

    #pragma unroll
    for (int mi = 0; mi < 2; mi++)
        #pragma unroll
        for (int ni = 0; ni < 7; ni++)
            #pragma unroll
            for (int b = 0; b < 2; b++) {
                int j = ni*8 + 2*c4 + b;
                float v0 = acc[mi][ni][b]   * scale;
                float v1 = acc[mi][ni][2+b] * scale;
                if (j >= 49) { v0 = -1e30f; v1 = -1e30f; }
                acc[mi][ni][b] = v0; acc[mi][ni][2+b] = v1;
                mx[mi][0] = fmaxf(mx[mi][0], v0);
                mx[mi][1] = fmaxf(mx[mi][1], v1);
            }
    #pragma unroll
    for (int mi = 0; mi < 2; mi++)
        #pragma unroll
        for (int r = 0; r < 2; r++) {
            float m_ = mx[mi][r];
            m_ = fmaxf(m_, __shfl_xor_sync(0xffffffffu, m_, 1));
            m_ = fmaxf(m_, __shfl_xor_sync(0xffffffffu, m_, 2));
            mx[mi][r] = m_;
        }
    #pragma unroll
    for (int mi = 0; mi < 2; mi++)
        #pragma unroll
        for (int ni = 0; ni < 7; ni++)
            #pragma unroll
            for (int b = 0; b < 2; b++) {
                float e0 = __expf(acc[mi][ni][b]   - mx[mi][0]);
                float e1 = __expf(acc[mi][ni][2+b] - mx[mi][1]);
                acc[mi][ni][b] = e0; acc[mi][ni][2+b] = e1;
                sum[mi][0] += e0; sum[mi][1] += e1;
            }
    #pragma unroll
    for (int mi = 0; mi < 2; mi++)
        #pragma unroll
        for (int r = 0; r < 2; r++) {
            float s_ = sum[mi][r];
            s_ += __shfl_xor_sync(0xffffffffu, s_, 1);
            s_ += __shfl_xor_sync(0xffffffffu, s_, 2);
            sum[mi][r] = 1.f / s_;
        }

    uint32_t ph[2][7][2];
    #pragma unroll
    for (int mi = 0; mi < 2; mi++)
        #pragma unroll
        for (int ni = 0; ni < 7; ni++) {
            __half2 p0 = __floats2half2_rn(acc[mi][ni][0]*sum[mi][0], acc[mi][ni][1]*sum[mi][0]);
            __half2 p1 = __floats2half2_rn(acc[mi][ni][2]*sum[mi][1], acc[mi][ni][3]*sum[mi][1]);
            ph[mi][ni][0] = *reinterpret_cast<uint32_t*>(&p0);
            ph[mi][ni][1] = *reinterpret_cast<uint32_t*>(&p1);
        }

    float oacc[2][4][4];
    #pragma unroll
    for (int i = 0; i < 2; i++)
        #pragma unroll
        for (int j = 0; j < 4; j++)
            #pragma unroll
            for (int k = 0; k < 4; k++) oacc[i][j][k] = 0.f;

    #pragma unroll
    for (int kf = 0; kf < 4; kf++) {
        uint32_t bf[2][4];
        #pragma unroll
        for (int cp = 0; cp < 2; cp++)
            ldsm4t(bf[cp][0], bf[cp][1], bf[cp][2], bf[cp][3],
                   Vsm + kf*16*T_STRIDE*2 + (2*cp + fk)*16);
        #pragma unroll
        for (int mi = 0; mi < 2; mi++) {
            const int n0f = 2*kf, n1f = 2*kf + 1;
            uint32_t a0 = ph[mi][n0f][0], a1 = ph[mi][n0f][1];
            uint32_t a2 = (n1f < 7) ? ph[mi][n1f][0] : 0u;
            uint32_t a3 = (n1f < 7) ? ph[mi][n1f][1] : 0u;
            #pragma unroll
            for (int ni2 = 0; ni2 < 4; ni2++) {
                const int cp = ni2 >> 1, q = ni2 & 1;
                MMA16816(oacc[mi][ni2][0], oacc[mi][ni2][1], oacc[mi][ni2][2], oacc[mi][ni2][3],
                         a0, a1, a2, a3, bf[cp][2*q], bf[cp][2*q + 1]);
            }
        }
    }

    #pragma unroll
    for (int mi = 0; mi < 2; mi++) {
        const int i0 = half*32 + mi*16 + g, i1 = i0 + 8;
        #pragma unroll
        for (int ni2 = 0; ni2 < 4; ni2++) {
            const int col = head*HDIM + ni2*8 + 2*c4;
            if (i0 < 49) {
                __half2 v = __floats2half2_rn(oacc[mi][ni2][0], oacc[mi][ni2][1]);
                *reinterpret_cast<__half2*>(&o[((size_t)win*49 + i0)*CH + col]) = v;
            }
            if (i1 < 49) {
                __half2 v = __floats2half2_rn(oacc[mi][ni2][2], oacc[mi][ni2][3]);
                *reinterpret_cast<__half2*>(&o[((size_t)win*49 + i1)*CH + col]) = v;
            }
        }
    }
}

// ---------------- launch ----------------
extern "C" void kernel_launch(void* const* d_in, const int* in_sizes, int n_in,
                              void* d_out, int out_size)
{
    const float* x      = (const float*)d_in[0];
    const float* n1_g   = (const float*)d_in[1];
    const float* n1_b   = (const float*)d_in[2];
    const float* qkv_w  = (const float*)d_in[3];
    const float* qkv_b  = (const float*)d_in[4];
    const float* proj_w = (const float*)d_in[5];
    const float* proj_b = (const float*)d_in[6];
    const float* n2_g   = (const float*)d_in[7];
    const float* n2_b   = (const float*)d_in[8];
    const float* mlp_w1 = (const float*)d_in[9];
    const float* mlp_b1 = (const float*)d_in[10];
    const float* mlp_w2 = (const float*)d_in[11];
    const float* mlp_b2 = (const float*)d_in[12];

    __half *ywin, *xh, *qkvb, *ow, *x1, *h2, *hmid;
    __half *wqkv, *wproj, *w1, *w2;
    cudaGetSymbolAddress((void**)&ywin,  g_ywin);
    cudaGetSymbolAddress((void**)&xh,    g_xh);
    cudaGetSymbolAddress((void**)&qkvb,  g_qkv);
    cudaGetSymbolAddress((void**)&ow,    g_ow);
    cudaGetSymbolAddress((void**)&x1,    g_x1);
    cudaGetSymbolAddress((void**)&h2,    g_h2);
    cudaGetSymbolAddress((void**)&hmid,  g_hmid);
    cudaGetSymbolAddress((void**)&wqkv,  g_wqkv);
    cudaGetSymbolAddress((void**)&wproj, g_wproj);
    cudaGetSymbolAddress((void**)&w1,    g_w1);
    cudaGetSymbolAddress((void**)&w2,    g_w2);

    static bool attr_done = false;
    if (!attr_done) {
        cudaFuncSetAttribute(mma_gemm<EPI_BIAS>,   cudaFuncAttributeMaxDynamicSharedMemorySize, SMEM_DYN);
        cudaFuncSetAttribute(mma_gemm<EPI_PROJLN>, cudaFuncAttributeMaxDynamicSharedMemorySize, SMEM_DYN);
        cudaFuncSetAttribute(mma_gemm<EPI_GELU>,   cudaFuncAttributeMaxDynamicSharedMemorySize, SMEM_DYN);
        cudaFuncSetAttribute(mma_gemm<EPI_RES>,    cudaFuncAttributeMaxDynamicSharedMemorySize, SMEM_DYN);
        cudaFuncSetAttribute(attn_kernel,          cudaFuncAttributeMaxDynamicSharedMemorySize, ATT_SMEM);
        attr_done = true;
    }

    // 0) all weights: transpose + fp16 round -> [N][K]
    transpose_round_all<<<768, 256>>>(qkv_w, wqkv, proj_w, wproj, mlp_w1, w1, mlp_w2, w2);

    // 1) LN1 + shift + window partition + fp16 shortcut
    ln1_kernel<<<BATCH*98, 256>>>(x, n1_g, n1_b, ywin, xh);

    // 2) qkv = ywin @ qkv_w + qkv_b
    mma_gemm<EPI_BIAS><<<dim3(QKVN/256, TOK/128), GTHREADS, SMEM_DYN>>>(
        ywin, wqkv, qkv_b, qkvb, nullptr, nullptr, nullptr, nullptr, TOK, QKVN, CH);

    // 3) tensor-core windowed attention (2 CTAs per window, 4 heads each)
    attn_kernel<<<4096, 256, ATT_SMEM>>>(qkvb, ow);

    // 4) x1(fp16) = shortcut(xh) + proj(ow); h2 = LN2(x1)   (fused)
    mma_gemm<EPI_PROJLN><<<dim3(CH/256, TOK/128), GTHREADS, SMEM_DYN>>>(
        ow, wproj, proj_b, x1, xh, n2_g, n2_b, h2, TOK, CH, CH);

    // 5) hmid = gelu(h2 @ mlp_w1 + mlp_b1)
    mma_gemm<EPI_GELU><<<dim3(HIDDEN/256, TOK/128), GTHREADS, SMEM_DYN>>>(
        h2, w1, mlp_b1, hmid, nullptr, nullptr, nullptr, nullptr, TOK, HIDDEN, CH);

    // 6) out(NCHW) = x1 + hmid @ mlp_w2 + mlp_b2   (smem-staged coalesced transpose)
    mma_gemm<EPI_RES><<<dim3(CH/256, TOK/128), GTHREADS, SMEM_DYN>>>(
        hmid, w2, mlp_b2, (float*)d_out, x1, nullptr, nullptr, nullptr, TOK, CH, HIDDEN);
}

// round 16
// speedup vs baseline: 1.9446x; 1.0422x over previous
#include <cuda_runtime.h>
#include <cuda_fp16.h>
#include <math.h>
#include <stdint.h>

// ---------------- problem constants ----------------
#define BATCH 32
#define CH    256
#define HWS   3136
#define TOK   100352
#define SHIFT3 3
#define HEADS 8
#define HDIM  32
#define HIDDEN 1024
#define QKVN  768

// ---------------- scratch ----------------
__device__ __half g_ywin [(size_t)TOK*CH];
__device__ __half g_xh   [(size_t)TOK*CH];     // fp16 shortcut, (b,hw,c)
__device__ __half g_qkv  [(size_t)TOK*QKVN];
__device__ __half g_ow   [(size_t)TOK*CH];
__device__ __half g_x1   [(size_t)TOK*CH];     // fp16 residual
__device__ __half g_h2   [(size_t)TOK*CH];
__device__ __half g_hmid [(size_t)TOK*HIDDEN];
// fp16, TRANSPOSED weight copies: [N][K]
__device__ __half g_wqkv [QKVN*CH];
__device__ __half g_wproj[CH*CH];
__device__ __half g_w1   [HIDDEN*CH];
__device__ __half g_w2   [CH*HIDDEN];

__device__ __forceinline__ void cpasync16(uint32_t dst, const void* src) {
    asm volatile("cp.async.cg.shared.global [%0], [%1], 16;" :: "r"(dst), "l"(src));
}

__device__ __forceinline__ void ldsm4(uint32_t& r0, uint32_t& r1, uint32_t& r2, uint32_t& r3,
                                      uint32_t addr) {
    asm volatile("ldmatrix.sync.aligned.m8n8.x4.shared.b16 {%0,%1,%2,%3}, [%4];"
                 : "=r"(r0), "=r"(r1), "=r"(r2), "=r"(r3) : "r"(addr));
}

__device__ __forceinline__ void ldsm4t(uint32_t& r0, uint32_t& r1, uint32_t& r2, uint32_t& r3,
                                       uint32_t addr) {
    asm volatile("ldmatrix.sync.aligned.m8n8.x4.trans.shared.b16 {%0,%1,%2,%3}, [%4];"
                 : "=r"(r0), "=r"(r1), "=r"(r2), "=r"(r3) : "r"(addr));
}

#define MMA16816(d0,d1,d2,d3,a0,a1,a2,a3,b0,b1) \
    asm volatile( \
        "mma.sync.aligned.m16n8k16.row.col.f32.f16.f16.f32 " \
        "{%0,%1,%2,%3}, {%4,%5,%6,%7}, {%8,%9}, {%0,%1,%2,%3};" \
        : "+f"(d0), "+f"(d1), "+f"(d2), "+f"(d3) \
        : "r"(a0), "r"(a1), "r"(a2), "r"(a3), "r"(b0), "r"(b1))

// ---------------- prep: ALL weights transpose + fp16 round, one launch ----------------
__global__ __launch_bounds__(256) void transpose_round_all(
    const float* __restrict__ w0, __half* __restrict__ o0,
    const float* __restrict__ w1_, __half* __restrict__ o1,
    const float* __restrict__ w2_, __half* __restrict__ o2,
    const float* __restrict__ w3_, __half* __restrict__ o3)
{
    __shared__ float t[32][33];
    int blk = blockIdx.x;
    const float* w; __half* wt; int K, N, nb;
    if (blk < 192)      { w = w0;  wt = o0; K = CH;     N = QKVN;   nb = QKVN/32; }
    else if (blk < 256) { blk -= 192; w = w1_; wt = o1; K = CH;     N = CH;     nb = CH/32; }
    else if (blk < 512) { blk -= 256; w = w2_; wt = o2; K = CH;     N = HIDDEN; nb = HIDDEN/32; }
    else                { blk -= 512; w = w3_; wt = o3; K = HIDDEN; N = CH;     nb = CH/32; }
    const int k0 = (blk / nb) * 32, n0 = (blk % nb) * 32;
    const int x = threadIdx.x & 31, y = threadIdx.x >> 5;
    for (int yy = y; yy < 32; yy += 8)
        t[yy][x] = w[(size_t)(k0 + yy)*N + n0 + x];
    __syncthreads();
    for (int yy = y; yy < 32; yy += 8)
        wt[(size_t)(n0 + yy)*K + k0 + x] = __float2half_rn(t[x][yy]);
}

// ---------------- kernel 1: LN1 + shift + window partition + fp16 NHWC shortcut ----------------
__global__ __launch_bounds__(256) void ln1_kernel(
    const float* __restrict__ x, const float* __restrict__ g, const float* __restrict__ bta,
    __half* __restrict__ ywin, __half* __restrict__ xh)
{
    __shared__ float ts[256*33];
    __shared__ float cmu[32], crs[32];
    const int blk = blockIdx.x;
    const int b   = blk / 98;
    const int hw0 = (blk % 98) * 32;
    const int tid = threadIdx.x;
    const float* xb = x + (size_t)b*CH*HWS;

    for (int idx = tid; idx < 256*32; idx += 256) {
        int ch = idx >> 5, j = idx & 31;
        ts[ch*33 + j] = xb[(size_t)ch*HWS + hw0 + j];
    }
    __syncthreads();

    {
        int col = tid >> 3, kk = tid & 7;
        float s = 0.f, s2 = 0.f;
        for (int ch = kk; ch < 256; ch += 8) {
            float v = ts[ch*33 + col];
            s += v; s2 += v*v;
        }
        #pragma unroll
        for (int o = 4; o; o >>= 1) {
            s  += __shfl_down_sync(0xffffffffu, s,  o, 8);
            s2 += __shfl_down_sync(0xffffffffu, s2, o, 8);
        }
        if (kk == 0) {
            float mu = s * (1.f/256.f);
            cmu[col] = mu;
            crs[col] = rsqrtf(s2*(1.f/256.f) - mu*mu + 1e-5f);
        }
    }
    __syncthreads();

    const float gg = g[tid], bb = bta[tid];
    for (int j = 0; j < 32; j++) {
        int hw = hw0 + j;
        int h = hw / 56, w = hw % 56;
        int hs = h + (56 - SHIFT3); if (hs >= 56) hs -= 56;
        int wsh = w + (56 - SHIFT3); if (wsh >= 56) wsh -= 56;
        int wi = hs / 7, r = hs % 7;
        int wj = wsh / 7, c = wsh % 7;
        int win = ((b << 3) + wi) * 8 + wj;
        int n = r*7 + c;
        float v = ts[tid*33 + j];
        xh[((size_t)b*HWS + hw)*CH + tid] = __float2half_rn(v);
        ywin[((size_t)win*49 + n)*CH + tid] =
            __float2half_rn((v - cmu[j]) * crs[j] * gg + bb);
    }
}

// ---------------- fp16 mma GEMM: CTA 128x256, 16 warps @ 32x64, BK=64, 4-stage ----------------
#define BK 64
#define STAGES 4
#define A_STAGE_B (128*128)
#define B_STAGE_B (256*128)
#define STAGE_B   (A_STAGE_B + B_STAGE_B)
#define SMEM_DYN  (STAGES*STAGE_B)     // 192 KB
#define GTHREADS  512

enum { EPI_BIAS = 0, EPI_PROJLN = 1, EPI_GELU = 2, EPI_RES = 3 };

template<int EPI>
__global__ __launch_bounds__(GTHREADS) void mma_gemm(
    const __half* __restrict__ A, const __half* __restrict__ BT,
    const float* __restrict__ bias, void* __restrict__ Cp,
    const void* __restrict__ auxp,
    const float* __restrict__ gamma, const float* __restrict__ beta2,
    __half* __restrict__ h2out,
    int M, int N, int K)
{
    extern __shared__ char sm[];
    const uint32_t smb = (uint32_t)__cvta_generic_to_shared(sm);

    const int tid  = threadIdx.x;
    const int lane = tid & 31, warp = tid >> 5;
    const int g    = lane >> 2, c4 = lane & 3;
    const int wm0  = (warp >> 2) * 32;
    const int wn0  = (warp & 3) * 64;
    const int m0   = blockIdx.y * 128, n0 = blockIdx.x * 256;

    const int fr  = ((lane >> 3) & 1) * 8 + (lane & 7);
    const int fk  = lane >> 4;

    int arow[2], asw[2], brow[4], bsw[4];
    #pragma unroll
    for (int i = 0; i < 2; i++) {
        int ra = wm0 + i*16 + fr;
        arow[i] = ra*128; asw[i] = ra & 7;
    }
    #pragma unroll
    for (int i = 0; i < 4; i++) {
        int rb = wn0 + i*16 + fr;
        brow[i] = rb*128; bsw[i] = rb & 7;
    }

    const int cr = tid >> 3, cc = tid & 7;

    float acc[2][8][4];
    #pragma unroll
    for (int i = 0; i < 2; i++)
        #pragma unroll
        for (int j = 0; j < 8; j++)
            #pragma unroll
            for (int k = 0; k < 4; k++) acc[i][j][k] = 0.f;

    auto fill = [&](int t) {
        const int s = t % STAGES;
        const uint32_t ab = smb + (uint32_t)(s*STAGE_B);
        const uint32_t bb = ab + A_STAGE_B;
        const int k0 = t * BK;
        #pragma unroll
        for (int i = 0; i < 2; i++) {
            int rr = cr + 64*i;
            cpasync16(ab + (uint32_t)(rr*128) + (uint32_t)((cc ^ (rr & 7)) << 4),
                      &A[(size_t)(m0 + rr)*K + k0 + cc*8]);
        }
        #pragma unroll
        for (int i = 0; i < 4; i++) {
            int rr = cr + 64*i;
            cpasync16(bb + (uint32_t)(rr*128) + (uint32_t)((cc ^ (rr & 7)) << 4),
                      &BT[(size_t)(n0 + rr)*K + k0 + cc*8]);
        }
    };

    const int nt = K / BK;
    #pragma unroll
    for (int s = 0; s < STAGES-1; s++) {
        if (s < nt) fill(s);
        asm volatile("cp.async.commit_group;");
    }

    for (int t = 0; t < nt; t++) {
        asm volatile("cp.async.wait_group %0;" :: "n"(STAGES-2));
        __syncthreads();
        if (t + STAGES - 1 < nt) fill(t + STAGES - 1);
        asm volatile("cp.async.commit_group;");

        const uint32_t ab = smb + (uint32_t)((t % STAGES)*STAGE_B);
        const uint32_t bb = ab + A_STAGE_B;

        #pragma unroll
        for (int kk = 0; kk < 4; kk++) {
            const int kc = kk*2 + fk;
            uint32_t af[2][4], bf[4][4];
            #pragma unroll
            for (int mi = 0; mi < 2; mi++)
                ldsm4(af[mi][0], af[mi][1], af[mi][2], af[mi][3],
                      ab + (uint32_t)arow[mi] + (uint32_t)((kc ^ asw[mi]) << 4));
            #pragma unroll
            for (int np = 0; np < 4; np++)
                ldsm4(bf[np][0], bf[np][1], bf[np][2], bf[np][3],
                      bb + (uint32_t)brow[np] + (uint32_t)((kc ^ bsw[np]) << 4));

            #pragma unroll
            for (int mi = 0; mi < 2; mi++)
                #pragma unroll
                for (int ni = 0; ni < 8; ni++) {
                    const int p = ni >> 1, sb = ni & 1;
                    MMA16816(acc[mi][ni][0], acc[mi][ni][1], acc[mi][ni][2], acc[mi][ni][3],
                             af[mi][0], af[mi][1], af[mi][2], af[mi][3],
                             bf[p][sb], bf[p][2 + sb]);
                }
        }
    }

    // -------- epilogue --------
    if (EPI == EPI_PROJLN) {
        asm volatile("cp.async.wait_group 0;" ::: "memory");
        __syncthreads();
        const __half* aux = (const __half*)auxp;
        float* red  = (float*)sm;
        float* red2 = red + 512;
        float* smu  = red2 + 512;
        float* srs  = smu + 128;

        __half* C = (__half*)Cp;
        float psum[2][2], psum2[2][2];
        #pragma unroll
        for (int mi = 0; mi < 2; mi++) { psum[mi][0]=psum[mi][1]=psum2[mi][0]=psum2[mi][1]=0.f; }

        #pragma unroll
        for (int mi = 0; mi < 2; mi++) {
            #pragma unroll
            for (int h = 0; h < 2; h++) {
                const int m = m0 + wm0 + mi*16 + g + 8*h;
                int win = m / 49, n = m % 49;
                int bq = win >> 6;
                int wr = (win >> 3) & 7;
                int wc = win & 7;
                int rr = n / 7, ccv = n % 7;
                int hh = wr*7 + rr + SHIFT3; if (hh >= 56) hh -= 56;
                int wwv = wc*7 + ccv + SHIFT3; if (wwv >= 56) wwv -= 56;
                int sp = hh*56 + wwv;
                size_t drow = (size_t)bq*HWS + sp;
                #pragma unroll
                for (int ni = 0; ni < 8; ni++) {
                    const int col = wn0 + ni*8 + 2*c4;
                    __half2 a = *reinterpret_cast<const __half2*>(&aux[drow*CH + col]);
                    float v0 = acc[mi][ni][2*h+0] + bias[col]   + __low2float(a);
                    float v1 = acc[mi][ni][2*h+1] + bias[col+1] + __high2float(a);
                    acc[mi][ni][2*h+0] = v0; acc[mi][ni][2*h+1] = v1;
                    *reinterpret_cast<__half2*>(&C[drow*CH + col]) = __floats2half2_rn(v0, v1);
                    psum [mi][h] += v0 + v1;
                    psum2[mi][h] += v0*v0 + v1*v1;
                }
            }
        }
        #pragma unroll
        for (int mi = 0; mi < 2; mi++)
            #pragma unroll
            for (int h = 0; h < 2; h++) {
                float s = psum[mi][h], s2 = psum2[mi][h];
                s  += __shfl_xor_sync(0xffffffffu, s, 1);  s  += __shfl_xor_sync(0xffffffffu, s, 2);
                s2 += __shfl_xor_sync(0xffffffffu, s2, 1); s2 += __shfl_xor_sync(0xffffffffu, s2, 2);
                if (c4 == 0) {
                    int rloc = wm0 + mi*16 + g + 8*h;
                    red [rloc*4 + (warp & 3)] = s;
                    red2[rloc*4 + (warp & 3)] = s2;
                }
            }
        __syncthreads();
        if (tid < 128) {
            float s  = red [tid*4] + red [tid*4+1] + red [tid*4+2] + red [tid*4+3];
            float s2 = red2[tid*4] + red2[tid*4+1] + red2[tid*4+2] + red2[tid*4+3];
            float mu = s * (1.f/256.f);
            smu[tid] = mu;
            srs[tid] = rsqrtf(s2*(1.f/256.f) - mu*mu + 1e-5f);
        }
        __syncthreads();
        #pragma unroll
        for (int mi = 0; mi < 2; mi++) {
            #pragma unroll
            for (int h = 0; h < 2; h++) {
                const int rloc = wm0 + mi*16 + g + 8*h;
                const int m = m0 + rloc;
                float mu = smu[rloc], rs = srs[rloc];
                int win = m / 49, n = m % 49;
                int bq = win >> 6;
                int wr = (win >> 3) & 7;
                int wc = win & 7;
                int rr = n / 7, ccv = n % 7;
                int hh = wr*7 + rr + SHIFT3; if (hh >= 56) hh -= 56;
                int wwv = wc*7 + ccv + SHIFT3; if (wwv >= 56) wwv -= 56;
                size_t drow = (size_t)bq*HWS + hh*56 + wwv;
                #pragma unroll
                for (int ni = 0; ni < 8; ni++) {
                    const int col = wn0 + ni*8 + 2*c4;
                    float h0 = (acc[mi][ni][2*h+0] - mu)*rs*gamma[col  ] + beta2[col  ];
                    float h1 = (acc[mi][ni][2*h+1] - mu)*rs*gamma[col+1] + beta2[col+1];
                    *reinterpret_cast<__half2*>(&h2out[drow*CH + col]) = __floats2half2_rn(h0, h1);
                }
            }
        }
        return;
    }

    if (EPI == EPI_RES) {
        asm volatile("cp.async.wait_group 0;" ::: "memory");
        __syncthreads();
        float* ts = (float*)sm;
        const __half* aux = (const __half*)auxp;
        float* C = (float*)Cp;

        #pragma unroll
        for (int mi = 0; mi < 2; mi++) {
            #pragma unroll
            for (int h = 0; h < 2; h++) {
                const int mloc = wm0 + mi*16 + g + 8*h;
                const int m = m0 + mloc;
                #pragma unroll
                for (int ni = 0; ni < 8; ni++) {
                    const int col = wn0 + ni*8 + 2*c4;
                    __half2 a = *reinterpret_cast<const __half2*>(&aux[(size_t)m*N + col]);
                    ts[ col   *132 + mloc] = acc[mi][ni][2*h+0] + bias[col]   + __low2float(a);
                    ts[(col+1)*132 + mloc] = acc[mi][ni][2*h+1] + bias[col+1] + __high2float(a);
                }
            }
        }
        __syncthreads();
        for (int i = tid; i < 256*32; i += GTHREADS) {
            const int colr = i >> 5, q = i & 31;
            const int m = m0 + q*4;
            const int bq = m / HWS;
            const int sp = m - bq*HWS;
            float4 v = *reinterpret_cast<const float4*>(&ts[colr*132 + q*4]);
            *reinterpret_cast<float4*>(&C[((size_t)(bq*CH + colr))*HWS + sp]) = v;
        }
        return;
    }

    #pragma unroll
    for (int mi = 0; mi < 2; mi++) {
        #pragma unroll
        for (int h = 0; h < 2; h++) {
            const int m = m0 + wm0 + mi*16 + g + 8*h;
            #pragma unroll
            for (int ni = 0; ni < 8; ni++) {
                const int col = n0 + wn0 + ni*8 + 2*c4;
                float v0 = acc[mi][ni][2*h + 0] + bias[col];
                float v1 = acc[mi][ni][2*h + 1] + bias[col + 1];
                if (EPI == EPI_BIAS) {
                    __half2* C = (__half2*)Cp;
                    C[((size_t)m*N + col) >> 1] = __floats2half2_rn(v0, v1);
                } else { // EPI_GELU
                    __half2* C = (__half2*)Cp;
                    float g0 = 0.5f*v0*(1.f + erff(v0*0.70710678118654752f));
                    float g1 = 0.5f*v1*(1.f + erff(v1*0.70710678118654752f));
                    C[((size_t)m*N + col) >> 1] = __floats2half2_rn(g0, g1);
                }
            }
        }
    }
}

// ---------------- kernel 3: TC attention, CTA = (window, 4 heads), 256 thr ----------------
// R13 load structure, cp.async loads
#define T_STRIDE 40
#define REG_HALFS (64*T_STRIDE)
#define ATT_SMEM  (12*REG_HALFS*2)      // 61440 B -> 3 CTAs/SM

__global__ __launch_bounds__(256) void attn_kernel(
    const __half* __restrict__ qkv, __half* __restrict__ o)
{
    extern __shared__ __half ash[];
    const int win  = blockIdx.x >> 1;
    const int hgrp = blockIdx.x & 1;
    const int tid  = threadIdx.x;
    const int warp = tid >> 5, lane = tid & 31;
    const int hloc = warp >> 1, half = warp & 1;
    const int head = hgrp*4 + hloc;
    const int g    = lane >> 2, c4 = lane & 3;
    const int fr   = ((lane >> 3) & 1) * 8 + (lane & 7);
    const int fk   = lane >> 4;

    __half* Qb = ash;
    __half* Kb = ash + 4*REG_HALFS;
    __half* Vb = ash + 8*REG_HALFS;
    const uint32_t ashb = (uint32_t)__cvta_generic_to_shared(ash);

    // zero V token-pad rows 49..63 (4 heads x 15 rows x 5 chunks = 300)
    for (int i = tid; i < 300; i += 256) {
        int h = i / 75, rem = i % 75;
        int row = 49 + rem / 5, q = rem % 5;
        *(uint4*)(Vb + h*REG_HALFS + row*T_STRIDE + q*8) = make_uint4(0,0,0,0);
    }

    // cp.async loads: 49 tokens x 48 chunks
    const __half* src = qkv + (size_t)win*49*QKVN;
    for (int idx = tid; idx < 49*48; idx += 256) {
        int n = idx / 48, ck = idx % 48;
        int sec = ck >> 4;
        int cc  = ck & 15;
        int hl  = cc >> 2, dq = (cc & 3)*8;
        int col = sec*256 + (hgrp*4 + hl)*32 + dq;
        uint32_t dst = ashb + (uint32_t)((sec*4 + hl)*REG_HALFS + n*T_STRIDE + dq)*2;
        cpasync16(dst, src + (size_t)n*QKVN + col);
    }
    asm volatile("cp.async.commit_group;");
    asm volatile("cp.async.wait_group 0;" ::: "memory");
    __syncthreads();

    const uint32_t Qsm = (uint32_t)__cvta_generic_to_shared(Qb + hloc*REG_HALFS)
                       + (half*32 + fr)*T_STRIDE*2;
    const uint32_t Ksm = (uint32_t)__cvta_generic_to_shared(Kb + hloc*REG_HALFS)
                       + fr*T_STRIDE*2;
    const uint32_t Vsm = (uint32_t)__cvta_generic_to_shared(Vb + hloc*REG_HALFS)
                       + fr*T_STRIDE*2;

    float acc[2][7][4];
    #pragma unroll
    for (int i = 0; i < 2; i++)
        #pragma unroll
        for (int j = 0; j < 7; j++)
            #pragma unroll
            for (int k = 0; k < 4; k++) acc[i][j][k] = 0.f;

    #pragma unroll
    for (int kk = 0; kk < 2; kk++) {
        const int kc = kk*2 + fk;
        uint32_t af[2][4], bf[4][4];
        #pragma unroll
        for (int mi = 0; mi < 2; mi++)
            ldsm4(af[mi][0], af[mi][1], af[mi][2], af[mi][3],
                  Qsm + mi*16*T_STRIDE*2 + kc*16);
        #pragma unroll
        for (int p = 0; p < 4; p++)
            ldsm4(bf[p][0], bf[p][1], bf[p][2], bf[p][3],
                  Ksm + p*16*T_STRIDE*2 + kc*16);
        #pragma unroll
        for (int mi = 0; mi < 2; mi++)
            #pragma unroll
            for (int ni = 0; ni < 7; ni++) {
                const int p = ni >> 1, sb = ni & 1;
                MMA16816(acc[mi][ni][0], acc[mi][ni][1], acc[mi][ni][2], acc[mi][ni][3],
                         af[mi][0], af[mi][1], af[mi][2], af[mi][3],
                         bf[p][sb], bf[p][2 + sb]);
            }
    }

    const float scale = 0.17677669529663687f;
    float mx[2][2], sum[2][2];
    #pragma unroll
    for (int mi = 0; mi < 2; mi++) { mx[mi][0] = mx[mi][1] = -1e30f; sum[mi][0] = sum[mi][1] = 0.f; }

    #pragma unroll
    for (int mi = 0; mi < 2; mi++)
        #pragma unroll
        for (int ni = 0; ni < 7; ni++)
            #pragma unroll
            for (int b = 0; b < 2; b++) {
                int j = ni*8 + 2*c4 + b;
                float v0 = acc[mi][ni][b]   * scale;
                float v1 = acc[mi][ni][2+b] * scale;
                if (j >= 49) { v0 = -1e30f; v1 = -1e30f; }
                acc[mi][ni][b] = v0; acc[mi][ni][2+b] = v1;
                mx[mi][0] = fmaxf(mx[mi][0], v0);
                mx[mi][1] = fmaxf(mx[mi][1], v1);
            }
    #pragma unroll
    for (int mi = 0; mi < 2; mi++)
        #pragma unroll
        for (int r = 0; r < 2; r++) {
            float m_ = mx[mi][r];
            m_ = fmaxf(m_, __shfl_xor_sync(0xffffffffu, m_, 1));
            m_ = fmaxf(m_, __shfl_xor_sync(0xffffffffu, m_, 2));
            mx[mi][r] = m_;
        }
    #pragma unroll
    for (int mi = 0; mi < 2; mi++)
        #pragma unroll
        for (int ni = 0; ni < 7; ni++)
            #pragma unroll
            for (int b = 0; b < 2; b++) {
                float e0 = __expf(acc[mi][ni][b]   - mx[mi][0]);
                float e1 = __expf(acc[mi][ni][2+b] - mx[mi][1]);
                acc[mi][ni][b] = e0; acc[mi][ni][2+b] = e1;
                sum[mi][0] += e0; sum[mi][1] += e1;
            }
    #pragma unroll
    for (int mi = 0; mi < 2; mi++)
        #pragma unroll
        for (int r = 0; r < 2; r++) {
            float s_ = sum[mi][r];
            s_ += __shfl_xor_sync(0xffffffffu, s_, 1);
            s_ += __shfl_xor_sync(0xffffffffu, s_, 2);
            sum[mi][r] = 1.f / s_;
        }

    uint32_t ph[2][7][2];
    #pragma unroll
    for (int mi = 0; mi < 2; mi++)
        #pragma unroll
        for (int ni = 0; ni < 7; ni++) {
            __half2 p0 = __floats2half2_rn(acc[mi][ni][0]*sum[mi][0], acc[mi][ni][1]*sum[mi][0]);
            __half2 p1 = __floats2half2_rn(acc[mi][ni][2]*sum[mi][1], acc[mi][ni][3]*sum[mi][1]);
            ph[mi][ni][0] = *reinterpret_cast<uint32_t*>(&p0);
            ph[mi][ni][1] = *reinterpret_cast<uint32_t*>(&p1);
        }

    float oacc[2][4][4];
    #pragma unroll
    for (int i = 0; i < 2; i++)
        #pragma unroll
        for (int j = 0; j < 4; j++)
            #pragma unroll
            for (int k = 0; k < 4; k++) oacc[i][j][k] = 0.f;

    #pragma unroll
    for (int kf = 0; kf < 4; kf++) {
        uint32_t bf[2][4];
        #pragma unroll
        for (int cp = 0; cp < 2; cp++)
            ldsm4t(bf[cp][0], bf[cp][1], bf[cp][2], bf[cp][3],
                   Vsm + kf*16*T_STRIDE*2 + (2*cp + fk)*16);
        #pragma unroll
        for (int mi = 0; mi < 2; mi++) {
            const int n0f = 2*kf, n1f = 2*kf + 1;
            uint32_t a0 = ph[mi][n0f][0], a1 = ph[mi][n0f][1];
            uint32_t a2 = (n1f < 7) ? ph[mi][n1f][0] : 0u;
            uint32_t a3 = (n1f < 7) ? ph[mi][n1f][1] : 0u;
            #pragma unroll
            for (int ni2 = 0; ni2 < 4; ni2++) {
                const int cp = ni2 >> 1, q = ni2 & 1;
                MMA16816(oacc[mi][ni2][0], oacc[mi][ni2][1], oacc[mi][ni2][2], oacc[mi][ni2][3],
                         a0, a1, a2, a3, bf[cp][2*q], bf[cp][2*q + 1]);
            }
        }
    }

    #pragma unroll
    for (int mi = 0; mi < 2; mi++) {
        const int i0 = half*32 + mi*16 + g, i1 = i0 + 8;
        #pragma unroll
        for (int ni2 = 0; ni2 < 4; ni2++) {
            const int col = head*HDIM + ni2*8 + 2*c4;
            if (i0 < 49) {
                __half2 v = __floats2half2_rn(oacc[mi][ni2][0], oacc[mi][ni2][1]);
                *reinterpret_cast<__half2*>(&o[((size_t)win*49 + i0)*CH + col]) = v;
            }
            if (i1 < 49) {
                __half2 v = __floats2half2_rn(oacc[mi][ni2][2], oacc[mi][ni2][3]);
                *reinterpret_cast<__half2*>(&o[((size_t)win*49 + i1)*CH + col]) = v;
            }
        }
    }
}

// ---------------- launch ----------------
extern "C" void kernel_launch(void* const* d_in, const int* in_sizes, int n_in,
                              void* d_out, int out_size)
{
    const float* x      = (const float*)d_in[0];
    const float* n1_g   = (const float*)d_in[1];
    const float* n1_b   = (const float*)d_in[2];
    const float* qkv_w  = (const float*)d_in[3];
    const float* qkv_b  = (const float*)d_in[4];
    const float* proj_w = (const float*)d_in[5];
    const float* proj_b = (const float*)d_in[6];
    const float* n2_g   = (const float*)d_in[7];
    const float* n2_b   = (const float*)d_in[8];
    const float* mlp_w1 = (const float*)d_in[9];
    const float* mlp_b1 = (const float*)d_in[10];
    const float* mlp_w2 = (const float*)d_in[11];
    const float* mlp_b2 = (const float*)d_in[12];

    __half *ywin, *xh, *qkvb, *ow, *x1, *h2, *hmid;
    __half *wqkv, *wproj, *w1, *w2;
    cudaGetSymbolAddress((void**)&ywin,  g_ywin);
    cudaGetSymbolAddress((void**)&xh,    g_xh);
    cudaGetSymbolAddress((void**)&qkvb,  g_qkv);
    cudaGetSymbolAddress((void**)&ow,    g_ow);
    cudaGetSymbolAddress((void**)&x1,    g_x1);
    cudaGetSymbolAddress((void**)&h2,    g_h2);
    cudaGetSymbolAddress((void**)&hmid,  g_hmid);
    cudaGetSymbolAddress((void**)&wqkv,  g_wqkv);
    cudaGetSymbolAddress((void**)&wproj, g_wproj);
    cudaGetSymbolAddress((void**)&w1,    g_w1);
    cudaGetSymbolAddress((void**)&w2,    g_w2);

    static bool attr_done = false;
    if (!attr_done) {
        cudaFuncSetAttribute(mma_gemm<EPI_BIAS>,   cudaFuncAttributeMaxDynamicSharedMemorySize, SMEM_DYN);
        cudaFuncSetAttribute(mma_gemm<EPI_PROJLN>, cudaFuncAttributeMaxDynamicSharedMemorySize, SMEM_DYN);
        cudaFuncSetAttribute(mma_gemm<EPI_GELU>,   cudaFuncAttributeMaxDynamicSharedMemorySize, SMEM_DYN);
        cudaFuncSetAttribute(mma_gemm<EPI_RES>,    cudaFuncAttributeMaxDynamicSharedMemorySize, SMEM_DYN);
        cudaFuncSetAttribute(attn_kernel,          cudaFuncAttributeMaxDynamicSharedMemorySize, ATT_SMEM);
        attr_done = true;
    }

    // 0) all weights: transpose + fp16 round -> [N][K]
    transpose_round_all<<<768, 256>>>(qkv_w, wqkv, proj_w, wproj, mlp_w1, w1, mlp_w2, w2);

    // 1) LN1 + shift + window partition + fp16 shortcut
    ln1_kernel<<<BATCH*98, 256>>>(x, n1_g, n1_b, ywin, xh);

    // 2) qkv = ywin @ qkv_w + qkv_b
    mma_gemm<EPI_BIAS><<<dim3(QKVN/256, TOK/128), GTHREADS, SMEM_DYN>>>(
        ywin, wqkv, qkv_b, qkvb, nullptr, nullptr, nullptr, nullptr, TOK, QKVN, CH);

    // 3) tensor-core windowed attention (2 CTAs per window, 4 heads each)
    attn_kernel<<<4096, 256, ATT_SMEM>>>(qkvb, ow);

    // 4) x1(fp16) = shortcut(xh) + proj(ow); h2 = LN2(x1)   (fused)
    mma_gemm<EPI_PROJLN><<<dim3(CH/256, TOK/128), GTHREADS, SMEM_DYN>>>(
        ow, wproj, proj_b, x1, xh, n2_g, n2_b, h2, TOK, CH, CH);

    // 5) hmid = gelu(h2 @ mlp_w1 + mlp_b1)
    mma_gemm<EPI_GELU><<<dim3(HIDDEN/256, TOK/128), GTHREADS, SMEM_DYN>>>(
        h2, w1, mlp_b1, hmid, nullptr, nullptr, nullptr, nullptr, TOK, HIDDEN, CH);

    // 6) out(NCHW) = x1 + hmid @ mlp_w2 + mlp_b2   (smem-staged coalesced transpose)
    mma_gemm<EPI_RES><<<dim3(CH/256, TOK/128), GTHREADS, SMEM_DYN>>>(
        hmid, w2, mlp_b2, (float*)d_out, x1, nullptr, nullptr, nullptr, TOK, CH, HIDDEN);
}